// round 2
// baseline (speedup 1.0000x reference)
#include <cuda_runtime.h>
#include <math.h>

// Problem constants
constexpr int BB = 4;     // batch
constexpr int NN = 6;     // views
constexpr int DDIM = 128; // model dim
constexpr int QQ = 1024;  // H*W queries
constexpr int KImg = 640; // h*w keys per view
constexpr int MD = 256;   // heads * dim_head
constexpr int DH = 64;    // dim_head

// Scratch (device globals; no allocation allowed)
__device__ float g_qh[BB * NN * QQ * MD];    // 25 MB
__device__ float g_kh[BB * NN * KImg * MD];  // 15.7 MB
__device__ float g_vh[BB * NN * KImg * MD];  // 15.7 MB
__device__ float g_a[BB * QQ * MD];          // 4 MB
__device__ float g_z0[BB * QQ * DDIM];
__device__ float g_z1[BB * QQ * DDIM];
__device__ float g_hh[BB * QQ * MD];
__device__ float g_z2[BB * QQ * DDIM];
__device__ int g_mask[NN * QQ];

// ---------------------------------------------------------------------------
// Mask prep: detect storage layout (bool bytes / float32 / int32) and expand
// to g_mask[n*QQ + q]. mview[n, h*W+w] = mask[h,w,n]; linear idx = q*6+n.
// ---------------------------------------------------------------------------
__global__ void mask_prep(const unsigned char* __restrict__ mraw) {
    __shared__ int flagBool, flagFloat;
    int t = threadIdx.x;
    if (t == 0) { flagBool = 0; flagFloat = 0; }
    __syncthreads();
    int fb = 0, ff = 0;
    for (int i = t; i < NN * QQ; i += 256) {
        unsigned char v = mraw[i];
        if (v) {
            int r = i & 3;
            if (r == 1) fb = 1;
            else if (r >= 2) ff = 1;
        }
    }
    if (fb) atomicOr(&flagBool, 1);
    if (ff) atomicOr(&flagFloat, 1);
    __syncthreads();
    int mode = flagBool ? 0 : (flagFloat ? 1 : 2); // 0=bool bytes,1=float32,2=int32
    const float* mf = (const float*)mraw;
    const int* mi = (const int*)mraw;
    for (int i = t; i < NN * QQ; i += 256) {
        int q = i / 6, n = i % 6;
        int val;
        if (mode == 0) val = (mraw[i] != 0);
        else if (mode == 1) val = (mf[i] != 0.0f);
        else val = (mi[i] != 0);
        g_mask[n * QQ + q] = val;
    }
}

// ---------------------------------------------------------------------------
// Fused LayerNorm + projection GEMM.
// Rows r = bn*S + s (bn = b*N+n). x element d at x[bn*128*S + d*S + s].
// out[r][j] = LN(x_row) @ Wm[128,256] + bias.  Tile: 64 rows x 256 cols.
// ---------------------------------------------------------------------------
template <int S>
__global__ __launch_bounds__(256) void proj_ln(
    const float* __restrict__ x, const float* __restrict__ lg,
    const float* __restrict__ lb, const float* __restrict__ Wm,
    const float* __restrict__ bias, float* __restrict__ out) {
    __shared__ float Xs[64][129];
    __shared__ float Ws[8][260];
    __shared__ float rsum[64][4], rsq[64][4];
    __shared__ float mu_s[64], rs_s[64];
    __shared__ float gs[128], bs[128];
    int t = threadIdx.x;
    int r0 = blockIdx.x * 64;
    int bn = r0 / S;
    int s0 = r0 % S; // tiles never straddle bn (S % 64 == 0)
    const float* xb = x + (long)bn * DDIM * S + s0;
    for (int i = t; i < 64 * 128; i += 256) {
        int sl = i & 63, d = i >> 6;
        Xs[sl][d] = xb[(long)d * S + sl];
    }
    if (t < 128) { gs[t] = lg[t]; bs[t] = lb[t]; }
    __syncthreads();
    {
        int row = t >> 2, part = t & 3;
        float sm = 0.f, sq = 0.f;
#pragma unroll
        for (int j = 0; j < 32; j++) {
            float v = Xs[row][part * 32 + j];
            sm += v; sq += v * v;
        }
        rsum[row][part] = sm; rsq[row][part] = sq;
    }
    __syncthreads();
    if (t < 64) {
        float sm = rsum[t][0] + rsum[t][1] + rsum[t][2] + rsum[t][3];
        float sq = rsq[t][0] + rsq[t][1] + rsq[t][2] + rsq[t][3];
        float mu = sm * (1.f / 128.f);
        float var = sq * (1.f / 128.f) - mu * mu;
        mu_s[t] = mu;
        rs_s[t] = rsqrtf(var + 1e-5f);
    }
    __syncthreads();
    for (int i = t; i < 64 * 128; i += 256) {
        int d = i & 127, sl = i >> 7;
        Xs[sl][d] = (Xs[sl][d] - mu_s[sl]) * rs_s[sl] * gs[d] + bs[d];
    }
    int cg = t & 31, rg = t >> 5;
    float acc[8][8];
#pragma unroll
    for (int i = 0; i < 8; i++)
#pragma unroll
        for (int j = 0; j < 8; j++) acc[i][j] = 0.f;
    for (int kc = 0; kc < 128; kc += 8) {
        __syncthreads();
        for (int i = t; i < 8 * 256; i += 256) {
            int kk = i >> 8, j = i & 255;
            Ws[kk][j] = Wm[(kc + kk) * 256 + j];
        }
        __syncthreads();
#pragma unroll
        for (int kk = 0; kk < 8; kk++) {
            float a_[8];
#pragma unroll
            for (int i2 = 0; i2 < 8; i2++) a_[i2] = Xs[rg * 8 + i2][kc + kk];
            float4 b0 = *(const float4*)&Ws[kk][cg * 8];
            float4 b1 = *(const float4*)&Ws[kk][cg * 8 + 4];
            float b_[8] = {b0.x, b0.y, b0.z, b0.w, b1.x, b1.y, b1.z, b1.w};
#pragma unroll
            for (int i2 = 0; i2 < 8; i2++)
#pragma unroll
                for (int j2 = 0; j2 < 8; j2++) acc[i2][j2] += a_[i2] * b_[j2];
        }
    }
    float4 bb0 = *(const float4*)&bias[cg * 8];
    float4 bb1 = *(const float4*)&bias[cg * 8 + 4];
    float bv[8] = {bb0.x, bb0.y, bb0.z, bb0.w, bb1.x, bb1.y, bb1.z, bb1.w};
#pragma unroll
    for (int i2 = 0; i2 < 8; i2++) {
        long rr = (long)(r0 + rg * 8 + i2);
        float4 o0 = {acc[i2][0] + bv[0], acc[i2][1] + bv[1],
                     acc[i2][2] + bv[2], acc[i2][3] + bv[3]};
        float4 o1 = {acc[i2][4] + bv[4], acc[i2][5] + bv[5],
                     acc[i2][6] + bv[6], acc[i2][7] + bv[7]};
        *(float4*)&out[rr * 256 + cg * 8] = o0;
        *(float4*)&out[rr * 256 + cg * 8 + 4] = o1;
    }
}

// ---------------------------------------------------------------------------
// Flash-style cross-view attention.
// Block = (qtile of 128, head m, batch b). Keys: 6 views x 640 (10 tiles of 64).
// Online softmax with per-row running max / denom in registers.
// ---------------------------------------------------------------------------
constexpr int ATTN_SMEM_FLOATS = 64 * 132 + 64 * 68 + 64 * 132 + 64 * 68;
constexpr int ATTN_SMEM_BYTES = ATTN_SMEM_FLOATS * 4 + 128 * 4;

__global__ __launch_bounds__(256) void attn_kernel() {
    extern __shared__ float smem[];
    float* QsT = smem;               // [64][132] (d-major, q fastest)
    float* KsT = QsT + 64 * 132;     // [64][68]
    float* PsT = KsT + 64 * 68;      // [64][132] (k-major, q fastest)
    float* Vs = PsT + 64 * 132;      // [64][68]  (k-major, d fastest)
    int* maskq = (int*)(Vs + 64 * 68);

    int t = threadIdx.x;
    int qt = blockIdx.x, m = blockIdx.y, b = blockIdx.z;
    int kg = t & 15, qg = t >> 4; // kg: 4 k-cols (or 4 d-cols), qg: 8 q-rows

    float mrun[8], lrun[8], acc[8][4];
#pragma unroll
    for (int i = 0; i < 8; i++) {
        mrun[i] = -1e30f; lrun[i] = 0.f;
#pragma unroll
        for (int j = 0; j < 4; j++) acc[i][j] = 0.f;
    }

    for (int n = 0; n < 6; n++) {
        __syncthreads();
        const float* qbase =
            g_qh + (long)((b * 6 + n) * 1024 + qt * 128) * 256 + m * 64;
        for (int i = t; i < 128 * 64; i += 256) {
            int ql = i >> 6, d = i & 63;
            QsT[d * 132 + ql] = qbase[ql * 256 + d] * 0.125f; // fold scale
        }
        if (t < 128) maskq[t] = g_mask[n * 1024 + qt * 128 + t];
        __syncthreads();

        for (int kt = 0; kt < 10; kt++) {
            __syncthreads();
            const float* kb =
                g_kh + (long)((b * 6 + n) * 640 + kt * 64) * 256 + m * 64;
            const float* vb =
                g_vh + (long)((b * 6 + n) * 640 + kt * 64) * 256 + m * 64;
            for (int i = t; i < 64 * 64; i += 256) {
                int kl = i >> 6, d = i & 63;
                KsT[d * 68 + kl] = kb[kl * 256 + d];
                Vs[kl * 68 + d] = vb[kl * 256 + d];
            }
            __syncthreads();

            // S = Q K^T  (128 x 64 tile), micro 8q x 4k
            float s[8][4];
#pragma unroll
            for (int i = 0; i < 8; i++)
#pragma unroll
                for (int j = 0; j < 4; j++) s[i][j] = 0.f;
#pragma unroll 8
            for (int d = 0; d < 64; d++) {
                float4 qa = *(const float4*)&QsT[d * 132 + qg * 8];
                float4 qb2 = *(const float4*)&QsT[d * 132 + qg * 8 + 4];
                float4 kv = *(const float4*)&KsT[d * 68 + kg * 4];
                float qv[8] = {qa.x, qa.y, qa.z, qa.w, qb2.x, qb2.y, qb2.z, qb2.w};
                float kr[4] = {kv.x, kv.y, kv.z, kv.w};
#pragma unroll
                for (int i = 0; i < 8; i++)
#pragma unroll
                    for (int j = 0; j < 4; j++) s[i][j] += qv[i] * kr[j];
            }

            // online softmax update (row = 16 threads, shuffle width 16)
#pragma unroll
            for (int i = 0; i < 8; i++) {
                int ql = qg * 8 + i;
                if (!maskq[ql]) {
#pragma unroll
                    for (int j = 0; j < 4; j++) s[i][j] = -1e30f;
                }
                float mx = fmaxf(fmaxf(s[i][0], s[i][1]), fmaxf(s[i][2], s[i][3]));
#pragma unroll
                for (int o = 8; o >= 1; o >>= 1)
                    mx = fmaxf(mx, __shfl_xor_sync(0xffffffffu, mx, o, 16));
                float mnew = fmaxf(mrun[i], mx);
                float corr = __expf(mrun[i] - mnew);
                float ps = 0.f;
#pragma unroll
                for (int j = 0; j < 4; j++) {
                    float p = __expf(s[i][j] - mnew);
                    s[i][j] = p;
                    ps += p;
                }
#pragma unroll
                for (int o = 8; o >= 1; o >>= 1)
                    ps += __shfl_xor_sync(0xffffffffu, ps, o, 16);
                lrun[i] = lrun[i] * corr + ps;
                mrun[i] = mnew;
#pragma unroll
                for (int j = 0; j < 4; j++) acc[i][j] *= corr;
#pragma unroll
                for (int j = 0; j < 4; j++) PsT[(kg * 4 + j) * 132 + ql] = s[i][j];
            }
            __syncthreads();

            // acc += P V  (128q x 64d), micro 8q x 4d (dg == kg)
#pragma unroll 8
            for (int k2 = 0; k2 < 64; k2++) {
                float4 pa = *(const float4*)&PsT[k2 * 132 + qg * 8];
                float4 pb = *(const float4*)&PsT[k2 * 132 + qg * 8 + 4];
                float4 vv = *(const float4*)&Vs[k2 * 68 + kg * 4];
                float pv[8] = {pa.x, pa.y, pa.z, pa.w, pb.x, pb.y, pb.z, pb.w};
                float vr[4] = {vv.x, vv.y, vv.z, vv.w};
#pragma unroll
                for (int i = 0; i < 8; i++)
#pragma unroll
                    for (int j = 0; j < 4; j++) acc[i][j] += pv[i] * vr[j];
            }
        }
    }

    float* ob = g_a + (long)(b * 1024 + qt * 128) * 256 + m * 64;
#pragma unroll
    for (int i = 0; i < 8; i++) {
        float inv = 1.f / lrun[i];
        int ql = qg * 8 + i;
        float4 o = {acc[i][0] * inv, acc[i][1] * inv, acc[i][2] * inv,
                    acc[i][3] * inv};
        *(float4*)&ob[ql * 256 + kg * 4] = o;
    }
}

// ---------------------------------------------------------------------------
// GEMM rows x 256 -> 128  (+bias +extra). mode 0: extra = skip[b][j][q] gather,
// mode 1: extra = residual row-major [rows][128].
// ---------------------------------------------------------------------------
__global__ __launch_bounds__(256) void gemm_256_128(
    const float* __restrict__ A, const float* __restrict__ Wm,
    const float* __restrict__ bias, const float* __restrict__ extra, int mode,
    float* __restrict__ out) {
    __shared__ float Xs[64][17];
    __shared__ float Ws[16][132];
    int t = threadIdx.x;
    int r0 = blockIdx.x * 64;
    int cg = t & 31, rg = t >> 5;
    float acc[8][4];
#pragma unroll
    for (int i = 0; i < 8; i++)
#pragma unroll
        for (int j = 0; j < 4; j++) acc[i][j] = 0.f;
    for (int kc = 0; kc < 256; kc += 16) {
        __syncthreads();
        for (int i = t; i < 64 * 16; i += 256) {
            int row = i >> 4, kk = i & 15;
            Xs[row][kk] = A[(long)(r0 + row) * 256 + kc + kk];
        }
        for (int i = t; i < 16 * 128; i += 256) {
            int kk = i >> 7, j = i & 127;
            Ws[kk][j] = Wm[(kc + kk) * 128 + j];
        }
        __syncthreads();
#pragma unroll
        for (int kk = 0; kk < 16; kk++) {
            float a_[8];
#pragma unroll
            for (int i2 = 0; i2 < 8; i2++) a_[i2] = Xs[rg * 8 + i2][kk];
            float4 b0 = *(const float4*)&Ws[kk][cg * 4];
            float b_[4] = {b0.x, b0.y, b0.z, b0.w};
#pragma unroll
            for (int i2 = 0; i2 < 8; i2++)
#pragma unroll
                for (int j2 = 0; j2 < 4; j2++) acc[i2][j2] += a_[i2] * b_[j2];
        }
    }
    float4 bb = *(const float4*)&bias[cg * 4];
    float bv[4] = {bb.x, bb.y, bb.z, bb.w};
#pragma unroll
    for (int i2 = 0; i2 < 8; i2++) {
        int row = r0 + rg * 8 + i2;
        float o[4];
#pragma unroll
        for (int j2 = 0; j2 < 4; j2++) {
            float add;
            int col = cg * 4 + j2;
            if (mode == 0) {
                int bIdx = row >> 10, q = row & 1023;
                add = extra[bIdx * (128 * 1024) + col * 1024 + q];
            } else {
                add = extra[(long)row * 128 + col];
            }
            o[j2] = acc[i2][j2] + bv[j2] + add;
        }
        float4 ov = {o[0], o[1], o[2], o[3]};
        *(float4*)&out[(long)row * 128 + cg * 4] = ov;
    }
}

// ---------------------------------------------------------------------------
// GEMM rows x 128 -> 256 with exact GELU epilogue.
// ---------------------------------------------------------------------------
__global__ __launch_bounds__(256) void gemm_128_256_gelu(
    const float* __restrict__ A, const float* __restrict__ Wm,
    const float* __restrict__ bias, float* __restrict__ out) {
    __shared__ float Xs[64][17];
    __shared__ float Ws[16][260];
    int t = threadIdx.x;
    int r0 = blockIdx.x * 64;
    int cg = t & 31, rg = t >> 5;
    float acc[8][8];
#pragma unroll
    for (int i = 0; i < 8; i++)
#pragma unroll
        for (int j = 0; j < 8; j++) acc[i][j] = 0.f;
    for (int kc = 0; kc < 128; kc += 16) {
        __syncthreads();
        for (int i = t; i < 64 * 16; i += 256) {
            int row = i >> 4, kk = i & 15;
            Xs[row][kk] = A[(long)(r0 + row) * 128 + kc + kk];
        }
        for (int i = t; i < 16 * 256; i += 256) {
            int kk = i >> 8, j = i & 255;
            Ws[kk][j] = Wm[(kc + kk) * 256 + j];
        }
        __syncthreads();
#pragma unroll
        for (int kk = 0; kk < 16; kk++) {
            float a_[8];
#pragma unroll
            for (int i2 = 0; i2 < 8; i2++) a_[i2] = Xs[rg * 8 + i2][kk];
            float4 b0 = *(const float4*)&Ws[kk][cg * 8];
            float4 b1 = *(const float4*)&Ws[kk][cg * 8 + 4];
            float b_[8] = {b0.x, b0.y, b0.z, b0.w, b1.x, b1.y, b1.z, b1.w};
#pragma unroll
            for (int i2 = 0; i2 < 8; i2++)
#pragma unroll
                for (int j2 = 0; j2 < 8; j2++) acc[i2][j2] += a_[i2] * b_[j2];
        }
    }
    float4 bb0 = *(const float4*)&bias[cg * 8];
    float4 bb1 = *(const float4*)&bias[cg * 8 + 4];
    float bv[8] = {bb0.x, bb0.y, bb0.z, bb0.w, bb1.x, bb1.y, bb1.z, bb1.w};
#pragma unroll
    for (int i2 = 0; i2 < 8; i2++) {
        long row = (long)(r0 + rg * 8 + i2);
        float o[8];
#pragma unroll
        for (int j2 = 0; j2 < 8; j2++) {
            float h = acc[i2][j2] + bv[j2];
            o[j2] = 0.5f * h * (1.0f + erff(h * 0.70710678118654752f));
        }
        float4 o0 = {o[0], o[1], o[2], o[3]};
        float4 o1 = {o[4], o[5], o[6], o[7]};
        *(float4*)&out[row * 256 + cg * 8] = o0;
        *(float4*)&out[row * 256 + cg * 8 + 4] = o1;
    }
}

// ---------------------------------------------------------------------------
// Row LayerNorm over 128, optional transposed store out[(b*128+d)*1024+q].
// ---------------------------------------------------------------------------
__global__ void ln128(const float* __restrict__ in, const float* __restrict__ g,
                      const float* __restrict__ b, float* __restrict__ out,
                      int transpose_out) {
    int r = blockIdx.x;
    int t = threadIdx.x;
    float v = in[(long)r * 128 + t];
    __shared__ float ws[4], ws2[4];
    float sm = v, sq = v * v;
#pragma unroll
    for (int o = 16; o >= 1; o >>= 1) {
        sm += __shfl_xor_sync(0xffffffffu, sm, o);
        sq += __shfl_xor_sync(0xffffffffu, sq, o);
    }
    int w = t >> 5;
    if ((t & 31) == 0) { ws[w] = sm; ws2[w] = sq; }
    __syncthreads();
    sm = ws[0] + ws[1] + ws[2] + ws[3];
    sq = ws2[0] + ws2[1] + ws2[2] + ws2[3];
    float mu = sm * (1.f / 128.f);
    float var = sq * (1.f / 128.f) - mu * mu;
    float y = (v - mu) * rsqrtf(var + 1e-5f) * g[t] + b[t];
    if (transpose_out) {
        int bIdx = r >> 10, q = r & 1023;
        out[((long)bIdx * 128 + t) * 1024 + q] = y;
    } else {
        out[(long)r * 128 + t] = y;
    }
}

// ---------------------------------------------------------------------------
extern "C" void kernel_launch(void* const* d_in, const int* in_sizes, int n_in,
                              void* d_out, int out_size) {
    const float* q = (const float*)d_in[0];
    const float* k = (const float*)d_in[1];
    const float* v = (const float*)d_in[2];
    const float* skip = (const float*)d_in[3];
    const unsigned char* mask = (const unsigned char*)d_in[4];
    const float* lnq_g = (const float*)d_in[5];
    const float* lnq_b = (const float*)d_in[6];
    const float* lnk_g = (const float*)d_in[7];
    const float* lnk_b = (const float*)d_in[8];
    const float* lnv_g = (const float*)d_in[9];
    const float* lnv_b = (const float*)d_in[10];
    const float* Wq = (const float*)d_in[11];
    const float* bq = (const float*)d_in[12];
    const float* Wk = (const float*)d_in[13];
    const float* bk = (const float*)d_in[14];
    const float* Wv = (const float*)d_in[15];
    const float* bv = (const float*)d_in[16];
    const float* Wp = (const float*)d_in[17];
    const float* bp = (const float*)d_in[18];
    const float* pre_g = (const float*)d_in[19];
    const float* pre_b = (const float*)d_in[20];
    const float* W1 = (const float*)d_in[21];
    const float* b1 = (const float*)d_in[22];
    const float* W2 = (const float*)d_in[23];
    const float* b2 = (const float*)d_in[24];
    const float* post_g = (const float*)d_in[25];
    const float* post_b = (const float*)d_in[26];
    float* out = (float*)d_out;

    cudaFuncSetAttribute(attn_kernel, cudaFuncAttributeMaxDynamicSharedMemorySize,
                         ATTN_SMEM_BYTES);

    // device scratch symbols are referenced directly by the kernels
    mask_prep<<<1, 256>>>(mask);

    float* d_qh; cudaGetSymbolAddress((void**)&d_qh, g_qh);
    float* d_kh; cudaGetSymbolAddress((void**)&d_kh, g_kh);
    float* d_vh; cudaGetSymbolAddress((void**)&d_vh, g_vh);
    float* d_a;  cudaGetSymbolAddress((void**)&d_a, g_a);
    float* d_z0; cudaGetSymbolAddress((void**)&d_z0, g_z0);
    float* d_z1; cudaGetSymbolAddress((void**)&d_z1, g_z1);
    float* d_hh; cudaGetSymbolAddress((void**)&d_hh, g_hh);
    float* d_z2; cudaGetSymbolAddress((void**)&d_z2, g_z2);

    proj_ln<1024><<<BB * NN * QQ / 64, 256>>>(q, lnq_g, lnq_b, Wq, bq, d_qh);
    proj_ln<640><<<BB * NN * KImg / 64, 256>>>(k, lnk_g, lnk_b, Wk, bk, d_kh);
    proj_ln<640><<<BB * NN * KImg / 64, 256>>>(v, lnv_g, lnv_b, Wv, bv, d_vh);

    attn_kernel<<<dim3(8, 4, 4), 256, ATTN_SMEM_BYTES>>>();

    gemm_256_128<<<BB * QQ / 64, 256>>>(d_a, Wp, bp, skip, 0, d_z0);
    ln128<<<BB * QQ, 128>>>(d_z0, pre_g, pre_b, d_z1, 0);
    gemm_128_256_gelu<<<BB * QQ / 64, 256>>>(d_z1, W1, b1, d_hh);
    gemm_256_128<<<BB * QQ / 64, 256>>>(d_hh, W2, b2, d_z1, 1, d_z2);
    ln128<<<BB * QQ, 128>>>(d_z2, post_g, post_b, out, 1);
}

// round 4
// speedup vs baseline: 1.4453x; 1.4453x over previous
#include <cuda_runtime.h>
#include <math.h>

// Problem constants
constexpr int BB = 4;     // batch
constexpr int NN = 6;     // views
constexpr int DDIM = 128; // model dim
constexpr int QQ = 1024;  // H*W queries
constexpr int KImg = 640; // h*w keys per view
constexpr int MD = 256;   // heads * dim_head

// Scratch (device globals; no allocation allowed)
__device__ float g_qh[BB * NN * QQ * MD];
__device__ float g_kh[BB * NN * KImg * MD];
__device__ float g_vh[BB * NN * KImg * MD];
__device__ float g_a[BB * QQ * MD];
__device__ float g_z0[BB * QQ * DDIM];
__device__ float g_z1[BB * QQ * DDIM];
__device__ float g_hh[BB * QQ * MD];
__device__ float g_z2[BB * QQ * DDIM];
__device__ int g_mask[NN * QQ];

// ---------------------------------------------------------------------------
// Helpers: tf32 convert + mma.m16n8k8 tf32
// ---------------------------------------------------------------------------
__device__ __forceinline__ unsigned int f2tf(float x) {
    unsigned int r;
    asm("cvt.rna.tf32.f32 %0, %1;" : "=r"(r) : "f"(x));
    return r;
}

__device__ __forceinline__ void mma_tf32(float& c0, float& c1, float& c2,
                                         float& c3, unsigned int a0,
                                         unsigned int a1, unsigned int a2,
                                         unsigned int a3, unsigned int b0,
                                         unsigned int b1) {
    asm volatile(
        "mma.sync.aligned.m16n8k8.row.col.f32.tf32.tf32.f32 "
        "{%0,%1,%2,%3},{%4,%5,%6,%7},{%8,%9},{%0,%1,%2,%3};\n"
        : "+f"(c0), "+f"(c1), "+f"(c2), "+f"(c3)
        : "r"(a0), "r"(a1), "r"(a2), "r"(a3), "r"(b0), "r"(b1));
}

// ---------------------------------------------------------------------------
// Mask prep (detect bool/float32/int32 storage, expand to g_mask[n*QQ+q])
// ---------------------------------------------------------------------------
__global__ void mask_prep(const unsigned char* __restrict__ mraw) {
    __shared__ int flagBool, flagFloat;
    int t = threadIdx.x;
    if (t == 0) { flagBool = 0; flagFloat = 0; }
    __syncthreads();
    int fb = 0, ff = 0;
    for (int i = t; i < NN * QQ; i += 256) {
        unsigned char v = mraw[i];
        if (v) {
            int r = i & 3;
            if (r == 1) fb = 1;
            else if (r >= 2) ff = 1;
        }
    }
    if (fb) atomicOr(&flagBool, 1);
    if (ff) atomicOr(&flagFloat, 1);
    __syncthreads();
    int mode = flagBool ? 0 : (flagFloat ? 1 : 2);
    const float* mf = (const float*)mraw;
    const int* mi = (const int*)mraw;
    for (int i = t; i < NN * QQ; i += 256) {
        int q = i / 6, n = i % 6;
        int val;
        if (mode == 0) val = (mraw[i] != 0);
        else if (mode == 1) val = (mf[i] != 0.0f);
        else val = (mi[i] != 0);
        g_mask[n * QQ + q] = val;
    }
}

// ---------------------------------------------------------------------------
// Fused LayerNorm + projection GEMM via tf32 mma.
// Tile: 64 rows x 256 cols, K=128. 8 warps; warp w covers n-range [w*32,w*32+32)
// across all 4 m16 tiles.
// W smem chunk [16k][256] stored column-XOR-swizzled: off = kk*256+(col^SWZ(kk)).
// ---------------------------------------------------------------------------
__device__ __forceinline__ int SWZ(int kk) {
    return ((kk & 3) << 3) | (kk >> 3);
}

template <int S>
__global__ __launch_bounds__(256) void proj_ln_mma(
    const float* __restrict__ x, const float* __restrict__ lg,
    const float* __restrict__ lb, const float* __restrict__ Wm,
    const float* __restrict__ bias, float* __restrict__ out) {
    __shared__ unsigned int Xs[64 * 132];
    __shared__ unsigned int Ws[16 * 256];
    __shared__ float rsum[64][4], rsq[64][4];
    __shared__ float mu_s[64], rs_s[64];
    __shared__ float gs[128], bs[128];
    int t = threadIdx.x;
    int r0 = blockIdx.x * 64;
    int bn = r0 / S;
    int s0 = r0 % S;
    const float* xb = x + (size_t)bn * DDIM * S + s0;
    for (int i = t; i < 64 * 128; i += 256) {
        int sl = i & 63, d = i >> 6;
        Xs[sl * 132 + d] = __float_as_uint(xb[(size_t)d * S + sl]);
    }
    if (t < 128) { gs[t] = lg[t]; bs[t] = lb[t]; }
    __syncthreads();
    {
        int row = t >> 2, part = t & 3;
        float sm = 0.f, sq = 0.f;
#pragma unroll
        for (int j = 0; j < 32; j++) {
            float v = __uint_as_float(Xs[row * 132 + part * 32 + j]);
            sm += v; sq += v * v;
        }
        rsum[row][part] = sm; rsq[row][part] = sq;
    }
    __syncthreads();
    if (t < 64) {
        float sm = rsum[t][0] + rsum[t][1] + rsum[t][2] + rsum[t][3];
        float sq = rsq[t][0] + rsq[t][1] + rsq[t][2] + rsq[t][3];
        float mu = sm * (1.f / 128.f);
        float var = sq * (1.f / 128.f) - mu * mu;
        mu_s[t] = mu;
        rs_s[t] = rsqrtf(var + 1e-5f);
    }
    __syncthreads();
    for (int i = t; i < 64 * 128; i += 256) {
        int d = i & 127, sl = i >> 7;
        float v = __uint_as_float(Xs[sl * 132 + d]);
        Xs[sl * 132 + d] = f2tf((v - mu_s[sl]) * rs_s[sl] * gs[d] + bs[d]);
    }

    int warp = t >> 5, lane = t & 31;
    int g = lane >> 2, tg = lane & 3;
    int n0 = warp * 32;
    float acc[4][4][4];
#pragma unroll
    for (int mt = 0; mt < 4; mt++)
#pragma unroll
        for (int nt = 0; nt < 4; nt++)
#pragma unroll
            for (int c = 0; c < 4; c++) acc[mt][nt][c] = 0.f;

    for (int kc = 0; kc < 128; kc += 16) {
        __syncthreads();
        for (int i = t; i < 16 * 256; i += 256) {
            int kk = i >> 8, col = i & 255;
            Ws[kk * 256 + (col ^ SWZ(kk))] = f2tf(Wm[(size_t)(kc + kk) * 256 + col]);
        }
        __syncthreads();
#pragma unroll
        for (int ks = 0; ks < 2; ks++) {
            int kb_ = 8 * ks;
            unsigned int a[4][4];
#pragma unroll
            for (int mt = 0; mt < 4; mt++) {
                int row = mt * 16 + g;
                a[mt][0] = Xs[row * 132 + kc + kb_ + tg];
                a[mt][1] = Xs[(row + 8) * 132 + kc + kb_ + tg];
                a[mt][2] = Xs[row * 132 + kc + kb_ + tg + 4];
                a[mt][3] = Xs[(row + 8) * 132 + kc + kb_ + tg + 4];
            }
#pragma unroll
            for (int nt = 0; nt < 4; nt++) {
                int col = n0 + nt * 8 + g;
                int kk0 = kb_ + tg, kk1 = kb_ + tg + 4;
                unsigned int b0 = Ws[kk0 * 256 + (col ^ SWZ(kk0))];
                unsigned int b1 = Ws[kk1 * 256 + (col ^ SWZ(kk1))];
#pragma unroll
                for (int mt = 0; mt < 4; mt++)
                    mma_tf32(acc[mt][nt][0], acc[mt][nt][1], acc[mt][nt][2],
                             acc[mt][nt][3], a[mt][0], a[mt][1], a[mt][2],
                             a[mt][3], b0, b1);
            }
        }
    }
#pragma unroll
    for (int mt = 0; mt < 4; mt++)
#pragma unroll
        for (int nt = 0; nt < 4; nt++) {
            int row = r0 + mt * 16 + g;
            int col = n0 + nt * 8 + 2 * tg;
            float bv0 = __ldg(&bias[col]);
            float bv1 = __ldg(&bias[col + 1]);
            float2 v0 = {acc[mt][nt][0] + bv0, acc[mt][nt][1] + bv1};
            float2 v1 = {acc[mt][nt][2] + bv0, acc[mt][nt][3] + bv1};
            *(float2*)&out[(size_t)row * 256 + col] = v0;
            *(float2*)&out[(size_t)(row + 8) * 256 + col] = v1;
        }
}

// ---------------------------------------------------------------------------
// Flash attention with tf32 mma.
// Block: (qtile 128, head m, batch b). 8 warps; warp handles 16 q-rows.
// Smem: Qs[128][68], Ks[64][68], Vt swizzled [64*64], Ps[128][68] (all tf32).
// ---------------------------------------------------------------------------
constexpr int ATTN_SMEM_WORDS = 128 * 68 + 64 * 68 + 64 * 64 + 128 * 68;
constexpr int ATTN_SMEM_BYTES = ATTN_SMEM_WORDS * 4;

__global__ __launch_bounds__(256) void attn_kernel() {
    extern __shared__ unsigned int smem_u[];
    unsigned int* Qs = smem_u;              // [128][68]
    unsigned int* Ks = Qs + 128 * 68;       // [64][68]
    unsigned int* Vt = Ks + 64 * 68;        // [64*64] swizzled (d-major)
    unsigned int* Ps = Vt + 64 * 64;        // [128][68]

    int t = threadIdx.x;
    int warp = t >> 5, lane = t & 31;
    int g = lane >> 2, tg = lane & 3;
    int qt = blockIdx.x, m = blockIdx.y, b = blockIdx.z;
    int q0 = warp * 16;

    float o[8][4];
#pragma unroll
    for (int nt = 0; nt < 8; nt++)
#pragma unroll
        for (int c = 0; c < 4; c++) o[nt][c] = 0.f;
    float mrun0 = -1e30f, mrun1 = -1e30f, lrun0 = 0.f, lrun1 = 0.f;

    for (int n = 0; n < 6; n++) {
        __syncthreads();
        const float* qbase =
            g_qh + (size_t)((b * 6 + n) * 1024 + qt * 128) * 256 + m * 64;
        for (int i = t; i < 128 * 64; i += 256) {
            int q = i >> 6, d = i & 63;
            Qs[q * 68 + d] = f2tf(qbase[q * 256 + d] * 0.125f);
        }
        int mk0 = __ldg(&g_mask[n * 1024 + qt * 128 + q0 + g]);
        int mk1 = __ldg(&g_mask[n * 1024 + qt * 128 + q0 + g + 8]);

        const float* kb0 = g_kh + (size_t)((b * 6 + n) * 640) * 256 + m * 64;
        const float* vb0 = g_vh + (size_t)((b * 6 + n) * 640) * 256 + m * 64;

        for (int kt = 0; kt < 10; kt++) {
            __syncthreads();
            const float* kb = kb0 + (size_t)kt * 64 * 256;
            const float* vb = vb0 + (size_t)kt * 64 * 256;
            for (int i = t; i < 64 * 64; i += 256) {
                int kl = i >> 6, d = i & 63;
                Ks[kl * 68 + d] = f2tf(kb[kl * 256 + d]);
            }
            for (int i = t; i < 64 * 64; i += 256) {
                int kp = i >> 6, d = i & 63;
                int sg = 4 * (d & 7) + ((d >> 3) & 3);
                Vt[d * 64 + (kp ^ sg)] = f2tf(vb[kp * 256 + d]);
            }
            __syncthreads();

            // S = Q K^T : warp computes 16q x 64k
            float s[8][4];
#pragma unroll
            for (int nt = 0; nt < 8; nt++)
#pragma unroll
                for (int c = 0; c < 4; c++) s[nt][c] = 0.f;
#pragma unroll
            for (int ks = 0; ks < 8; ks++) {
                unsigned int a0 = Qs[(q0 + g) * 68 + 8 * ks + tg];
                unsigned int a1 = Qs[(q0 + g + 8) * 68 + 8 * ks + tg];
                unsigned int a2 = Qs[(q0 + g) * 68 + 8 * ks + tg + 4];
                unsigned int a3 = Qs[(q0 + g + 8) * 68 + 8 * ks + tg + 4];
#pragma unroll
                for (int nt = 0; nt < 8; nt++) {
                    unsigned int b0 = Ks[(8 * nt + g) * 68 + 8 * ks + tg];
                    unsigned int b1 = Ks[(8 * nt + g) * 68 + 8 * ks + tg + 4];
                    mma_tf32(s[nt][0], s[nt][1], s[nt][2], s[nt][3], a0, a1,
                             a2, a3, b0, b1);
                }
            }

            if (!mk0) {
#pragma unroll
                for (int nt = 0; nt < 8; nt++) { s[nt][0] = -1e30f; s[nt][1] = -1e30f; }
            }
            if (!mk1) {
#pragma unroll
                for (int nt = 0; nt < 8; nt++) { s[nt][2] = -1e30f; s[nt][3] = -1e30f; }
            }

            // online softmax, rows g (c0,c1) and g+8 (c2,c3)
            float rm0 = -1e30f, rm1 = -1e30f;
#pragma unroll
            for (int nt = 0; nt < 8; nt++) {
                rm0 = fmaxf(rm0, fmaxf(s[nt][0], s[nt][1]));
                rm1 = fmaxf(rm1, fmaxf(s[nt][2], s[nt][3]));
            }
            rm0 = fmaxf(rm0, __shfl_xor_sync(0xffffffffu, rm0, 1));
            rm0 = fmaxf(rm0, __shfl_xor_sync(0xffffffffu, rm0, 2));
            rm1 = fmaxf(rm1, __shfl_xor_sync(0xffffffffu, rm1, 1));
            rm1 = fmaxf(rm1, __shfl_xor_sync(0xffffffffu, rm1, 2));
            float mn0 = fmaxf(mrun0, rm0), mn1 = fmaxf(mrun1, rm1);
            float cr0 = __expf(mrun0 - mn0), cr1 = __expf(mrun1 - mn1);
            mrun0 = mn0; mrun1 = mn1;
            float sum0 = 0.f, sum1 = 0.f;
#pragma unroll
            for (int nt = 0; nt < 8; nt++) {
                float p00 = __expf(s[nt][0] - mn0);
                float p01 = __expf(s[nt][1] - mn0);
                float p10 = __expf(s[nt][2] - mn1);
                float p11 = __expf(s[nt][3] - mn1);
                sum0 += p00 + p01;
                sum1 += p10 + p11;
                uint2 w0 = {f2tf(p00), f2tf(p01)};
                uint2 w1 = {f2tf(p10), f2tf(p11)};
                *(uint2*)&Ps[(q0 + g) * 68 + 8 * nt + 2 * tg] = w0;
                *(uint2*)&Ps[(q0 + g + 8) * 68 + 8 * nt + 2 * tg] = w1;
            }
            sum0 += __shfl_xor_sync(0xffffffffu, sum0, 1);
            sum0 += __shfl_xor_sync(0xffffffffu, sum0, 2);
            sum1 += __shfl_xor_sync(0xffffffffu, sum1, 1);
            sum1 += __shfl_xor_sync(0xffffffffu, sum1, 2);
            lrun0 = lrun0 * cr0 + sum0;
            lrun1 = lrun1 * cr1 + sum1;
#pragma unroll
            for (int nt = 0; nt < 8; nt++) {
                o[nt][0] *= cr0; o[nt][1] *= cr0;
                o[nt][2] *= cr1; o[nt][3] *= cr1;
            }
            __syncwarp();

            // O += P V : 16q x 64d
#pragma unroll
            for (int ks = 0; ks < 8; ks++) {
                unsigned int a0 = Ps[(q0 + g) * 68 + 8 * ks + tg];
                unsigned int a1 = Ps[(q0 + g + 8) * 68 + 8 * ks + tg];
                unsigned int a2 = Ps[(q0 + g) * 68 + 8 * ks + tg + 4];
                unsigned int a3 = Ps[(q0 + g + 8) * 68 + 8 * ks + tg + 4];
#pragma unroll
                for (int nt = 0; nt < 8; nt++) {
                    int dd = 8 * nt + g;
                    int sg = 4 * g + (nt & 3);
                    unsigned int b0 = Vt[dd * 64 + ((8 * ks + tg) ^ sg)];
                    unsigned int b1 = Vt[dd * 64 + ((8 * ks + tg + 4) ^ sg)];
                    mma_tf32(o[nt][0], o[nt][1], o[nt][2], o[nt][3], a0, a1,
                             a2, a3, b0, b1);
                }
            }
        }
    }

    float inv0 = 1.f / lrun0, inv1 = 1.f / lrun1;
    float* ob = g_a + (size_t)(b * 1024 + qt * 128 + q0) * 256 + m * 64;
#pragma unroll
    for (int nt = 0; nt < 8; nt++) {
        float2 v0 = {o[nt][0] * inv0, o[nt][1] * inv0};
        float2 v1 = {o[nt][2] * inv1, o[nt][3] * inv1};
        *(float2*)&ob[g * 256 + 8 * nt + 2 * tg] = v0;
        *(float2*)&ob[(g + 8) * 256 + 8 * nt + 2 * tg] = v1;
    }
}

// ---------------------------------------------------------------------------
// Tail kernels (scalar; small fraction of runtime)
// ---------------------------------------------------------------------------
__global__ __launch_bounds__(256) void gemm_256_128(
    const float* __restrict__ A, const float* __restrict__ Wm,
    const float* __restrict__ bias, const float* __restrict__ extra, int mode,
    float* __restrict__ out) {
    __shared__ float Xs[64][17];
    __shared__ float Ws[16][132];
    int t = threadIdx.x;
    int r0 = blockIdx.x * 64;
    int cg = t & 31, rg = t >> 5;
    float acc[8][4];
#pragma unroll
    for (int i = 0; i < 8; i++)
#pragma unroll
        for (int j = 0; j < 4; j++) acc[i][j] = 0.f;
    for (int kc = 0; kc < 256; kc += 16) {
        __syncthreads();
        for (int i = t; i < 64 * 16; i += 256) {
            int row = i >> 4, kk = i & 15;
            Xs[row][kk] = A[(size_t)(r0 + row) * 256 + kc + kk];
        }
        for (int i = t; i < 16 * 128; i += 256) {
            int kk = i >> 7, j = i & 127;
            Ws[kk][j] = Wm[(kc + kk) * 128 + j];
        }
        __syncthreads();
#pragma unroll
        for (int kk = 0; kk < 16; kk++) {
            float a_[8];
#pragma unroll
            for (int i2 = 0; i2 < 8; i2++) a_[i2] = Xs[rg * 8 + i2][kk];
            float4 b0 = *(const float4*)&Ws[kk][cg * 4];
            float b_[4] = {b0.x, b0.y, b0.z, b0.w};
#pragma unroll
            for (int i2 = 0; i2 < 8; i2++)
#pragma unroll
                for (int j2 = 0; j2 < 4; j2++) acc[i2][j2] += a_[i2] * b_[j2];
        }
    }
    float4 bb = *(const float4*)&bias[cg * 4];
    float bv[4] = {bb.x, bb.y, bb.z, bb.w};
#pragma unroll
    for (int i2 = 0; i2 < 8; i2++) {
        int row = r0 + rg * 8 + i2;
        float o[4];
#pragma unroll
        for (int j2 = 0; j2 < 4; j2++) {
            float add;
            int col = cg * 4 + j2;
            if (mode == 0) {
                int bIdx = row >> 10, q = row & 1023;
                add = extra[bIdx * (128 * 1024) + col * 1024 + q];
            } else {
                add = extra[(size_t)row * 128 + col];
            }
            o[j2] = acc[i2][j2] + bv[j2] + add;
        }
        float4 ov = {o[0], o[1], o[2], o[3]};
        *(float4*)&out[(size_t)row * 128 + cg * 4] = ov;
    }
}

__global__ __launch_bounds__(256) void gemm_128_256_gelu(
    const float* __restrict__ A, const float* __restrict__ Wm,
    const float* __restrict__ bias, float* __restrict__ out) {
    __shared__ float Xs[64][17];
    __shared__ float Ws[16][260];
    int t = threadIdx.x;
    int r0 = blockIdx.x * 64;
    int cg = t & 31, rg = t >> 5;
    float acc[8][8];
#pragma unroll
    for (int i = 0; i < 8; i++)
#pragma unroll
        for (int j = 0; j < 8; j++) acc[i][j] = 0.f;
    for (int kc = 0; kc < 128; kc += 16) {
        __syncthreads();
        for (int i = t; i < 64 * 16; i += 256) {
            int row = i >> 4, kk = i & 15;
            Xs[row][kk] = A[(size_t)(r0 + row) * 128 + kc + kk];
        }
        for (int i = t; i < 16 * 256; i += 256) {
            int kk = i >> 8, j = i & 255;
            Ws[kk][j] = Wm[(kc + kk) * 256 + j];
        }
        __syncthreads();
#pragma unroll
        for (int kk = 0; kk < 16; kk++) {
            float a_[8];
#pragma unroll
            for (int i2 = 0; i2 < 8; i2++) a_[i2] = Xs[rg * 8 + i2][kk];
            float4 b0 = *(const float4*)&Ws[kk][cg * 8];
            float4 b1 = *(const float4*)&Ws[kk][cg * 8 + 4];
            float b_[8] = {b0.x, b0.y, b0.z, b0.w, b1.x, b1.y, b1.z, b1.w};
#pragma unroll
            for (int i2 = 0; i2 < 8; i2++)
#pragma unroll
                for (int j2 = 0; j2 < 8; j2++) acc[i2][j2] += a_[i2] * b_[j2];
        }
    }
    float4 bb0 = *(const float4*)&bias[cg * 8];
    float4 bb1 = *(const float4*)&bias[cg * 8 + 4];
    float bv[8] = {bb0.x, bb0.y, bb0.z, bb0.w, bb1.x, bb1.y, bb1.z, bb1.w};
#pragma unroll
    for (int i2 = 0; i2 < 8; i2++) {
        size_t row = (size_t)(r0 + rg * 8 + i2);
        float o[8];
#pragma unroll
        for (int j2 = 0; j2 < 8; j2++) {
            float h = acc[i2][j2] + bv[j2];
            o[j2] = 0.5f * h * (1.0f + erff(h * 0.70710678118654752f));
        }
        float4 o0 = {o[0], o[1], o[2], o[3]};
        float4 o1 = {o[4], o[5], o[6], o[7]};
        *(float4*)&out[row * 256 + cg * 8] = o0;
        *(float4*)&out[row * 256 + cg * 8 + 4] = o1;
    }
}

__global__ void ln128(const float* __restrict__ in, const float* __restrict__ g,
                      const float* __restrict__ b, float* __restrict__ out,
                      int transpose_out) {
    int r = blockIdx.x;
    int t = threadIdx.x;
    float v = in[(size_t)r * 128 + t];
    __shared__ float ws[4], ws2[4];
    float sm = v, sq = v * v;
#pragma unroll
    for (int o = 16; o >= 1; o >>= 1) {
        sm += __shfl_xor_sync(0xffffffffu, sm, o);
        sq += __shfl_xor_sync(0xffffffffu, sq, o);
    }
    int w = t >> 5;
    if ((t & 31) == 0) { ws[w] = sm; ws2[w] = sq; }
    __syncthreads();
    sm = ws[0] + ws[1] + ws[2] + ws[3];
    sq = ws2[0] + ws2[1] + ws2[2] + ws2[3];
    float mu = sm * (1.f / 128.f);
    float var = sq * (1.f / 128.f) - mu * mu;
    float y = (v - mu) * rsqrtf(var + 1e-5f) * g[t] + b[t];
    if (transpose_out) {
        int bIdx = r >> 10, q = r & 1023;
        out[((size_t)bIdx * 128 + t) * 1024 + q] = y;
    } else {
        out[(size_t)r * 128 + t] = y;
    }
}

// ---------------------------------------------------------------------------
extern "C" void kernel_launch(void* const* d_in, const int* in_sizes, int n_in,
                              void* d_out, int out_size) {
    const float* q = (const float*)d_in[0];
    const float* k = (const float*)d_in[1];
    const float* v = (const float*)d_in[2];
    const float* skip = (const float*)d_in[3];
    const unsigned char* mask = (const unsigned char*)d_in[4];
    const float* lnq_g = (const float*)d_in[5];
    const float* lnq_b = (const float*)d_in[6];
    const float* lnk_g = (const float*)d_in[7];
    const float* lnk_b = (const float*)d_in[8];
    const float* lnv_g = (const float*)d_in[9];
    const float* lnv_b = (const float*)d_in[10];
    const float* Wq = (const float*)d_in[11];
    const float* bq = (const float*)d_in[12];
    const float* Wk = (const float*)d_in[13];
    const float* bk = (const float*)d_in[14];
    const float* Wv = (const float*)d_in[15];
    const float* bv = (const float*)d_in[16];
    const float* Wp = (const float*)d_in[17];
    const float* bp = (const float*)d_in[18];
    const float* pre_g = (const float*)d_in[19];
    const float* pre_b = (const float*)d_in[20];
    const float* W1 = (const float*)d_in[21];
    const float* b1 = (const float*)d_in[22];
    const float* W2 = (const float*)d_in[23];
    const float* b2 = (const float*)d_in[24];
    const float* post_g = (const float*)d_in[25];
    const float* post_b = (const float*)d_in[26];
    float* out = (float*)d_out;

    cudaFuncSetAttribute(attn_kernel,
                         cudaFuncAttributeMaxDynamicSharedMemorySize,
                         ATTN_SMEM_BYTES);

    mask_prep<<<1, 256>>>(mask);

    float* d_qh; cudaGetSymbolAddress((void**)&d_qh, g_qh);
    float* d_kh; cudaGetSymbolAddress((void**)&d_kh, g_kh);
    float* d_vh; cudaGetSymbolAddress((void**)&d_vh, g_vh);
    float* d_a;  cudaGetSymbolAddress((void**)&d_a, g_a);
    float* d_z0; cudaGetSymbolAddress((void**)&d_z0, g_z0);
    float* d_z1; cudaGetSymbolAddress((void**)&d_z1, g_z1);
    float* d_hh; cudaGetSymbolAddress((void**)&d_hh, g_hh);
    float* d_z2; cudaGetSymbolAddress((void**)&d_z2, g_z2);

    proj_ln_mma<1024><<<BB * NN * QQ / 64, 256>>>(q, lnq_g, lnq_b, Wq, bq, d_qh);
    proj_ln_mma<640><<<BB * NN * KImg / 64, 256>>>(k, lnk_g, lnk_b, Wk, bk, d_kh);
    proj_ln_mma<640><<<BB * NN * KImg / 64, 256>>>(v, lnv_g, lnv_b, Wv, bv, d_vh);

    attn_kernel<<<dim3(8, 4, 4), 256, ATTN_SMEM_BYTES>>>();

    gemm_256_128<<<BB * QQ / 64, 256>>>(d_a, Wp, bp, skip, 0, d_z0);
    ln128<<<BB * QQ, 128>>>(d_z0, pre_g, pre_b, d_z1, 0);
    gemm_128_256_gelu<<<BB * QQ / 64, 256>>>(d_z1, W1, b1, d_hh);
    gemm_256_128<<<BB * QQ / 64, 256>>>(d_hh, W2, b2, d_z1, 1, d_z2);
    ln128<<<BB * QQ, 128>>>(d_z2, post_g, post_b, out, 1);
}

// round 5
// speedup vs baseline: 2.1146x; 1.4631x over previous
#include <cuda_runtime.h>
#include <math.h>

// Problem constants
constexpr int BB = 4;     // batch
constexpr int NN = 6;     // views
constexpr int DDIM = 128; // model dim
constexpr int QQ = 1024;  // H*W queries
constexpr int KImg = 640; // h*w keys per view
constexpr int MD = 256;   // heads * dim_head

// Scratch (device globals; no allocation allowed)
__device__ float g_qh[BB * NN * QQ * MD];
__device__ float g_kh[BB * NN * KImg * MD];
__device__ float g_vh[BB * NN * KImg * MD];
__device__ float g_a[BB * QQ * MD];
__device__ float g_z1[BB * QQ * DDIM];
__device__ float g_hh[BB * QQ * MD];
__device__ int g_mask[NN * QQ];

// ---------------------------------------------------------------------------
// Helpers
// ---------------------------------------------------------------------------
__device__ __forceinline__ unsigned int f2tf(float x) {
    unsigned int r;
    asm("cvt.rna.tf32.f32 %0, %1;" : "=r"(r) : "f"(x));
    return r;
}

__device__ __forceinline__ float ex2f(float x) {
    float y;
    asm("ex2.approx.f32 %0, %1;" : "=f"(y) : "f"(x));
    return y;
}

__device__ __forceinline__ void mma_tf32(float& c0, float& c1, float& c2,
                                         float& c3, unsigned int a0,
                                         unsigned int a1, unsigned int a2,
                                         unsigned int a3, unsigned int b0,
                                         unsigned int b1) {
    asm volatile(
        "mma.sync.aligned.m16n8k8.row.col.f32.tf32.tf32.f32 "
        "{%0,%1,%2,%3},{%4,%5,%6,%7},{%8,%9},{%0,%1,%2,%3};\n"
        : "+f"(c0), "+f"(c1), "+f"(c2), "+f"(c3)
        : "r"(a0), "r"(a1), "r"(a2), "r"(a3), "r"(b0), "r"(b1));
}

__device__ __forceinline__ void cpa16(unsigned int dst, const void* src) {
    asm volatile("cp.async.cg.shared.global [%0], [%1], 16;" ::"r"(dst),
                 "l"(src));
}
__device__ __forceinline__ void cpa_commit() {
    asm volatile("cp.async.commit_group;");
}
__device__ __forceinline__ void cpa_wait0() {
    asm volatile("cp.async.wait_group 0;");
}

// ---------------------------------------------------------------------------
// Mask prep (detect bool/float32/int32 storage, expand to g_mask[n*QQ+q])
// ---------------------------------------------------------------------------
__global__ void mask_prep(const unsigned char* __restrict__ mraw) {
    __shared__ int flagBool, flagFloat;
    int t = threadIdx.x;
    if (t == 0) { flagBool = 0; flagFloat = 0; }
    __syncthreads();
    int fb = 0, ff = 0;
    for (int i = t; i < NN * QQ; i += 256) {
        unsigned char v = mraw[i];
        if (v) {
            int r = i & 3;
            if (r == 1) fb = 1;
            else if (r >= 2) ff = 1;
        }
    }
    if (fb) atomicOr(&flagBool, 1);
    if (ff) atomicOr(&flagFloat, 1);
    __syncthreads();
    int mode = flagBool ? 0 : (flagFloat ? 1 : 2);
    const float* mf = (const float*)mraw;
    const int* mi = (const int*)mraw;
    for (int i = t; i < NN * QQ; i += 256) {
        int q = i / 6, n = i % 6;
        int val;
        if (mode == 0) val = (mraw[i] != 0);
        else if (mode == 1) val = (mf[i] != 0.0f);
        else val = (mi[i] != 0);
        g_mask[n * QQ + q] = val;
    }
}

// ---------------------------------------------------------------------------
// Fused LayerNorm + projection GEMM via tf32 mma (unchanged from R4).
// ---------------------------------------------------------------------------
__device__ __forceinline__ int SWZ(int kk) {
    return ((kk & 3) << 3) | (kk >> 3);
}

template <int S>
__global__ __launch_bounds__(256) void proj_ln_mma(
    const float* __restrict__ x, const float* __restrict__ lg,
    const float* __restrict__ lb, const float* __restrict__ Wm,
    const float* __restrict__ bias, float* __restrict__ out) {
    __shared__ unsigned int Xs[64 * 132];
    __shared__ unsigned int Ws[16 * 256];
    __shared__ float rsum[64][4], rsq[64][4];
    __shared__ float mu_s[64], rs_s[64];
    __shared__ float gs[128], bs[128];
    int t = threadIdx.x;
    int r0 = blockIdx.x * 64;
    int bn = r0 / S;
    int s0 = r0 % S;
    const float* xb = x + (size_t)bn * DDIM * S + s0;
    for (int i = t; i < 64 * 128; i += 256) {
        int sl = i & 63, d = i >> 6;
        Xs[sl * 132 + d] = __float_as_uint(xb[(size_t)d * S + sl]);
    }
    if (t < 128) { gs[t] = lg[t]; bs[t] = lb[t]; }
    __syncthreads();
    {
        int row = t >> 2, part = t & 3;
        float sm = 0.f, sq = 0.f;
#pragma unroll
        for (int j = 0; j < 32; j++) {
            float v = __uint_as_float(Xs[row * 132 + part * 32 + j]);
            sm += v; sq += v * v;
        }
        rsum[row][part] = sm; rsq[row][part] = sq;
    }
    __syncthreads();
    if (t < 64) {
        float sm = rsum[t][0] + rsum[t][1] + rsum[t][2] + rsum[t][3];
        float sq = rsq[t][0] + rsq[t][1] + rsq[t][2] + rsq[t][3];
        float mu = sm * (1.f / 128.f);
        float var = sq * (1.f / 128.f) - mu * mu;
        mu_s[t] = mu;
        rs_s[t] = rsqrtf(var + 1e-5f);
    }
    __syncthreads();
    for (int i = t; i < 64 * 128; i += 256) {
        int d = i & 127, sl = i >> 7;
        float v = __uint_as_float(Xs[sl * 132 + d]);
        Xs[sl * 132 + d] = f2tf((v - mu_s[sl]) * rs_s[sl] * gs[d] + bs[d]);
    }

    int warp = t >> 5, lane = t & 31;
    int g = lane >> 2, tg = lane & 3;
    int n0 = warp * 32;
    float acc[4][4][4];
#pragma unroll
    for (int mt = 0; mt < 4; mt++)
#pragma unroll
        for (int nt = 0; nt < 4; nt++)
#pragma unroll
            for (int c = 0; c < 4; c++) acc[mt][nt][c] = 0.f;

    for (int kc = 0; kc < 128; kc += 16) {
        __syncthreads();
        for (int i = t; i < 16 * 256; i += 256) {
            int kk = i >> 8, col = i & 255;
            Ws[kk * 256 + (col ^ SWZ(kk))] = f2tf(Wm[(size_t)(kc + kk) * 256 + col]);
        }
        __syncthreads();
#pragma unroll
        for (int ks = 0; ks < 2; ks++) {
            int kb_ = 8 * ks;
            unsigned int a[4][4];
#pragma unroll
            for (int mt = 0; mt < 4; mt++) {
                int row = mt * 16 + g;
                a[mt][0] = Xs[row * 132 + kc + kb_ + tg];
                a[mt][1] = Xs[(row + 8) * 132 + kc + kb_ + tg];
                a[mt][2] = Xs[row * 132 + kc + kb_ + tg + 4];
                a[mt][3] = Xs[(row + 8) * 132 + kc + kb_ + tg + 4];
            }
#pragma unroll
            for (int nt = 0; nt < 4; nt++) {
                int col = n0 + nt * 8 + g;
                int kk0 = kb_ + tg, kk1 = kb_ + tg + 4;
                unsigned int b0 = Ws[kk0 * 256 + (col ^ SWZ(kk0))];
                unsigned int b1 = Ws[kk1 * 256 + (col ^ SWZ(kk1))];
#pragma unroll
                for (int mt = 0; mt < 4; mt++)
                    mma_tf32(acc[mt][nt][0], acc[mt][nt][1], acc[mt][nt][2],
                             acc[mt][nt][3], a[mt][0], a[mt][1], a[mt][2],
                             a[mt][3], b0, b1);
            }
        }
    }
#pragma unroll
    for (int mt = 0; mt < 4; mt++)
#pragma unroll
        for (int nt = 0; nt < 4; nt++) {
            int row = r0 + mt * 16 + g;
            int col = n0 + nt * 8 + 2 * tg;
            float bv0 = __ldg(&bias[col]);
            float bv1 = __ldg(&bias[col + 1]);
            float2 v0 = {acc[mt][nt][0] + bv0, acc[mt][nt][1] + bv1};
            float2 v1 = {acc[mt][nt][2] + bv0, acc[mt][nt][3] + bv1};
            *(float2*)&out[(size_t)row * 256 + col] = v0;
            *(float2*)&out[(size_t)(row + 8) * 256 + col] = v1;
        }
}

// ---------------------------------------------------------------------------
// Flash attention, tf32 mma, cp.async double-buffered K/V.
// Block: 64 q-rows, 4 warps (warp = 16 q). Grid (16 qtiles, 4 heads, 4 batch).
// K layout [k][d] stride 68; V layout [k][d] stride 72 (both natural; raw fp32
// bits fed to tf32 mma). P round-trip stride 68.
// ---------------------------------------------------------------------------
constexpr int QS_W = 64 * 68;                // 4352
constexpr int KS_W = 64 * 68;                // per buffer
constexpr int VS_W = 64 * 72;                // per buffer
constexpr int PS_W = 64 * 68;
constexpr int ATTN_SMEM_WORDS = QS_W + 2 * KS_W + 2 * VS_W + PS_W;
constexpr int ATTN_SMEM_BYTES = ATTN_SMEM_WORDS * 4;

__global__ __launch_bounds__(128) void attn_kernel() {
    extern __shared__ unsigned int smem_u[];
    unsigned int* Qs = smem_u;
    unsigned int* KsB = Qs + QS_W;            // 2 buffers
    unsigned int* VsB = KsB + 2 * KS_W;       // 2 buffers
    unsigned int* Ps = VsB + 2 * VS_W;

    int t = threadIdx.x;
    int warp = t >> 5, lane = t & 31;
    int g = lane >> 2, tg = lane & 3;
    int qt = blockIdx.x, m = blockIdx.y, b = blockIdx.z;
    int q0 = warp * 16;

    const float* kbase = g_kh + (size_t)(b * 6) * 640 * 256 + m * 64;
    const float* vbase = g_vh + (size_t)(b * 6) * 640 * 256 + m * 64;

    int row_f = t >> 4;          // 0..7 base row for fills (stride 8)
    int c_f = t & 15;            // 16B chunk within row

    // issue cp.async fills for tile `it` into buffer `buf`
    auto issue_tile = [&](int it, int buf) {
        const float* kb = kbase + (size_t)it * 64 * 256;
        const float* vb = vbase + (size_t)it * 64 * 256;
        unsigned int* Kd = KsB + buf * KS_W;
        unsigned int* Vd = VsB + buf * VS_W;
#pragma unroll
        for (int j = 0; j < 8; j++) {
            int row = row_f + 8 * j;
            unsigned int kdst =
                (unsigned int)__cvta_generic_to_shared(&Kd[row * 68 + 4 * c_f]);
            cpa16(kdst, kb + row * 256 + 4 * c_f);
            unsigned int vdst =
                (unsigned int)__cvta_generic_to_shared(&Vd[row * 72 + 4 * c_f]);
            cpa16(vdst, vb + row * 256 + 4 * c_f);
        }
        cpa_commit();
    };

    float o[8][4];
#pragma unroll
    for (int nt = 0; nt < 8; nt++)
#pragma unroll
        for (int c = 0; c < 4; c++) o[nt][c] = 0.f;
    float mrun0 = -1e30f, mrun1 = -1e30f, lrun0 = 0.f, lrun1 = 0.f;
    int mk0 = 1, mk1 = 1;

    constexpr float SC = 0.125f * 1.4426950408889634f; // scale * log2(e)

    issue_tile(0, 0);

    for (int it = 0; it < 60; it++) {
        int buf = it & 1;
        if (it % 10 == 0) {
            int n = it / 10;
            __syncthreads(); // all warps done reading old Qs
            const float* qbase =
                g_qh + (size_t)((b * 6 + n) * 1024 + qt * 64) * 256 + m * 64;
#pragma unroll
            for (int j = 0; j < 8; j++) {
                int idx = t + 128 * j;
                int qr = idx >> 4, c = idx & 15;
                float4 vv = *(const float4*)(qbase + qr * 256 + 4 * c);
                uint4 st = {__float_as_uint(vv.x * SC), __float_as_uint(vv.y * SC),
                            __float_as_uint(vv.z * SC), __float_as_uint(vv.w * SC)};
                *(uint4*)&Qs[qr * 68 + 4 * c] = st;
            }
            mk0 = __ldg(&g_mask[n * 1024 + qt * 64 + q0 + g]);
            mk1 = __ldg(&g_mask[n * 1024 + qt * 64 + q0 + g + 8]);
        }
        cpa_wait0();
        __syncthreads(); // Ks/Vs[buf] + Qs visible to all
        if (it + 1 < 60) issue_tile(it + 1, buf ^ 1);

        unsigned int* Kb = KsB + buf * KS_W;
        unsigned int* Vb = VsB + buf * VS_W;

        // S = Q K^T : 16q x 64k per warp
        float s[8][4];
#pragma unroll
        for (int nt = 0; nt < 8; nt++)
#pragma unroll
            for (int c = 0; c < 4; c++) s[nt][c] = 0.f;
#pragma unroll
        for (int ks = 0; ks < 8; ks++) {
            unsigned int a0 = Qs[(q0 + g) * 68 + 8 * ks + tg];
            unsigned int a1 = Qs[(q0 + g + 8) * 68 + 8 * ks + tg];
            unsigned int a2 = Qs[(q0 + g) * 68 + 8 * ks + tg + 4];
            unsigned int a3 = Qs[(q0 + g + 8) * 68 + 8 * ks + tg + 4];
#pragma unroll
            for (int nt = 0; nt < 8; nt++) {
                unsigned int b0 = Kb[(8 * nt + g) * 68 + 8 * ks + tg];
                unsigned int b1 = Kb[(8 * nt + g) * 68 + 8 * ks + tg + 4];
                mma_tf32(s[nt][0], s[nt][1], s[nt][2], s[nt][3], a0, a1, a2,
                         a3, b0, b1);
            }
        }

        if (!mk0) {
#pragma unroll
            for (int nt = 0; nt < 8; nt++) { s[nt][0] = -1e30f; s[nt][1] = -1e30f; }
        }
        if (!mk1) {
#pragma unroll
            for (int nt = 0; nt < 8; nt++) { s[nt][2] = -1e30f; s[nt][3] = -1e30f; }
        }

        // online softmax (base-2), rows g (c0,c1) and g+8 (c2,c3)
        float rm0 = -1e30f, rm1 = -1e30f;
#pragma unroll
        for (int nt = 0; nt < 8; nt++) {
            rm0 = fmaxf(rm0, fmaxf(s[nt][0], s[nt][1]));
            rm1 = fmaxf(rm1, fmaxf(s[nt][2], s[nt][3]));
        }
        rm0 = fmaxf(rm0, __shfl_xor_sync(0xffffffffu, rm0, 1));
        rm0 = fmaxf(rm0, __shfl_xor_sync(0xffffffffu, rm0, 2));
        rm1 = fmaxf(rm1, __shfl_xor_sync(0xffffffffu, rm1, 1));
        rm1 = fmaxf(rm1, __shfl_xor_sync(0xffffffffu, rm1, 2));
        float mn0 = fmaxf(mrun0, rm0), mn1 = fmaxf(mrun1, rm1);
        float cr0 = ex2f(mrun0 - mn0), cr1 = ex2f(mrun1 - mn1);
        mrun0 = mn0; mrun1 = mn1;
        float sum0 = 0.f, sum1 = 0.f;
#pragma unroll
        for (int nt = 0; nt < 8; nt++) {
            float p00 = ex2f(s[nt][0] - mn0);
            float p01 = ex2f(s[nt][1] - mn0);
            float p10 = ex2f(s[nt][2] - mn1);
            float p11 = ex2f(s[nt][3] - mn1);
            sum0 += p00 + p01;
            sum1 += p10 + p11;
            uint2 w0 = {__float_as_uint(p00), __float_as_uint(p01)};
            uint2 w1 = {__float_as_uint(p10), __float_as_uint(p11)};
            *(uint2*)&Ps[(q0 + g) * 68 + 8 * nt + 2 * tg] = w0;
            *(uint2*)&Ps[(q0 + g + 8) * 68 + 8 * nt + 2 * tg] = w1;
        }
        sum0 += __shfl_xor_sync(0xffffffffu, sum0, 1);
        sum0 += __shfl_xor_sync(0xffffffffu, sum0, 2);
        sum1 += __shfl_xor_sync(0xffffffffu, sum1, 1);
        sum1 += __shfl_xor_sync(0xffffffffu, sum1, 2);
        lrun0 = lrun0 * cr0 + sum0;
        lrun1 = lrun1 * cr1 + sum1;
#pragma unroll
        for (int nt = 0; nt < 8; nt++) {
            o[nt][0] *= cr0; o[nt][1] *= cr0;
            o[nt][2] *= cr1; o[nt][3] *= cr1;
        }
        __syncwarp();

        // O += P V : 16q x 64d (V natural [k][d], stride 72 => conflict-free)
#pragma unroll
        for (int ks = 0; ks < 8; ks++) {
            unsigned int a0 = Ps[(q0 + g) * 68 + 8 * ks + tg];
            unsigned int a1 = Ps[(q0 + g + 8) * 68 + 8 * ks + tg];
            unsigned int a2 = Ps[(q0 + g) * 68 + 8 * ks + tg + 4];
            unsigned int a3 = Ps[(q0 + g + 8) * 68 + 8 * ks + tg + 4];
#pragma unroll
            for (int nt = 0; nt < 8; nt++) {
                unsigned int b0 = Vb[(8 * ks + tg) * 72 + 8 * nt + g];
                unsigned int b1 = Vb[(8 * ks + tg + 4) * 72 + 8 * nt + g];
                mma_tf32(o[nt][0], o[nt][1], o[nt][2], o[nt][3], a0, a1, a2,
                         a3, b0, b1);
            }
        }
    }

    float inv0 = 1.f / lrun0, inv1 = 1.f / lrun1;
    float* ob = g_a + (size_t)(b * 1024 + qt * 64 + q0) * 256 + m * 64;
#pragma unroll
    for (int nt = 0; nt < 8; nt++) {
        float2 v0 = {o[nt][0] * inv0, o[nt][1] * inv0};
        float2 v1 = {o[nt][2] * inv1, o[nt][3] * inv1};
        *(float2*)&ob[g * 256 + 8 * nt + 2 * tg] = v0;
        *(float2*)&ob[(g + 8) * 256 + 8 * nt + 2 * tg] = v1;
    }
}

// ---------------------------------------------------------------------------
// GEMM rows x 256 -> 128 (+bias +extra) with fused LayerNorm.
// Tile 32 rows x 128 cols, 256 threads. Each row lives in one warp.
// mode 0: extra = skip gather [b][col][q], row-major store.
// mode 1: extra = residual row-major, transposed store to out.
// ---------------------------------------------------------------------------
__global__ __launch_bounds__(256) void gemm_ln(
    const float* __restrict__ A, const float* __restrict__ Wm,
    const float* __restrict__ bias, const float* __restrict__ extra,
    const float* __restrict__ lng, const float* __restrict__ lnb, int mode,
    float* __restrict__ out) {
    __shared__ float Xs[32][17];
    __shared__ float Ws[16][132];
    int t = threadIdx.x;
    int r0 = blockIdx.x * 32;
    int cg = t & 31, rg = t >> 5;
    float acc[4][4];
#pragma unroll
    for (int i = 0; i < 4; i++)
#pragma unroll
        for (int j = 0; j < 4; j++) acc[i][j] = 0.f;
    for (int kc = 0; kc < 256; kc += 16) {
        __syncthreads();
        for (int i = t; i < 32 * 16; i += 256) {
            int row = i >> 4, kk = i & 15;
            Xs[row][kk] = A[(size_t)(r0 + row) * 256 + kc + kk];
        }
        for (int i = t; i < 16 * 128; i += 256) {
            int kk = i >> 7, j = i & 127;
            Ws[kk][j] = Wm[(kc + kk) * 128 + j];
        }
        __syncthreads();
#pragma unroll
        for (int kk = 0; kk < 16; kk++) {
            float a_[4];
#pragma unroll
            for (int i2 = 0; i2 < 4; i2++) a_[i2] = Xs[rg * 4 + i2][kk];
            float4 b0 = *(const float4*)&Ws[kk][cg * 4];
            float b_[4] = {b0.x, b0.y, b0.z, b0.w};
#pragma unroll
            for (int i2 = 0; i2 < 4; i2++)
#pragma unroll
                for (int j2 = 0; j2 < 4; j2++) acc[i2][j2] += a_[i2] * b_[j2];
        }
    }
    float4 bb = *(const float4*)&bias[cg * 4];
    float bv[4] = {bb.x, bb.y, bb.z, bb.w};
    float4 gg = *(const float4*)&lng[cg * 4];
    float4 nb = *(const float4*)&lnb[cg * 4];
    float gv[4] = {gg.x, gg.y, gg.z, gg.w};
    float nv[4] = {nb.x, nb.y, nb.z, nb.w};
#pragma unroll
    for (int i2 = 0; i2 < 4; i2++) {
        int row = r0 + rg * 4 + i2;
        int bIdx = row >> 10, q = row & 1023;
        float o[4];
#pragma unroll
        for (int j2 = 0; j2 < 4; j2++) {
            int col = cg * 4 + j2;
            float add;
            if (mode == 0)
                add = extra[bIdx * (128 * 1024) + col * 1024 + q];
            else
                add = extra[(size_t)row * 128 + col];
            o[j2] = acc[i2][j2] + bv[j2] + add;
        }
        float sm = o[0] + o[1] + o[2] + o[3];
        float sq = o[0] * o[0] + o[1] * o[1] + o[2] * o[2] + o[3] * o[3];
#pragma unroll
        for (int off = 16; off >= 1; off >>= 1) {
            sm += __shfl_xor_sync(0xffffffffu, sm, off);
            sq += __shfl_xor_sync(0xffffffffu, sq, off);
        }
        float mu = sm * (1.f / 128.f);
        float var = sq * (1.f / 128.f) - mu * mu;
        float rs = rsqrtf(var + 1e-5f);
        float y[4];
#pragma unroll
        for (int j2 = 0; j2 < 4; j2++)
            y[j2] = (o[j2] - mu) * rs * gv[j2] + nv[j2];
        if (mode == 0) {
            float4 ov = {y[0], y[1], y[2], y[3]};
            *(float4*)&out[(size_t)row * 128 + cg * 4] = ov;
        } else {
#pragma unroll
            for (int j2 = 0; j2 < 4; j2++) {
                int col = cg * 4 + j2;
                out[((size_t)bIdx * 128 + col) * 1024 + q] = y[j2];
            }
        }
    }
}

// ---------------------------------------------------------------------------
// GEMM rows x 128 -> 256 with exact GELU epilogue, 32-row tiles.
// ---------------------------------------------------------------------------
__global__ __launch_bounds__(256) void gemm_128_256_gelu(
    const float* __restrict__ A, const float* __restrict__ Wm,
    const float* __restrict__ bias, float* __restrict__ out) {
    __shared__ float Xs[32][17];
    __shared__ float Ws[16][260];
    int t = threadIdx.x;
    int r0 = blockIdx.x * 32;
    int cg = t & 31, rg = t >> 5;
    float acc[4][8];
#pragma unroll
    for (int i = 0; i < 4; i++)
#pragma unroll
        for (int j = 0; j < 8; j++) acc[i][j] = 0.f;
    for (int kc = 0; kc < 128; kc += 16) {
        __syncthreads();
        for (int i = t; i < 32 * 16; i += 256) {
            int row = i >> 4, kk = i & 15;
            Xs[row][kk] = A[(size_t)(r0 + row) * 128 + kc + kk];
        }
        for (int i = t; i < 16 * 256; i += 256) {
            int kk = i >> 8, j = i & 255;
            Ws[kk][j] = Wm[(kc + kk) * 256 + j];
        }
        __syncthreads();
#pragma unroll
        for (int kk = 0; kk < 16; kk++) {
            float a_[4];
#pragma unroll
            for (int i2 = 0; i2 < 4; i2++) a_[i2] = Xs[rg * 4 + i2][kk];
            float4 b0 = *(const float4*)&Ws[kk][cg * 8];
            float4 b1 = *(const float4*)&Ws[kk][cg * 8 + 4];
            float b_[8] = {b0.x, b0.y, b0.z, b0.w, b1.x, b1.y, b1.z, b1.w};
#pragma unroll
            for (int i2 = 0; i2 < 4; i2++)
#pragma unroll
                for (int j2 = 0; j2 < 8; j2++) acc[i2][j2] += a_[i2] * b_[j2];
        }
    }
    float4 bb0 = *(const float4*)&bias[cg * 8];
    float4 bb1 = *(const float4*)&bias[cg * 8 + 4];
    float bv[8] = {bb0.x, bb0.y, bb0.z, bb0.w, bb1.x, bb1.y, bb1.z, bb1.w};
#pragma unroll
    for (int i2 = 0; i2 < 4; i2++) {
        size_t row = (size_t)(r0 + rg * 4 + i2);
        float o[8];
#pragma unroll
        for (int j2 = 0; j2 < 8; j2++) {
            float h = acc[i2][j2] + bv[j2];
            o[j2] = 0.5f * h * (1.0f + erff(h * 0.70710678118654752f));
        }
        float4 o0 = {o[0], o[1], o[2], o[3]};
        float4 o1 = {o[4], o[5], o[6], o[7]};
        *(float4*)&out[row * 256 + cg * 8] = o0;
        *(float4*)&out[row * 256 + cg * 8 + 4] = o1;
    }
}

// ---------------------------------------------------------------------------
extern "C" void kernel_launch(void* const* d_in, const int* in_sizes, int n_in,
                              void* d_out, int out_size) {
    const float* q = (const float*)d_in[0];
    const float* k = (const float*)d_in[1];
    const float* v = (const float*)d_in[2];
    const float* skip = (const float*)d_in[3];
    const unsigned char* mask = (const unsigned char*)d_in[4];
    const float* lnq_g = (const float*)d_in[5];
    const float* lnq_b = (const float*)d_in[6];
    const float* lnk_g = (const float*)d_in[7];
    const float* lnk_b = (const float*)d_in[8];
    const float* lnv_g = (const float*)d_in[9];
    const float* lnv_b = (const float*)d_in[10];
    const float* Wq = (const float*)d_in[11];
    const float* bq = (const float*)d_in[12];
    const float* Wk = (const float*)d_in[13];
    const float* bk = (const float*)d_in[14];
    const float* Wv = (const float*)d_in[15];
    const float* bv = (const float*)d_in[16];
    const float* Wp = (const float*)d_in[17];
    const float* bp = (const float*)d_in[18];
    const float* pre_g = (const float*)d_in[19];
    const float* pre_b = (const float*)d_in[20];
    const float* W1 = (const float*)d_in[21];
    const float* b1 = (const float*)d_in[22];
    const float* W2 = (const float*)d_in[23];
    const float* b2 = (const float*)d_in[24];
    const float* post_g = (const float*)d_in[25];
    const float* post_b = (const float*)d_in[26];
    float* out = (float*)d_out;

    cudaFuncSetAttribute(attn_kernel,
                         cudaFuncAttributeMaxDynamicSharedMemorySize,
                         ATTN_SMEM_BYTES);

    mask_prep<<<1, 256>>>(mask);

    float* d_qh; cudaGetSymbolAddress((void**)&d_qh, g_qh);
    float* d_kh; cudaGetSymbolAddress((void**)&d_kh, g_kh);
    float* d_vh; cudaGetSymbolAddress((void**)&d_vh, g_vh);
    float* d_a;  cudaGetSymbolAddress((void**)&d_a, g_a);
    float* d_z1; cudaGetSymbolAddress((void**)&d_z1, g_z1);
    float* d_hh; cudaGetSymbolAddress((void**)&d_hh, g_hh);

    proj_ln_mma<1024><<<BB * NN * QQ / 64, 256>>>(q, lnq_g, lnq_b, Wq, bq, d_qh);
    proj_ln_mma<640><<<BB * NN * KImg / 64, 256>>>(k, lnk_g, lnk_b, Wk, bk, d_kh);
    proj_ln_mma<640><<<BB * NN * KImg / 64, 256>>>(v, lnv_g, lnv_b, Wv, bv, d_vh);

    attn_kernel<<<dim3(16, 4, 4), 128, ATTN_SMEM_BYTES>>>();

    // out-proj + skip + pre-LN (fused)
    gemm_ln<<<BB * QQ / 32, 256>>>(d_a, Wp, bp, skip, pre_g, pre_b, 0, d_z1);
    // FFN up + gelu
    gemm_128_256_gelu<<<BB * QQ / 32, 256>>>(d_z1, W1, b1, d_hh);
    // FFN down + residual + post-LN + transposed store (fused)
    gemm_ln<<<BB * QQ / 32, 256>>>(d_hh, W2, b2, d_z1, post_g, post_b, 1, out);
}

// round 12
// speedup vs baseline: 3.5117x; 1.6608x over previous
#include <cuda_runtime.h>
#include <cuda_bf16.h>
#include <math.h>

// Problem constants
constexpr int BB = 4;     // batch
constexpr int NN = 6;     // views
constexpr int DDIM = 128; // model dim
constexpr int QQ = 1024;  // H*W queries
constexpr int KImg = 640; // h*w keys per view
constexpr int MD = 256;   // heads * dim_head

// Scratch (device globals; no allocation allowed)
__device__ __nv_bfloat16 g_qh[BB * NN * QQ * MD];
__device__ __nv_bfloat16 g_kh[BB * NN * KImg * MD];
__device__ __nv_bfloat16 g_vh[BB * NN * KImg * MD];
__device__ float g_a[BB * QQ * MD];
__device__ float g_z1[BB * QQ * DDIM];
__device__ float g_hh[BB * QQ * MD];
__device__ int g_mask[NN * QQ];

// ---------------------------------------------------------------------------
// Helpers
// ---------------------------------------------------------------------------
__device__ __forceinline__ unsigned int f2tf(float x) {
    unsigned int r;
    asm("cvt.rna.tf32.f32 %0, %1;" : "=r"(r) : "f"(x));
    return r;
}

__device__ __forceinline__ float ex2f(float x) {
    float y;
    asm("ex2.approx.f32 %0, %1;" : "=f"(y) : "f"(x));
    return y;
}

__device__ __forceinline__ void mma_tf32(float& c0, float& c1, float& c2,
                                         float& c3, unsigned int a0,
                                         unsigned int a1, unsigned int a2,
                                         unsigned int a3, unsigned int b0,
                                         unsigned int b1) {
    asm volatile(
        "mma.sync.aligned.m16n8k8.row.col.f32.tf32.tf32.f32 "
        "{%0,%1,%2,%3},{%4,%5,%6,%7},{%8,%9},{%0,%1,%2,%3};\n"
        : "+f"(c0), "+f"(c1), "+f"(c2), "+f"(c3)
        : "r"(a0), "r"(a1), "r"(a2), "r"(a3), "r"(b0), "r"(b1));
}

__device__ __forceinline__ void mma_bf16(float* c, unsigned int a0,
                                         unsigned int a1, unsigned int a2,
                                         unsigned int a3, unsigned int b0,
                                         unsigned int b1) {
    asm volatile(
        "mma.sync.aligned.m16n8k16.row.col.f32.bf16.bf16.f32 "
        "{%0,%1,%2,%3},{%4,%5,%6,%7},{%8,%9},{%0,%1,%2,%3};\n"
        : "+f"(c[0]), "+f"(c[1]), "+f"(c[2]), "+f"(c[3])
        : "r"(a0), "r"(a1), "r"(a2), "r"(a3), "r"(b0), "r"(b1));
}

__device__ __forceinline__ void ldsm_x4(unsigned int& r0, unsigned int& r1,
                                        unsigned int& r2, unsigned int& r3,
                                        unsigned int addr) {
    asm volatile(
        "ldmatrix.sync.aligned.m8n8.x4.shared.b16 {%0,%1,%2,%3}, [%4];"
        : "=r"(r0), "=r"(r1), "=r"(r2), "=r"(r3)
        : "r"(addr));
}

__device__ __forceinline__ void ldsm_x4_t(unsigned int& r0, unsigned int& r1,
                                          unsigned int& r2, unsigned int& r3,
                                          unsigned int addr) {
    asm volatile(
        "ldmatrix.sync.aligned.m8n8.x4.trans.shared.b16 {%0,%1,%2,%3}, [%4];"
        : "=r"(r0), "=r"(r1), "=r"(r2), "=r"(r3)
        : "r"(addr));
}

__device__ __forceinline__ void cpa16(unsigned int dst, const void* src) {
    asm volatile("cp.async.cg.shared.global [%0], [%1], 16;" ::"r"(dst),
                 "l"(src));
}
__device__ __forceinline__ void cpa_commit() {
    asm volatile("cp.async.commit_group;");
}
__device__ __forceinline__ void cpa_wait0() {
    asm volatile("cp.async.wait_group 0;");
}

// ---------------------------------------------------------------------------
// Mask prep (detect bool/float32/int32 storage, expand to g_mask[n*QQ+q])
// ---------------------------------------------------------------------------
__global__ void mask_prep(const unsigned char* __restrict__ mraw) {
    __shared__ int flagBool, flagFloat;
    int t = threadIdx.x;
    if (t == 0) { flagBool = 0; flagFloat = 0; }
    __syncthreads();
    int fb = 0, ff = 0;
    for (int i = t; i < NN * QQ; i += 256) {
        unsigned char v = mraw[i];
        if (v) {
            int r = i & 3;
            if (r == 1) fb = 1;
            else if (r >= 2) ff = 1;
        }
    }
    if (fb) atomicOr(&flagBool, 1);
    if (ff) atomicOr(&flagFloat, 1);
    __syncthreads();
    int mode = flagBool ? 0 : (flagFloat ? 1 : 2);
    const float* mf = (const float*)mraw;
    const int* mi = (const int*)mraw;
    for (int i = t; i < NN * QQ; i += 256) {
        int q = i / 6, n = i % 6;
        int val;
        if (mode == 0) val = (mraw[i] != 0);
        else if (mode == 1) val = (mf[i] != 0.0f);
        else val = (mi[i] != 0);
        g_mask[n * QQ + q] = val;
    }
}

// ---------------------------------------------------------------------------
// Fused LayerNorm + projection GEMM via tf32 mma; bf16 output * oscale.
// ---------------------------------------------------------------------------
__device__ __forceinline__ int SWZ(int kk) {
    return ((kk & 3) << 3) | (kk >> 3);
}

template <int S>
__global__ __launch_bounds__(256) void proj_ln_mma(
    const float* __restrict__ x, const float* __restrict__ lg,
    const float* __restrict__ lb, const float* __restrict__ Wm,
    const float* __restrict__ bias, float oscale,
    __nv_bfloat16* __restrict__ out) {
    __shared__ unsigned int Xs[64 * 132];
    __shared__ unsigned int Ws[16 * 256];
    __shared__ float rsum[64][4], rsq[64][4];
    __shared__ float mu_s[64], rs_s[64];
    __shared__ float gs[128], bs[128];
    int t = threadIdx.x;
    int r0 = blockIdx.x * 64;
    int bn = r0 / S;
    int s0 = r0 % S;
    const float* xb = x + (size_t)bn * DDIM * S + s0;
    for (int i = t; i < 64 * 128; i += 256) {
        int sl = i & 63, d = i >> 6;
        Xs[sl * 132 + d] = __float_as_uint(xb[(size_t)d * S + sl]);
    }
    if (t < 128) { gs[t] = lg[t]; bs[t] = lb[t]; }
    __syncthreads();
    {
        int row = t >> 2, part = t & 3;
        float sm = 0.f, sq = 0.f;
#pragma unroll
        for (int j = 0; j < 32; j++) {
            float v = __uint_as_float(Xs[row * 132 + part * 32 + j]);
            sm += v; sq += v * v;
        }
        rsum[row][part] = sm; rsq[row][part] = sq;
    }
    __syncthreads();
    if (t < 64) {
        float sm = rsum[t][0] + rsum[t][1] + rsum[t][2] + rsum[t][3];
        float sq = rsq[t][0] + rsq[t][1] + rsq[t][2] + rsq[t][3];
        float mu = sm * (1.f / 128.f);
        float var = sq * (1.f / 128.f) - mu * mu;
        mu_s[t] = mu;
        rs_s[t] = rsqrtf(var + 1e-5f);
    }
    __syncthreads();
    for (int i = t; i < 64 * 128; i += 256) {
        int d = i & 127, sl = i >> 7;
        float v = __uint_as_float(Xs[sl * 132 + d]);
        Xs[sl * 132 + d] = f2tf((v - mu_s[sl]) * rs_s[sl] * gs[d] + bs[d]);
    }

    int warp = t >> 5, lane = t & 31;
    int g = lane >> 2, tg = lane & 3;
    int n0 = warp * 32;
    float acc[4][4][4];
#pragma unroll
    for (int mt = 0; mt < 4; mt++)
#pragma unroll
        for (int nt = 0; nt < 4; nt++)
#pragma unroll
            for (int c = 0; c < 4; c++) acc[mt][nt][c] = 0.f;

    for (int kc = 0; kc < 128; kc += 16) {
        __syncthreads();
        for (int i = t; i < 16 * 256; i += 256) {
            int kk = i >> 8, col = i & 255;
            Ws[kk * 256 + (col ^ SWZ(kk))] = f2tf(Wm[(size_t)(kc + kk) * 256 + col]);
        }
        __syncthreads();
#pragma unroll
        for (int ks = 0; ks < 2; ks++) {
            int kb_ = 8 * ks;
            unsigned int a[4][4];
#pragma unroll
            for (int mt = 0; mt < 4; mt++) {
                int row = mt * 16 + g;
                a[mt][0] = Xs[row * 132 + kc + kb_ + tg];
                a[mt][1] = Xs[(row + 8) * 132 + kc + kb_ + tg];
                a[mt][2] = Xs[row * 132 + kc + kb_ + tg + 4];
                a[mt][3] = Xs[(row + 8) * 132 + kc + kb_ + tg + 4];
            }
#pragma unroll
            for (int nt = 0; nt < 4; nt++) {
                int col = n0 + nt * 8 + g;
                int kk0 = kb_ + tg, kk1 = kb_ + tg + 4;
                unsigned int b0 = Ws[kk0 * 256 + (col ^ SWZ(kk0))];
                unsigned int b1 = Ws[kk1 * 256 + (col ^ SWZ(kk1))];
#pragma unroll
                for (int mt = 0; mt < 4; mt++)
                    mma_tf32(acc[mt][nt][0], acc[mt][nt][1], acc[mt][nt][2],
                             acc[mt][nt][3], a[mt][0], a[mt][1], a[mt][2],
                             a[mt][3], b0, b1);
            }
        }
    }
#pragma unroll
    for (int mt = 0; mt < 4; mt++)
#pragma unroll
        for (int nt = 0; nt < 4; nt++) {
            int row = r0 + mt * 16 + g;
            int col = n0 + nt * 8 + 2 * tg;
            float bv0 = __ldg(&bias[col]);
            float bv1 = __ldg(&bias[col + 1]);
            __nv_bfloat162 p0 = __floats2bfloat162_rn(
                (acc[mt][nt][0] + bv0) * oscale, (acc[mt][nt][1] + bv1) * oscale);
            __nv_bfloat162 p1 = __floats2bfloat162_rn(
                (acc[mt][nt][2] + bv0) * oscale, (acc[mt][nt][3] + bv1) * oscale);
            *(__nv_bfloat162*)&out[(size_t)row * 256 + col] = p0;
            *(__nv_bfloat162*)&out[(size_t)(row + 8) * 256 + col] = p1;
        }
}

// ---------------------------------------------------------------------------
// Flash attention, bf16 mma m16n8k16, ldmatrix, cp.async double-buffered K/V.
// Block: 64 q-rows, 4 warps. Grid (16 qtiles, 4 heads, 4 batch).
// All tiles 64 rows x 64 bf16 (128B/row), 16B-chunk XOR swizzle (c ^ (row&7)).
// ---------------------------------------------------------------------------
constexpr int TILE_B = 64 * 128; // 8KB per tile
constexpr int ATTN_SMEM_BYTES = 6 * TILE_B; // Q, K0, K1, V0, V1, P

__global__ __launch_bounds__(128) void attn_kernel() {
    extern __shared__ char smem[];
    unsigned int sb = (unsigned int)__cvta_generic_to_shared(smem);
    unsigned int Qb = sb;
    unsigned int Kbase = sb + TILE_B;       // 2 buffers
    unsigned int Vbase = sb + 3 * TILE_B;   // 2 buffers
    unsigned int Pb = sb + 5 * TILE_B;
    char* Pp = smem + 5 * TILE_B;

    int t = threadIdx.x;
    int warp = t >> 5, lane = t & 31;
    int g = lane >> 2, tg = lane & 3;
    int qt = blockIdx.x, m = blockIdx.y, b = blockIdx.z;
    int q0 = warp * 16;

    // ldmatrix per-thread geometry
    int mat = lane >> 3, r8 = lane & 7;
    int arow = q0 + r8 + (mat & 1) * 8;    // A rows (Q and P)
    unsigned int aoff = arow * 128;
    int arm = arow & 7;
    int ac = mat >> 1;                     // A chunk parity
    int brow0 = r8 + ((mat >> 1) << 3);    // B-K row base (add n0)
    int bc = mat & 1;
    int vrow0 = r8 + ((mat & 1) << 3);     // B-V row base (add ks*16)
    int vc = mat >> 1;

    const __nv_bfloat16* kbase = g_kh + (size_t)(b * 6) * 640 * 256 + m * 64;
    const __nv_bfloat16* vbase = g_vh + (size_t)(b * 6) * 640 * 256 + m * 64;

    auto fill64 = [&](const __nv_bfloat16* src, unsigned int dstBase) {
#pragma unroll
        for (int j = 0; j < 4; j++) {
            int i = t + 128 * j;
            int row = i >> 3, c = i & 7;
            cpa16(dstBase + row * 128 + ((c ^ (row & 7)) << 4),
                  src + row * 256 + c * 8);
        }
    };
    auto issue_tile = [&](int it, int buf) {
        fill64(kbase + (size_t)it * 64 * 256, Kbase + buf * TILE_B);
        fill64(vbase + (size_t)it * 64 * 256, Vbase + buf * TILE_B);
        cpa_commit();
    };

    float o[8][4];
#pragma unroll
    for (int nt = 0; nt < 8; nt++)
#pragma unroll
        for (int c = 0; c < 4; c++) o[nt][c] = 0.f;
    float mrun0 = -1e30f, mrun1 = -1e30f, lrun0 = 0.f, lrun1 = 0.f;
    int mk0 = 1, mk1 = 1;

    issue_tile(0, 0);

    for (int it = 0; it < 60; it++) {
        int buf = it & 1;
        if (it % 10 == 0) {
            int n = it / 10;
            __syncthreads(); // all warps done reading old Qs
            const __nv_bfloat16* qbase =
                g_qh + (size_t)((b * 6 + n) * 1024 + qt * 64) * 256 + m * 64;
            fill64(qbase, Qb);
            cpa_commit();
            mk0 = __ldg(&g_mask[n * 1024 + qt * 64 + q0 + g]);
            mk1 = __ldg(&g_mask[n * 1024 + qt * 64 + q0 + g + 8]);
        }
        cpa_wait0();
        __syncthreads();
        if (it + 1 < 60) issue_tile(it + 1, buf ^ 1);

        unsigned int Kb = Kbase + buf * TILE_B;
        unsigned int Vb = Vbase + buf * TILE_B;

        // S = Q K^T : 16q x 64k per warp
        float s[8][4];
#pragma unroll
        for (int nt = 0; nt < 8; nt++)
#pragma unroll
            for (int c = 0; c < 4; c++) s[nt][c] = 0.f;
#pragma unroll
        for (int ks = 0; ks < 4; ks++) {
            unsigned int a0, a1, a2, a3;
            ldsm_x4(a0, a1, a2, a3, Qb + aoff + (((2 * ks + ac) ^ arm) << 4));
#pragma unroll
            for (int nb = 0; nb < 4; nb++) {
                int row = brow0 + nb * 16;
                unsigned int b0, b1, b2, b3;
                ldsm_x4(b0, b1, b2, b3,
                        Kb + row * 128 + (((2 * ks + bc) ^ (row & 7)) << 4));
                mma_bf16(s[2 * nb], a0, a1, a2, a3, b0, b1);
                mma_bf16(s[2 * nb + 1], a0, a1, a2, a3, b2, b3);
            }
        }

        if (!mk0) {
#pragma unroll
            for (int nt = 0; nt < 8; nt++) { s[nt][0] = -1e30f; s[nt][1] = -1e30f; }
        }
        if (!mk1) {
#pragma unroll
            for (int nt = 0; nt < 8; nt++) { s[nt][2] = -1e30f; s[nt][3] = -1e30f; }
        }

        // online softmax (base-2), rows g (c0,c1) and g+8 (c2,c3)
        float rm0 = -1e30f, rm1 = -1e30f;
#pragma unroll
        for (int nt = 0; nt < 8; nt++) {
            rm0 = fmaxf(rm0, fmaxf(s[nt][0], s[nt][1]));
            rm1 = fmaxf(rm1, fmaxf(s[nt][2], s[nt][3]));
        }
        rm0 = fmaxf(rm0, __shfl_xor_sync(0xffffffffu, rm0, 1));
        rm0 = fmaxf(rm0, __shfl_xor_sync(0xffffffffu, rm0, 2));
        rm1 = fmaxf(rm1, __shfl_xor_sync(0xffffffffu, rm1, 1));
        rm1 = fmaxf(rm1, __shfl_xor_sync(0xffffffffu, rm1, 2));
        float mn0 = fmaxf(mrun0, rm0), mn1 = fmaxf(mrun1, rm1);
        float cr0 = ex2f(mrun0 - mn0), cr1 = ex2f(mrun1 - mn1);
        mrun0 = mn0; mrun1 = mn1;
        float sum0 = 0.f, sum1 = 0.f;
        int row0 = q0 + g, row1 = q0 + g + 8;
        char* P0 = Pp + row0 * 128 + tg * 4;
        char* P1 = Pp + row1 * 128 + tg * 4;
        int rm0i = row0 & 7, rm1i = row1 & 7;
#pragma unroll
        for (int nt = 0; nt < 8; nt++) {
            float p00 = ex2f(s[nt][0] - mn0);
            float p01 = ex2f(s[nt][1] - mn0);
            float p10 = ex2f(s[nt][2] - mn1);
            float p11 = ex2f(s[nt][3] - mn1);
            sum0 += p00 + p01;
            sum1 += p10 + p11;
            *(__nv_bfloat162*)(P0 + ((nt ^ rm0i) << 4)) =
                __floats2bfloat162_rn(p00, p01);
            *(__nv_bfloat162*)(P1 + ((nt ^ rm1i) << 4)) =
                __floats2bfloat162_rn(p10, p11);
        }
        sum0 += __shfl_xor_sync(0xffffffffu, sum0, 1);
        sum0 += __shfl_xor_sync(0xffffffffu, sum0, 2);
        sum1 += __shfl_xor_sync(0xffffffffu, sum1, 1);
        sum1 += __shfl_xor_sync(0xffffffffu, sum1, 2);
        lrun0 = lrun0 * cr0 + sum0;
        lrun1 = lrun1 * cr1 + sum1;
#pragma unroll
        for (int nt = 0; nt < 8; nt++) {
            o[nt][0] *= cr0; o[nt][1] *= cr0;
            o[nt][2] *= cr1; o[nt][3] *= cr1;
        }
        __syncwarp();

        // O += P V : 16q x 64d (B = V^T via ldmatrix.trans)
#pragma unroll
        for (int ks = 0; ks < 4; ks++) {
            unsigned int a0, a1, a2, a3;
            ldsm_x4(a0, a1, a2, a3, Pb + aoff + (((2 * ks + ac) ^ arm) << 4));
#pragma unroll
            for (int db = 0; db < 4; db++) {
                int row = vrow0 + ks * 16;
                unsigned int b0, b1, b2, b3;
                ldsm_x4_t(b0, b1, b2, b3,
                          Vb + row * 128 + (((2 * db + vc) ^ (row & 7)) << 4));
                mma_bf16(o[2 * db], a0, a1, a2, a3, b0, b1);
                mma_bf16(o[2 * db + 1], a0, a1, a2, a3, b2, b3);
            }
        }
    }

    float inv0 = 1.f / lrun0, inv1 = 1.f / lrun1;
    float* ob = g_a + (size_t)(b * 1024 + qt * 64 + q0) * 256 + m * 64;
#pragma unroll
    for (int nt = 0; nt < 8; nt++) {
        float2 v0 = {o[nt][0] * inv0, o[nt][1] * inv0};
        float2 v1 = {o[nt][2] * inv1, o[nt][3] * inv1};
        *(float2*)&ob[g * 256 + 8 * nt + 2 * tg] = v0;
        *(float2*)&ob[(g + 8) * 256 + 8 * nt + 2 * tg] = v1;
    }
}

// ---------------------------------------------------------------------------
// GEMM rows x 256 -> 128 (+bias +extra) with fused LayerNorm.
// mode 0: extra = skip gather [b][col][q], row-major store.
// mode 1: extra = residual row-major, transposed store to out.
// ---------------------------------------------------------------------------
__global__ __launch_bounds__(256) void gemm_ln(
    const float* __restrict__ A, const float* __restrict__ Wm,
    const float* __restrict__ bias, const float* __restrict__ extra,
    const float* __restrict__ lng, const float* __restrict__ lnb, int mode,
    float* __restrict__ out) {
    __shared__ float Xs[32][17];
    __shared__ float Ws[16][132];
    int t = threadIdx.x;
    int r0 = blockIdx.x * 32;
    int cg = t & 31, rg = t >> 5;
    float acc[4][4];
#pragma unroll
    for (int i = 0; i < 4; i++)
#pragma unroll
        for (int j = 0; j < 4; j++) acc[i][j] = 0.f;
    for (int kc = 0; kc < 256; kc += 16) {
        __syncthreads();
        for (int i = t; i < 32 * 16; i += 256) {
            int row = i >> 4, kk = i & 15;
            Xs[row][kk] = A[(size_t)(r0 + row) * 256 + kc + kk];
        }
        for (int i = t; i < 16 * 128; i += 256) {
            int kk = i >> 7, j = i & 127;
            Ws[kk][j] = Wm[(kc + kk) * 128 + j];
        }
        __syncthreads();
#pragma unroll
        for (int kk = 0; kk < 16; kk++) {
            float a_[4];
#pragma unroll
            for (int i2 = 0; i2 < 4; i2++) a_[i2] = Xs[rg * 4 + i2][kk];
            float4 b0 = *(const float4*)&Ws[kk][cg * 4];
            float b_[4] = {b0.x, b0.y, b0.z, b0.w};
#pragma unroll
            for (int i2 = 0; i2 < 4; i2++)
#pragma unroll
                for (int j2 = 0; j2 < 4; j2++) acc[i2][j2] += a_[i2] * b_[j2];
        }
    }
    float4 bb = *(const float4*)&bias[cg * 4];
    float bv[4] = {bb.x, bb.y, bb.z, bb.w};
    float4 gg = *(const float4*)&lng[cg * 4];
    float4 nb = *(const float4*)&lnb[cg * 4];
    float gv[4] = {gg.x, gg.y, gg.z, gg.w};
    float nv[4] = {nb.x, nb.y, nb.z, nb.w};
#pragma unroll
    for (int i2 = 0; i2 < 4; i2++) {
        int row = r0 + rg * 4 + i2;
        int bIdx = row >> 10, q = row & 1023;
        float o[4];
#pragma unroll
        for (int j2 = 0; j2 < 4; j2++) {
            int col = cg * 4 + j2;
            float add;
            if (mode == 0)
                add = extra[bIdx * (128 * 1024) + col * 1024 + q];
            else
                add = extra[(size_t)row * 128 + col];
            o[j2] = acc[i2][j2] + bv[j2] + add;
        }
        float sm = o[0] + o[1] + o[2] + o[3];
        float sq = o[0] * o[0] + o[1] * o[1] + o[2] * o[2] + o[3] * o[3];
#pragma unroll
        for (int off = 16; off >= 1; off >>= 1) {
            sm += __shfl_xor_sync(0xffffffffu, sm, off);
            sq += __shfl_xor_sync(0xffffffffu, sq, off);
        }
        float mu = sm * (1.f / 128.f);
        float var = sq * (1.f / 128.f) - mu * mu;
        float rs = rsqrtf(var + 1e-5f);
        float y[4];
#pragma unroll
        for (int j2 = 0; j2 < 4; j2++)
            y[j2] = (o[j2] - mu) * rs * gv[j2] + nv[j2];
        if (mode == 0) {
            float4 ov = {y[0], y[1], y[2], y[3]};
            *(float4*)&out[(size_t)row * 128 + cg * 4] = ov;
        } else {
#pragma unroll
            for (int j2 = 0; j2 < 4; j2++) {
                int col = cg * 4 + j2;
                out[((size_t)bIdx * 128 + col) * 1024 + q] = y[j2];
            }
        }
    }
}

// ---------------------------------------------------------------------------
// GEMM rows x 128 -> 256 with exact GELU epilogue, 32-row tiles.
// ---------------------------------------------------------------------------
__global__ __launch_bounds__(256) void gemm_128_256_gelu(
    const float* __restrict__ A, const float* __restrict__ Wm,
    const float* __restrict__ bias, float* __restrict__ out) {
    __shared__ float Xs[32][17];
    __shared__ float Ws[16][260];
    int t = threadIdx.x;
    int r0 = blockIdx.x * 32;
    int cg = t & 31, rg = t >> 5;
    float acc[4][8];
#pragma unroll
    for (int i = 0; i < 4; i++)
#pragma unroll
        for (int j = 0; j < 8; j++) acc[i][j] = 0.f;
    for (int kc = 0; kc < 128; kc += 16) {
        __syncthreads();
        for (int i = t; i < 32 * 16; i += 256) {
            int row = i >> 4, kk = i & 15;
            Xs[row][kk] = A[(size_t)(r0 + row) * 128 + kc + kk];
        }
        for (int i = t; i < 16 * 256; i += 256) {
            int kk = i >> 8, j = i & 255;
            Ws[kk][j] = Wm[(kc + kk) * 256 + j];
        }
        __syncthreads();
#pragma unroll
        for (int kk = 0; kk < 16; kk++) {
            float a_[4];
#pragma unroll
            for (int i2 = 0; i2 < 4; i2++) a_[i2] = Xs[rg * 4 + i2][kk];
            float4 b0 = *(const float4*)&Ws[kk][cg * 8];
            float4 b1 = *(const float4*)&Ws[kk][cg * 8 + 4];
            float b_[8] = {b0.x, b0.y, b0.z, b0.w, b1.x, b1.y, b1.z, b1.w};
#pragma unroll
            for (int i2 = 0; i2 < 4; i2++)
#pragma unroll
                for (int j2 = 0; j2 < 8; j2++) acc[i2][j2] += a_[i2] * b_[j2];
        }
    }
    float4 bb0 = *(const float4*)&bias[cg * 8];
    float4 bb1 = *(const float4*)&bias[cg * 8 + 4];
    float bv[8] = {bb0.x, bb0.y, bb0.z, bb0.w, bb1.x, bb1.y, bb1.z, bb1.w};
#pragma unroll
    for (int i2 = 0; i2 < 4; i2++) {
        size_t row = (size_t)(r0 + rg * 4 + i2);
        float o[8];
#pragma unroll
        for (int j2 = 0; j2 < 8; j2++) {
            float h = acc[i2][j2] + bv[j2];
            o[j2] = 0.5f * h * (1.0f + erff(h * 0.70710678118654752f));
        }
        float4 o0 = {o[0], o[1], o[2], o[3]};
        float4 o1 = {o[4], o[5], o[6], o[7]};
        *(float4*)&out[row * 256 + cg * 8] = o0;
        *(float4*)&out[row * 256 + cg * 8 + 4] = o1;
    }
}

// ---------------------------------------------------------------------------
extern "C" void kernel_launch(void* const* d_in, const int* in_sizes, int n_in,
                              void* d_out, int out_size) {
    const float* q = (const float*)d_in[0];
    const float* k = (const float*)d_in[1];
    const float* v = (const float*)d_in[2];
    const float* skip = (const float*)d_in[3];
    const unsigned char* mask = (const unsigned char*)d_in[4];
    const float* lnq_g = (const float*)d_in[5];
    const float* lnq_b = (const float*)d_in[6];
    const float* lnk_g = (const float*)d_in[7];
    const float* lnk_b = (const float*)d_in[8];
    const float* lnv_g = (const float*)d_in[9];
    const float* lnv_b = (const float*)d_in[10];
    const float* Wq = (const float*)d_in[11];
    const float* bq = (const float*)d_in[12];
    const float* Wk = (const float*)d_in[13];
    const float* bk = (const float*)d_in[14];
    const float* Wv = (const float*)d_in[15];
    const float* bv = (const float*)d_in[16];
    const float* Wp = (const float*)d_in[17];
    const float* bp = (const float*)d_in[18];
    const float* pre_g = (const float*)d_in[19];
    const float* pre_b = (const float*)d_in[20];
    const float* W1 = (const float*)d_in[21];
    const float* b1 = (const float*)d_in[22];
    const float* W2 = (const float*)d_in[23];
    const float* b2 = (const float*)d_in[24];
    const float* post_g = (const float*)d_in[25];
    const float* post_b = (const float*)d_in[26];
    float* out = (float*)d_out;

    cudaFuncSetAttribute(attn_kernel,
                         cudaFuncAttributeMaxDynamicSharedMemorySize,
                         ATTN_SMEM_BYTES);

    mask_prep<<<1, 256>>>(mask);

    __nv_bfloat16* d_qh; cudaGetSymbolAddress((void**)&d_qh, g_qh);
    __nv_bfloat16* d_kh; cudaGetSymbolAddress((void**)&d_kh, g_kh);
    __nv_bfloat16* d_vh; cudaGetSymbolAddress((void**)&d_vh, g_vh);
    float* d_a;  cudaGetSymbolAddress((void**)&d_a, g_a);
    float* d_z1; cudaGetSymbolAddress((void**)&d_z1, g_z1);
    float* d_hh; cudaGetSymbolAddress((void**)&d_hh, g_hh);

    const float QSC = 0.125f * 1.4426950408889634f; // scale * log2(e)

    proj_ln_mma<1024><<<BB * NN * QQ / 64, 256>>>(q, lnq_g, lnq_b, Wq, bq, QSC, d_qh);
    proj_ln_mma<640><<<BB * NN * KImg / 64, 256>>>(k, lnk_g, lnk_b, Wk, bk, 1.0f, d_kh);
    proj_ln_mma<640><<<BB * NN * KImg / 64, 256>>>(v, lnv_g, lnv_b, Wv, bv, 1.0f, d_vh);

    attn_kernel<<<dim3(16, 4, 4), 128, ATTN_SMEM_BYTES>>>();

    // out-proj + skip + pre-LN (fused)
    gemm_ln<<<BB * QQ / 32, 256>>>(d_a, Wp, bp, skip, pre_g, pre_b, 0, d_z1);
    // FFN up + gelu
    gemm_128_256_gelu<<<BB * QQ / 32, 256>>>(d_z1, W1, b1, d_hh);
    // FFN down + residual + post-LN + transposed store (fused)
    gemm_ln<<<BB * QQ / 32, 256>>>(d_hh, W2, b2, d_z1, post_g, post_b, 1, out);
}

// round 13
// speedup vs baseline: 4.1112x; 1.1707x over previous
#include <cuda_runtime.h>
#include <cuda_bf16.h>
#include <math.h>

// Problem constants
constexpr int BB = 4;     // batch
constexpr int NN = 6;     // views
constexpr int DDIM = 128; // model dim
constexpr int QQ = 1024;  // H*W queries
constexpr int KImg = 640; // h*w keys per view
constexpr int MD = 256;   // heads * dim_head

// Scratch (device globals; no allocation allowed)
__device__ __nv_bfloat16 g_qh[BB * NN * QQ * MD];
__device__ __nv_bfloat16 g_kh[BB * NN * KImg * MD];
__device__ __nv_bfloat16 g_vh[BB * NN * KImg * MD];
__device__ float g_a[BB * QQ * MD];
__device__ float g_z1[BB * QQ * DDIM];
__device__ float g_hh[BB * QQ * MD];
__device__ int g_mask[NN * QQ];

// ---------------------------------------------------------------------------
// Helpers
// ---------------------------------------------------------------------------
__device__ __forceinline__ unsigned int f2tf(float x) {
    unsigned int r;
    asm("cvt.rna.tf32.f32 %0, %1;" : "=r"(r) : "f"(x));
    return r;
}

__device__ __forceinline__ float ex2f(float x) {
    float y;
    asm("ex2.approx.f32 %0, %1;" : "=f"(y) : "f"(x));
    return y;
}

__device__ __forceinline__ void mma_tf32(float& c0, float& c1, float& c2,
                                         float& c3, unsigned int a0,
                                         unsigned int a1, unsigned int a2,
                                         unsigned int a3, unsigned int b0,
                                         unsigned int b1) {
    asm volatile(
        "mma.sync.aligned.m16n8k8.row.col.f32.tf32.tf32.f32 "
        "{%0,%1,%2,%3},{%4,%5,%6,%7},{%8,%9},{%0,%1,%2,%3};\n"
        : "+f"(c0), "+f"(c1), "+f"(c2), "+f"(c3)
        : "r"(a0), "r"(a1), "r"(a2), "r"(a3), "r"(b0), "r"(b1));
}

__device__ __forceinline__ void mma_bf16(float* c, unsigned int a0,
                                         unsigned int a1, unsigned int a2,
                                         unsigned int a3, unsigned int b0,
                                         unsigned int b1) {
    asm volatile(
        "mma.sync.aligned.m16n8k16.row.col.f32.bf16.bf16.f32 "
        "{%0,%1,%2,%3},{%4,%5,%6,%7},{%8,%9},{%0,%1,%2,%3};\n"
        : "+f"(c[0]), "+f"(c[1]), "+f"(c[2]), "+f"(c[3])
        : "r"(a0), "r"(a1), "r"(a2), "r"(a3), "r"(b0), "r"(b1));
}

__device__ __forceinline__ void ldsm_x4(unsigned int& r0, unsigned int& r1,
                                        unsigned int& r2, unsigned int& r3,
                                        unsigned int addr) {
    asm volatile(
        "ldmatrix.sync.aligned.m8n8.x4.shared.b16 {%0,%1,%2,%3}, [%4];"
        : "=r"(r0), "=r"(r1), "=r"(r2), "=r"(r3)
        : "r"(addr));
}

__device__ __forceinline__ void ldsm_x4_t(unsigned int& r0, unsigned int& r1,
                                          unsigned int& r2, unsigned int& r3,
                                          unsigned int addr) {
    asm volatile(
        "ldmatrix.sync.aligned.m8n8.x4.trans.shared.b16 {%0,%1,%2,%3}, [%4];"
        : "=r"(r0), "=r"(r1), "=r"(r2), "=r"(r3)
        : "r"(addr));
}

__device__ __forceinline__ void cpa16(unsigned int dst, const void* src) {
    asm volatile("cp.async.cg.shared.global [%0], [%1], 16;" ::"r"(dst),
                 "l"(src));
}
__device__ __forceinline__ void cpa_commit() {
    asm volatile("cp.async.commit_group;");
}
__device__ __forceinline__ void cpa_wait0() {
    asm volatile("cp.async.wait_group 0;");
}

// ---------------------------------------------------------------------------
// Mask prep (detect bool/float32/int32 storage, expand to g_mask[n*QQ+q])
// ---------------------------------------------------------------------------
__global__ void mask_prep(const unsigned char* __restrict__ mraw) {
    __shared__ int flagBool, flagFloat;
    int t = threadIdx.x;
    if (t == 0) { flagBool = 0; flagFloat = 0; }
    __syncthreads();
    int fb = 0, ff = 0;
    for (int i = t; i < NN * QQ; i += 256) {
        unsigned char v = mraw[i];
        if (v) {
            int r = i & 3;
            if (r == 1) fb = 1;
            else if (r >= 2) ff = 1;
        }
    }
    if (fb) atomicOr(&flagBool, 1);
    if (ff) atomicOr(&flagFloat, 1);
    __syncthreads();
    int mode = flagBool ? 0 : (flagFloat ? 1 : 2);
    const float* mf = (const float*)mraw;
    const int* mi = (const int*)mraw;
    for (int i = t; i < NN * QQ; i += 256) {
        int q = i / 6, n = i % 6;
        int val;
        if (mode == 0) val = (mraw[i] != 0);
        else if (mode == 1) val = (mf[i] != 0.0f);
        else val = (mi[i] != 0);
        g_mask[n * QQ + q] = val;
    }
}

// ---------------------------------------------------------------------------
// Merged LayerNorm + projection (q, k, v in ONE launch) via tf32 mma.
// 864 CTAs: [0,384) q-tiles, [384,624) k-tiles, [624,864) v-tiles.
// W staged by cp.async (raw fp32 bits -> tf32 mma), double-buffered.
// Ws chunk layout: row kk (16 rows), 64 x 16B chunks, chunk swizzle
// c ^ ((kk&3)<<1)  => b-fragment reads hit 32 distinct banks.
// ---------------------------------------------------------------------------
constexpr int PROJ_XS_W = 64 * 132;       // 8448 words
constexpr int PROJ_WS_W = 2 * 16 * 256;   // 8192 words (2 buffers)
constexpr int PROJ_SCR_W = 896;
constexpr int PROJ_SMEM_BYTES = (PROJ_XS_W + PROJ_WS_W + PROJ_SCR_W) * 4;

__global__ __launch_bounds__(256) void proj_all(
    const float* __restrict__ qx, const float* __restrict__ kx,
    const float* __restrict__ vx, const float* __restrict__ lnq_g,
    const float* __restrict__ lnq_b, const float* __restrict__ lnk_g,
    const float* __restrict__ lnk_b, const float* __restrict__ lnv_g,
    const float* __restrict__ lnv_b, const float* __restrict__ Wq,
    const float* __restrict__ bq, const float* __restrict__ Wk,
    const float* __restrict__ bk, const float* __restrict__ Wv,
    const float* __restrict__ bv, __nv_bfloat16* __restrict__ outq,
    __nv_bfloat16* __restrict__ outk, __nv_bfloat16* __restrict__ outv,
    float qsc) {
    extern __shared__ unsigned int smem_u[];
    unsigned int* Xs = smem_u;
    unsigned int* WsA = smem_u + PROJ_XS_W;
    float* fscr = (float*)(smem_u + PROJ_XS_W + PROJ_WS_W);
    float* rsum = fscr;        // [64][4]
    float* rsq = fscr + 256;   // [64][4]
    float* mu_s = fscr + 512;  // [64]
    float* rs_s = fscr + 576;  // [64]
    float* gs = fscr + 640;    // [128]
    float* bs = fscr + 768;    // [128]

    int t = threadIdx.x;
    int bid = blockIdx.x;
    const float *x, *lg, *lb, *Wm, *bias;
    float oscale;
    __nv_bfloat16* out;
    int S, r0;
    if (bid < 384) {
        x = qx; S = 1024; r0 = bid * 64;
        lg = lnq_g; lb = lnq_b; Wm = Wq; bias = bq;
        oscale = qsc; out = outq;
    } else if (bid < 624) {
        x = kx; S = 640; r0 = (bid - 384) * 64;
        lg = lnk_g; lb = lnk_b; Wm = Wk; bias = bk;
        oscale = 1.0f; out = outk;
    } else {
        x = vx; S = 640; r0 = (bid - 624) * 64;
        lg = lnv_g; lb = lnv_b; Wm = Wv; bias = bv;
        oscale = 1.0f; out = outv;
    }
    unsigned int ws_b = (unsigned int)__cvta_generic_to_shared(WsA);

    // cp.async fill of one 16x256 W chunk (raw fp32 bits), chunk-swizzled
    auto fill_W = [&](int kc, int buf) {
#pragma unroll
        for (int j = 0; j < 4; j++) {
            int i = t + 256 * j;
            int kk = i >> 6, c = i & 63;
            cpa16(ws_b + buf * 16384 + kk * 1024 +
                      ((c ^ ((kk & 3) << 1)) << 4),
                  Wm + (size_t)(kc + kk) * 256 + c * 4);
        }
        cpa_commit();
    };

    fill_W(0, 0); // overlap first W chunk with entire LN phase

    int bn = r0 / S;
    int s0 = r0 % S; // tiles never straddle bn (S % 64 == 0)
    const float* xb = x + (size_t)bn * DDIM * S + s0;
    for (int i = t; i < 64 * 128; i += 256) {
        int sl = i & 63, d = i >> 6;
        Xs[sl * 132 + d] = __float_as_uint(xb[(size_t)d * S + sl]);
    }
    if (t < 128) { gs[t] = lg[t]; bs[t] = lb[t]; }
    __syncthreads();
    {
        int row = t >> 2, part = t & 3;
        float sm = 0.f, sq = 0.f;
#pragma unroll
        for (int j = 0; j < 32; j++) {
            float v = __uint_as_float(Xs[row * 132 + part * 32 + j]);
            sm += v; sq += v * v;
        }
        rsum[row * 4 + part] = sm; rsq[row * 4 + part] = sq;
    }
    __syncthreads();
    if (t < 64) {
        float sm = rsum[t * 4] + rsum[t * 4 + 1] + rsum[t * 4 + 2] + rsum[t * 4 + 3];
        float sq = rsq[t * 4] + rsq[t * 4 + 1] + rsq[t * 4 + 2] + rsq[t * 4 + 3];
        float mu = sm * (1.f / 128.f);
        float var = sq * (1.f / 128.f) - mu * mu;
        mu_s[t] = mu;
        rs_s[t] = rsqrtf(var + 1e-5f);
    }
    __syncthreads();
    for (int i = t; i < 64 * 128; i += 256) {
        int d = i & 127, sl = i >> 7;
        float v = __uint_as_float(Xs[sl * 132 + d]);
        Xs[sl * 132 + d] = f2tf((v - mu_s[sl]) * rs_s[sl] * gs[d] + bs[d]);
    }

    int warp = t >> 5, lane = t & 31;
    int g = lane >> 2, tg = lane & 3;
    int n0 = warp * 32;
    float acc[4][4][4];
#pragma unroll
    for (int mt = 0; mt < 4; mt++)
#pragma unroll
        for (int nt = 0; nt < 4; nt++)
#pragma unroll
            for (int c = 0; c < 4; c++) acc[mt][nt][c] = 0.f;

    for (int kcb = 0; kcb < 8; kcb++) {
        cpa_wait0();
        __syncthreads(); // Ws[kcb&1] ready; all readers of Ws[(kcb+1)&1] done
        if (kcb + 1 < 8) fill_W((kcb + 1) * 16, (kcb + 1) & 1);
        unsigned int* Wb = WsA + (kcb & 1) * 4096;
        int kc = kcb * 16;
#pragma unroll
        for (int ks = 0; ks < 2; ks++) {
            int kb_ = 8 * ks;
            unsigned int a[4][4];
#pragma unroll
            for (int mt = 0; mt < 4; mt++) {
                int row = mt * 16 + g;
                a[mt][0] = Xs[row * 132 + kc + kb_ + tg];
                a[mt][1] = Xs[(row + 8) * 132 + kc + kb_ + tg];
                a[mt][2] = Xs[row * 132 + kc + kb_ + tg + 4];
                a[mt][3] = Xs[(row + 8) * 132 + kc + kb_ + tg + 4];
            }
            int kk0 = kb_ + tg, kk1 = kb_ + tg + 4;
            int sh = (tg & 3) << 1; // (kk&3)<<1 for both kk0, kk1
#pragma unroll
            for (int nt = 0; nt < 4; nt++) {
                int col = n0 + nt * 8 + g;
                int idx = (((col >> 2) ^ sh) << 2) | (col & 3);
                unsigned int b0 = Wb[kk0 * 256 + idx];
                unsigned int b1 = Wb[kk1 * 256 + idx];
#pragma unroll
                for (int mt = 0; mt < 4; mt++)
                    mma_tf32(acc[mt][nt][0], acc[mt][nt][1], acc[mt][nt][2],
                             acc[mt][nt][3], a[mt][0], a[mt][1], a[mt][2],
                             a[mt][3], b0, b1);
            }
        }
    }
#pragma unroll
    for (int mt = 0; mt < 4; mt++)
#pragma unroll
        for (int nt = 0; nt < 4; nt++) {
            int row = r0 + mt * 16 + g;
            int col = n0 + nt * 8 + 2 * tg;
            float bv0 = __ldg(&bias[col]);
            float bv1 = __ldg(&bias[col + 1]);
            __nv_bfloat162 p0 = __floats2bfloat162_rn(
                (acc[mt][nt][0] + bv0) * oscale, (acc[mt][nt][1] + bv1) * oscale);
            __nv_bfloat162 p1 = __floats2bfloat162_rn(
                (acc[mt][nt][2] + bv0) * oscale, (acc[mt][nt][3] + bv1) * oscale);
            *(__nv_bfloat162*)&out[(size_t)row * 256 + col] = p0;
            *(__nv_bfloat162*)&out[(size_t)(row + 8) * 256 + col] = p1;
        }
}

// ---------------------------------------------------------------------------
// Flash attention, bf16 mma m16n8k16, ldmatrix, cp.async double-buffered K/V.
// (UNCHANGED from R12 winner: 250.6us, rel_err 3.5e-6)
// ---------------------------------------------------------------------------
constexpr int TILE_B = 64 * 128; // 8KB per tile
constexpr int ATTN_SMEM_BYTES = 6 * TILE_B; // Q, K0, K1, V0, V1, P

__global__ __launch_bounds__(128) void attn_kernel() {
    extern __shared__ char smem[];
    unsigned int sb = (unsigned int)__cvta_generic_to_shared(smem);
    unsigned int Qb = sb;
    unsigned int Kbase = sb + TILE_B;       // 2 buffers
    unsigned int Vbase = sb + 3 * TILE_B;   // 2 buffers
    unsigned int Pb = sb + 5 * TILE_B;
    char* Pp = smem + 5 * TILE_B;

    int t = threadIdx.x;
    int warp = t >> 5, lane = t & 31;
    int g = lane >> 2, tg = lane & 3;
    int qt = blockIdx.x, m = blockIdx.y, b = blockIdx.z;
    int q0 = warp * 16;

    // ldmatrix per-thread geometry
    int mat = lane >> 3, r8 = lane & 7;
    int arow = q0 + r8 + (mat & 1) * 8;    // A rows (Q and P)
    unsigned int aoff = arow * 128;
    int arm = arow & 7;
    int ac = mat >> 1;                     // A chunk parity
    int brow0 = r8 + ((mat >> 1) << 3);    // B-K row base (add n0)
    int bc = mat & 1;
    int vrow0 = r8 + ((mat & 1) << 3);     // B-V row base (add ks*16)
    int vc = mat >> 1;

    const __nv_bfloat16* kbase = g_kh + (size_t)(b * 6) * 640 * 256 + m * 64;
    const __nv_bfloat16* vbase = g_vh + (size_t)(b * 6) * 640 * 256 + m * 64;

    auto fill64 = [&](const __nv_bfloat16* src, unsigned int dstBase) {
#pragma unroll
        for (int j = 0; j < 4; j++) {
            int i = t + 128 * j;
            int row = i >> 3, c = i & 7;
            cpa16(dstBase + row * 128 + ((c ^ (row & 7)) << 4),
                  src + row * 256 + c * 8);
        }
    };
    auto issue_tile = [&](int it, int buf) {
        fill64(kbase + (size_t)it * 64 * 256, Kbase + buf * TILE_B);
        fill64(vbase + (size_t)it * 64 * 256, Vbase + buf * TILE_B);
        cpa_commit();
    };

    float o[8][4];
#pragma unroll
    for (int nt = 0; nt < 8; nt++)
#pragma unroll
        for (int c = 0; c < 4; c++) o[nt][c] = 0.f;
    float mrun0 = -1e30f, mrun1 = -1e30f, lrun0 = 0.f, lrun1 = 0.f;
    int mk0 = 1, mk1 = 1;

    issue_tile(0, 0);

    for (int it = 0; it < 60; it++) {
        int buf = it & 1;
        if (it % 10 == 0) {
            int n = it / 10;
            __syncthreads(); // all warps done reading old Qs
            const __nv_bfloat16* qbase =
                g_qh + (size_t)((b * 6 + n) * 1024 + qt * 64) * 256 + m * 64;
            fill64(qbase, Qb);
            cpa_commit();
            mk0 = __ldg(&g_mask[n * 1024 + qt * 64 + q0 + g]);
            mk1 = __ldg(&g_mask[n * 1024 + qt * 64 + q0 + g + 8]);
        }
        cpa_wait0();
        __syncthreads();
        if (it + 1 < 60) issue_tile(it + 1, buf ^ 1);

        unsigned int Kb = Kbase + buf * TILE_B;
        unsigned int Vb = Vbase + buf * TILE_B;

        // S = Q K^T : 16q x 64k per warp
        float s[8][4];
#pragma unroll
        for (int nt = 0; nt < 8; nt++)
#pragma unroll
            for (int c = 0; c < 4; c++) s[nt][c] = 0.f;
#pragma unroll
        for (int ks = 0; ks < 4; ks++) {
            unsigned int a0, a1, a2, a3;
            ldsm_x4(a0, a1, a2, a3, Qb + aoff + (((2 * ks + ac) ^ arm) << 4));
#pragma unroll
            for (int nb = 0; nb < 4; nb++) {
                int row = brow0 + nb * 16;
                unsigned int b0, b1, b2, b3;
                ldsm_x4(b0, b1, b2, b3,
                        Kb + row * 128 + (((2 * ks + bc) ^ (row & 7)) << 4));
                mma_bf16(s[2 * nb], a0, a1, a2, a3, b0, b1);
                mma_bf16(s[2 * nb + 1], a0, a1, a2, a3, b2, b3);
            }
        }

        if (!mk0) {
#pragma unroll
            for (int nt = 0; nt < 8; nt++) { s[nt][0] = -1e30f; s[nt][1] = -1e30f; }
        }
        if (!mk1) {
#pragma unroll
            for (int nt = 0; nt < 8; nt++) { s[nt][2] = -1e30f; s[nt][3] = -1e30f; }
        }

        // online softmax (base-2), rows g (c0,c1) and g+8 (c2,c3)
        float rm0 = -1e30f, rm1 = -1e30f;
#pragma unroll
        for (int nt = 0; nt < 8; nt++) {
            rm0 = fmaxf(rm0, fmaxf(s[nt][0], s[nt][1]));
            rm1 = fmaxf(rm1, fmaxf(s[nt][2], s[nt][3]));
        }
        rm0 = fmaxf(rm0, __shfl_xor_sync(0xffffffffu, rm0, 1));
        rm0 = fmaxf(rm0, __shfl_xor_sync(0xffffffffu, rm0, 2));
        rm1 = fmaxf(rm1, __shfl_xor_sync(0xffffffffu, rm1, 1));
        rm1 = fmaxf(rm1, __shfl_xor_sync(0xffffffffu, rm1, 2));
        float mn0 = fmaxf(mrun0, rm0), mn1 = fmaxf(mrun1, rm1);
        float cr0 = ex2f(mrun0 - mn0), cr1 = ex2f(mrun1 - mn1);
        mrun0 = mn0; mrun1 = mn1;
        float sum0 = 0.f, sum1 = 0.f;
        int row0 = q0 + g, row1 = q0 + g + 8;
        char* P0 = Pp + row0 * 128 + tg * 4;
        char* P1 = Pp + row1 * 128 + tg * 4;
        int rm0i = row0 & 7, rm1i = row1 & 7;
#pragma unroll
        for (int nt = 0; nt < 8; nt++) {
            float p00 = ex2f(s[nt][0] - mn0);
            float p01 = ex2f(s[nt][1] - mn0);
            float p10 = ex2f(s[nt][2] - mn1);
            float p11 = ex2f(s[nt][3] - mn1);
            sum0 += p00 + p01;
            sum1 += p10 + p11;
            *(__nv_bfloat162*)(P0 + ((nt ^ rm0i) << 4)) =
                __floats2bfloat162_rn(p00, p01);
            *(__nv_bfloat162*)(P1 + ((nt ^ rm1i) << 4)) =
                __floats2bfloat162_rn(p10, p11);
        }
        sum0 += __shfl_xor_sync(0xffffffffu, sum0, 1);
        sum0 += __shfl_xor_sync(0xffffffffu, sum0, 2);
        sum1 += __shfl_xor_sync(0xffffffffu, sum1, 1);
        sum1 += __shfl_xor_sync(0xffffffffu, sum1, 2);
        lrun0 = lrun0 * cr0 + sum0;
        lrun1 = lrun1 * cr1 + sum1;
#pragma unroll
        for (int nt = 0; nt < 8; nt++) {
            o[nt][0] *= cr0; o[nt][1] *= cr0;
            o[nt][2] *= cr1; o[nt][3] *= cr1;
        }
        __syncwarp();

        // O += P V : 16q x 64d (B = V^T via ldmatrix.trans)
#pragma unroll
        for (int ks = 0; ks < 4; ks++) {
            unsigned int a0, a1, a2, a3;
            ldsm_x4(a0, a1, a2, a3, Pb + aoff + (((2 * ks + ac) ^ arm) << 4));
#pragma unroll
            for (int db = 0; db < 4; db++) {
                int row = vrow0 + ks * 16;
                unsigned int b0, b1, b2, b3;
                ldsm_x4_t(b0, b1, b2, b3,
                          Vb + row * 128 + (((2 * db + vc) ^ (row & 7)) << 4));
                mma_bf16(o[2 * db], a0, a1, a2, a3, b0, b1);
                mma_bf16(o[2 * db + 1], a0, a1, a2, a3, b2, b3);
            }
        }
    }

    float inv0 = 1.f / lrun0, inv1 = 1.f / lrun1;
    float* ob = g_a + (size_t)(b * 1024 + qt * 64 + q0) * 256 + m * 64;
#pragma unroll
    for (int nt = 0; nt < 8; nt++) {
        float2 v0 = {o[nt][0] * inv0, o[nt][1] * inv0};
        float2 v1 = {o[nt][2] * inv1, o[nt][3] * inv1};
        *(float2*)&ob[g * 256 + 8 * nt + 2 * tg] = v0;
        *(float2*)&ob[(g + 8) * 256 + 8 * nt + 2 * tg] = v1;
    }
}

// ---------------------------------------------------------------------------
// GEMM rows x 256 -> 128 (+bias +extra) with fused LayerNorm. (unchanged)
// ---------------------------------------------------------------------------
__global__ __launch_bounds__(256) void gemm_ln(
    const float* __restrict__ A, const float* __restrict__ Wm,
    const float* __restrict__ bias, const float* __restrict__ extra,
    const float* __restrict__ lng, const float* __restrict__ lnb, int mode,
    float* __restrict__ out) {
    __shared__ float Xs[32][17];
    __shared__ float Ws[16][132];
    int t = threadIdx.x;
    int r0 = blockIdx.x * 32;
    int cg = t & 31, rg = t >> 5;
    float acc[4][4];
#pragma unroll
    for (int i = 0; i < 4; i++)
#pragma unroll
        for (int j = 0; j < 4; j++) acc[i][j] = 0.f;
    for (int kc = 0; kc < 256; kc += 16) {
        __syncthreads();
        for (int i = t; i < 32 * 16; i += 256) {
            int row = i >> 4, kk = i & 15;
            Xs[row][kk] = A[(size_t)(r0 + row) * 256 + kc + kk];
        }
        for (int i = t; i < 16 * 128; i += 256) {
            int kk = i >> 7, j = i & 127;
            Ws[kk][j] = Wm[(kc + kk) * 128 + j];
        }
        __syncthreads();
#pragma unroll
        for (int kk = 0; kk < 16; kk++) {
            float a_[4];
#pragma unroll
            for (int i2 = 0; i2 < 4; i2++) a_[i2] = Xs[rg * 4 + i2][kk];
            float4 b0 = *(const float4*)&Ws[kk][cg * 4];
            float b_[4] = {b0.x, b0.y, b0.z, b0.w};
#pragma unroll
            for (int i2 = 0; i2 < 4; i2++)
#pragma unroll
                for (int j2 = 0; j2 < 4; j2++) acc[i2][j2] += a_[i2] * b_[j2];
        }
    }
    float4 bb = *(const float4*)&bias[cg * 4];
    float bv[4] = {bb.x, bb.y, bb.z, bb.w};
    float4 gg = *(const float4*)&lng[cg * 4];
    float4 nb = *(const float4*)&lnb[cg * 4];
    float gv[4] = {gg.x, gg.y, gg.z, gg.w};
    float nv[4] = {nb.x, nb.y, nb.z, nb.w};
#pragma unroll
    for (int i2 = 0; i2 < 4; i2++) {
        int row = r0 + rg * 4 + i2;
        int bIdx = row >> 10, q = row & 1023;
        float o[4];
#pragma unroll
        for (int j2 = 0; j2 < 4; j2++) {
            int col = cg * 4 + j2;
            float add;
            if (mode == 0)
                add = extra[bIdx * (128 * 1024) + col * 1024 + q];
            else
                add = extra[(size_t)row * 128 + col];
            o[j2] = acc[i2][j2] + bv[j2] + add;
        }
        float sm = o[0] + o[1] + o[2] + o[3];
        float sq = o[0] * o[0] + o[1] * o[1] + o[2] * o[2] + o[3] * o[3];
#pragma unroll
        for (int off = 16; off >= 1; off >>= 1) {
            sm += __shfl_xor_sync(0xffffffffu, sm, off);
            sq += __shfl_xor_sync(0xffffffffu, sq, off);
        }
        float mu = sm * (1.f / 128.f);
        float var = sq * (1.f / 128.f) - mu * mu;
        float rs = rsqrtf(var + 1e-5f);
        float y[4];
#pragma unroll
        for (int j2 = 0; j2 < 4; j2++)
            y[j2] = (o[j2] - mu) * rs * gv[j2] + nv[j2];
        if (mode == 0) {
            float4 ov = {y[0], y[1], y[2], y[3]};
            *(float4*)&out[(size_t)row * 128 + cg * 4] = ov;
        } else {
#pragma unroll
            for (int j2 = 0; j2 < 4; j2++) {
                int col = cg * 4 + j2;
                out[((size_t)bIdx * 128 + col) * 1024 + q] = y[j2];
            }
        }
    }
}

// ---------------------------------------------------------------------------
// GEMM rows x 128 -> 256 with exact GELU epilogue, 32-row tiles. (unchanged)
// ---------------------------------------------------------------------------
__global__ __launch_bounds__(256) void gemm_128_256_gelu(
    const float* __restrict__ A, const float* __restrict__ Wm,
    const float* __restrict__ bias, float* __restrict__ out) {
    __shared__ float Xs[32][17];
    __shared__ float Ws[16][260];
    int t = threadIdx.x;
    int r0 = blockIdx.x * 32;
    int cg = t & 31, rg = t >> 5;
    float acc[4][8];
#pragma unroll
    for (int i = 0; i < 4; i++)
#pragma unroll
        for (int j = 0; j < 8; j++) acc[i][j] = 0.f;
    for (int kc = 0; kc < 128; kc += 16) {
        __syncthreads();
        for (int i = t; i < 32 * 16; i += 256) {
            int row = i >> 4, kk = i & 15;
            Xs[row][kk] = A[(size_t)(r0 + row) * 128 + kc + kk];
        }
        for (int i = t; i < 16 * 256; i += 256) {
            int kk = i >> 8, j = i & 255;
            Ws[kk][j] = Wm[(kc + kk) * 256 + j];
        }
        __syncthreads();
#pragma unroll
        for (int kk = 0; kk < 16; kk++) {
            float a_[4];
#pragma unroll
            for (int i2 = 0; i2 < 4; i2++) a_[i2] = Xs[rg * 4 + i2][kk];
            float4 b0 = *(const float4*)&Ws[kk][cg * 8];
            float4 b1 = *(const float4*)&Ws[kk][cg * 8 + 4];
            float b_[8] = {b0.x, b0.y, b0.z, b0.w, b1.x, b1.y, b1.z, b1.w};
#pragma unroll
            for (int i2 = 0; i2 < 4; i2++)
#pragma unroll
                for (int j2 = 0; j2 < 8; j2++) acc[i2][j2] += a_[i2] * b_[j2];
        }
    }
    float4 bb0 = *(const float4*)&bias[cg * 8];
    float4 bb1 = *(const float4*)&bias[cg * 8 + 4];
    float bv[8] = {bb0.x, bb0.y, bb0.z, bb0.w, bb1.x, bb1.y, bb1.z, bb1.w};
#pragma unroll
    for (int i2 = 0; i2 < 4; i2++) {
        size_t row = (size_t)(r0 + rg * 4 + i2);
        float o[8];
#pragma unroll
        for (int j2 = 0; j2 < 8; j2++) {
            float h = acc[i2][j2] + bv[j2];
            o[j2] = 0.5f * h * (1.0f + erff(h * 0.70710678118654752f));
        }
        float4 o0 = {o[0], o[1], o[2], o[3]};
        float4 o1 = {o[4], o[5], o[6], o[7]};
        *(float4*)&out[row * 256 + cg * 8] = o0;
        *(float4*)&out[row * 256 + cg * 8 + 4] = o1;
    }
}

// ---------------------------------------------------------------------------
extern "C" void kernel_launch(void* const* d_in, const int* in_sizes, int n_in,
                              void* d_out, int out_size) {
    const float* q = (const float*)d_in[0];
    const float* k = (const float*)d_in[1];
    const float* v = (const float*)d_in[2];
    const float* skip = (const float*)d_in[3];
    const unsigned char* mask = (const unsigned char*)d_in[4];
    const float* lnq_g = (const float*)d_in[5];
    const float* lnq_b = (const float*)d_in[6];
    const float* lnk_g = (const float*)d_in[7];
    const float* lnk_b = (const float*)d_in[8];
    const float* lnv_g = (const float*)d_in[9];
    const float* lnv_b = (const float*)d_in[10];
    const float* Wq = (const float*)d_in[11];
    const float* bq = (const float*)d_in[12];
    const float* Wk = (const float*)d_in[13];
    const float* bk = (const float*)d_in[14];
    const float* Wv = (const float*)d_in[15];
    const float* bv = (const float*)d_in[16];
    const float* Wp = (const float*)d_in[17];
    const float* bp = (const float*)d_in[18];
    const float* pre_g = (const float*)d_in[19];
    const float* pre_b = (const float*)d_in[20];
    const float* W1 = (const float*)d_in[21];
    const float* b1 = (const float*)d_in[22];
    const float* W2 = (const float*)d_in[23];
    const float* b2 = (const float*)d_in[24];
    const float* post_g = (const float*)d_in[25];
    const float* post_b = (const float*)d_in[26];
    float* out = (float*)d_out;

    cudaFuncSetAttribute(attn_kernel,
                         cudaFuncAttributeMaxDynamicSharedMemorySize,
                         ATTN_SMEM_BYTES);
    cudaFuncSetAttribute(proj_all,
                         cudaFuncAttributeMaxDynamicSharedMemorySize,
                         PROJ_SMEM_BYTES);

    mask_prep<<<1, 256>>>(mask);

    __nv_bfloat16* d_qh; cudaGetSymbolAddress((void**)&d_qh, g_qh);
    __nv_bfloat16* d_kh; cudaGetSymbolAddress((void**)&d_kh, g_kh);
    __nv_bfloat16* d_vh; cudaGetSymbolAddress((void**)&d_vh, g_vh);
    float* d_a;  cudaGetSymbolAddress((void**)&d_a, g_a);
    float* d_z1; cudaGetSymbolAddress((void**)&d_z1, g_z1);
    float* d_hh; cudaGetSymbolAddress((void**)&d_hh, g_hh);

    const float QSC = 0.125f * 1.4426950408889634f; // scale * log2(e)

    proj_all<<<864, 256, PROJ_SMEM_BYTES>>>(
        q, k, v, lnq_g, lnq_b, lnk_g, lnk_b, lnv_g, lnv_b, Wq, bq, Wk, bk,
        Wv, bv, d_qh, d_kh, d_vh, QSC);

    attn_kernel<<<dim3(16, 4, 4), 128, ATTN_SMEM_BYTES>>>();

    // out-proj + skip + pre-LN (fused)
    gemm_ln<<<BB * QQ / 32, 256>>>(d_a, Wp, bp, skip, pre_g, pre_b, 0, d_z1);
    // FFN up + gelu
    gemm_128_256_gelu<<<BB * QQ / 32, 256>>>(d_z1, W1, b1, d_hh);
    // FFN down + residual + post-LN + transposed store (fused)
    gemm_ln<<<BB * QQ / 32, 256>>>(d_hh, W2, b2, d_z1, post_g, post_b, 1, out);
}

// round 14
// speedup vs baseline: 5.8581x; 1.4249x over previous
#include <cuda_runtime.h>
#include <cuda_bf16.h>
#include <math.h>

// Problem constants
constexpr int BB = 4;     // batch
constexpr int NN = 6;     // views
constexpr int DDIM = 128; // model dim
constexpr int QQ = 1024;  // H*W queries
constexpr int KImg = 640; // h*w keys per view
constexpr int MD = 256;   // heads * dim_head

// Scratch (device globals; no allocation allowed)
__device__ __nv_bfloat16 g_qh[BB * NN * QQ * MD];
__device__ __nv_bfloat16 g_kh[BB * NN * KImg * MD];
__device__ __nv_bfloat16 g_vh[BB * NN * KImg * MD];
__device__ float g_a[BB * QQ * MD];
__device__ int g_mask[NN * QQ];

// ---------------------------------------------------------------------------
// Helpers
// ---------------------------------------------------------------------------
__device__ __forceinline__ unsigned int f2tf(float x) {
    unsigned int r;
    asm("cvt.rna.tf32.f32 %0, %1;" : "=r"(r) : "f"(x));
    return r;
}

__device__ __forceinline__ float ex2f(float x) {
    float y;
    asm("ex2.approx.f32 %0, %1;" : "=f"(y) : "f"(x));
    return y;
}

__device__ __forceinline__ void mma_tf32(float& c0, float& c1, float& c2,
                                         float& c3, unsigned int a0,
                                         unsigned int a1, unsigned int a2,
                                         unsigned int a3, unsigned int b0,
                                         unsigned int b1) {
    asm volatile(
        "mma.sync.aligned.m16n8k8.row.col.f32.tf32.tf32.f32 "
        "{%0,%1,%2,%3},{%4,%5,%6,%7},{%8,%9},{%0,%1,%2,%3};\n"
        : "+f"(c0), "+f"(c1), "+f"(c2), "+f"(c3)
        : "r"(a0), "r"(a1), "r"(a2), "r"(a3), "r"(b0), "r"(b1));
}

__device__ __forceinline__ void mma_bf16(float* c, unsigned int a0,
                                         unsigned int a1, unsigned int a2,
                                         unsigned int a3, unsigned int b0,
                                         unsigned int b1) {
    asm volatile(
        "mma.sync.aligned.m16n8k16.row.col.f32.bf16.bf16.f32 "
        "{%0,%1,%2,%3},{%4,%5,%6,%7},{%8,%9},{%0,%1,%2,%3};\n"
        : "+f"(c[0]), "+f"(c[1]), "+f"(c[2]), "+f"(c[3])
        : "r"(a0), "r"(a1), "r"(a2), "r"(a3), "r"(b0), "r"(b1));
}

__device__ __forceinline__ void ldsm_x4(unsigned int& r0, unsigned int& r1,
                                        unsigned int& r2, unsigned int& r3,
                                        unsigned int addr) {
    asm volatile(
        "ldmatrix.sync.aligned.m8n8.x4.shared.b16 {%0,%1,%2,%3}, [%4];"
        : "=r"(r0), "=r"(r1), "=r"(r2), "=r"(r3)
        : "r"(addr));
}

__device__ __forceinline__ void ldsm_x4_t(unsigned int& r0, unsigned int& r1,
                                          unsigned int& r2, unsigned int& r3,
                                          unsigned int addr) {
    asm volatile(
        "ldmatrix.sync.aligned.m8n8.x4.trans.shared.b16 {%0,%1,%2,%3}, [%4];"
        : "=r"(r0), "=r"(r1), "=r"(r2), "=r"(r3)
        : "r"(addr));
}

__device__ __forceinline__ void cpa16(unsigned int dst, const void* src) {
    asm volatile("cp.async.cg.shared.global [%0], [%1], 16;" ::"r"(dst),
                 "l"(src));
}
__device__ __forceinline__ void cpa_commit() {
    asm volatile("cp.async.commit_group;");
}
__device__ __forceinline__ void cpa_wait0() {
    asm volatile("cp.async.wait_group 0;");
}

// ---------------------------------------------------------------------------
// Mask prep (detect bool/float32/int32 storage, expand to g_mask[n*QQ+q])
// ---------------------------------------------------------------------------
__global__ void mask_prep(const unsigned char* __restrict__ mraw) {
    __shared__ int flagBool, flagFloat;
    int t = threadIdx.x;
    if (t == 0) { flagBool = 0; flagFloat = 0; }
    __syncthreads();
    int fb = 0, ff = 0;
    for (int i = t; i < NN * QQ; i += 256) {
        unsigned char v = mraw[i];
        if (v) {
            int r = i & 3;
            if (r == 1) fb = 1;
            else if (r >= 2) ff = 1;
        }
    }
    if (fb) atomicOr(&flagBool, 1);
    if (ff) atomicOr(&flagFloat, 1);
    __syncthreads();
    int mode = flagBool ? 0 : (flagFloat ? 1 : 2);
    const float* mf = (const float*)mraw;
    const int* mi = (const int*)mraw;
    for (int i = t; i < NN * QQ; i += 256) {
        int q = i / 6, n = i % 6;
        int val;
        if (mode == 0) val = (mraw[i] != 0);
        else if (mode == 1) val = (mf[i] != 0.0f);
        else val = (mi[i] != 0);
        g_mask[n * QQ + q] = val;
    }
}

// ---------------------------------------------------------------------------
// Merged LayerNorm + projection (q, k, v in ONE launch) via tf32 mma.
// (UNCHANGED from R13 winner)
// ---------------------------------------------------------------------------
constexpr int PROJ_XS_W = 64 * 132;
constexpr int PROJ_WS_W = 2 * 16 * 256;
constexpr int PROJ_SCR_W = 896;
constexpr int PROJ_SMEM_BYTES = (PROJ_XS_W + PROJ_WS_W + PROJ_SCR_W) * 4;

__global__ __launch_bounds__(256) void proj_all(
    const float* __restrict__ qx, const float* __restrict__ kx,
    const float* __restrict__ vx, const float* __restrict__ lnq_g,
    const float* __restrict__ lnq_b, const float* __restrict__ lnk_g,
    const float* __restrict__ lnk_b, const float* __restrict__ lnv_g,
    const float* __restrict__ lnv_b, const float* __restrict__ Wq,
    const float* __restrict__ bq, const float* __restrict__ Wk,
    const float* __restrict__ bk, const float* __restrict__ Wv,
    const float* __restrict__ bv, __nv_bfloat16* __restrict__ outq,
    __nv_bfloat16* __restrict__ outk, __nv_bfloat16* __restrict__ outv,
    float qsc) {
    extern __shared__ unsigned int smem_u[];
    unsigned int* Xs = smem_u;
    unsigned int* WsA = smem_u + PROJ_XS_W;
    float* fscr = (float*)(smem_u + PROJ_XS_W + PROJ_WS_W);
    float* rsum = fscr;
    float* rsq = fscr + 256;
    float* mu_s = fscr + 512;
    float* rs_s = fscr + 576;
    float* gs = fscr + 640;
    float* bs = fscr + 768;

    int t = threadIdx.x;
    int bid = blockIdx.x;
    const float *x, *lg, *lb, *Wm, *bias;
    float oscale;
    __nv_bfloat16* out;
    int S, r0;
    if (bid < 384) {
        x = qx; S = 1024; r0 = bid * 64;
        lg = lnq_g; lb = lnq_b; Wm = Wq; bias = bq;
        oscale = qsc; out = outq;
    } else if (bid < 624) {
        x = kx; S = 640; r0 = (bid - 384) * 64;
        lg = lnk_g; lb = lnk_b; Wm = Wk; bias = bk;
        oscale = 1.0f; out = outk;
    } else {
        x = vx; S = 640; r0 = (bid - 624) * 64;
        lg = lnv_g; lb = lnv_b; Wm = Wv; bias = bv;
        oscale = 1.0f; out = outv;
    }
    unsigned int ws_b = (unsigned int)__cvta_generic_to_shared(WsA);

    auto fill_W = [&](int kc, int buf) {
#pragma unroll
        for (int j = 0; j < 4; j++) {
            int i = t + 256 * j;
            int kk = i >> 6, c = i & 63;
            cpa16(ws_b + buf * 16384 + kk * 1024 +
                      ((c ^ ((kk & 3) << 1)) << 4),
                  Wm + (size_t)(kc + kk) * 256 + c * 4);
        }
        cpa_commit();
    };

    fill_W(0, 0);

    int bn = r0 / S;
    int s0 = r0 % S;
    const float* xb = x + (size_t)bn * DDIM * S + s0;
    for (int i = t; i < 64 * 128; i += 256) {
        int sl = i & 63, d = i >> 6;
        Xs[sl * 132 + d] = __float_as_uint(xb[(size_t)d * S + sl]);
    }
    if (t < 128) { gs[t] = lg[t]; bs[t] = lb[t]; }
    __syncthreads();
    {
        int row = t >> 2, part = t & 3;
        float sm = 0.f, sq = 0.f;
#pragma unroll
        for (int j = 0; j < 32; j++) {
            float v = __uint_as_float(Xs[row * 132 + part * 32 + j]);
            sm += v; sq += v * v;
        }
        rsum[row * 4 + part] = sm; rsq[row * 4 + part] = sq;
    }
    __syncthreads();
    if (t < 64) {
        float sm = rsum[t * 4] + rsum[t * 4 + 1] + rsum[t * 4 + 2] + rsum[t * 4 + 3];
        float sq = rsq[t * 4] + rsq[t * 4 + 1] + rsq[t * 4 + 2] + rsq[t * 4 + 3];
        float mu = sm * (1.f / 128.f);
        float var = sq * (1.f / 128.f) - mu * mu;
        mu_s[t] = mu;
        rs_s[t] = rsqrtf(var + 1e-5f);
    }
    __syncthreads();
    for (int i = t; i < 64 * 128; i += 256) {
        int d = i & 127, sl = i >> 7;
        float v = __uint_as_float(Xs[sl * 132 + d]);
        Xs[sl * 132 + d] = f2tf((v - mu_s[sl]) * rs_s[sl] * gs[d] + bs[d]);
    }

    int warp = t >> 5, lane = t & 31;
    int g = lane >> 2, tg = lane & 3;
    int n0 = warp * 32;
    float acc[4][4][4];
#pragma unroll
    for (int mt = 0; mt < 4; mt++)
#pragma unroll
        for (int nt = 0; nt < 4; nt++)
#pragma unroll
            for (int c = 0; c < 4; c++) acc[mt][nt][c] = 0.f;

    for (int kcb = 0; kcb < 8; kcb++) {
        cpa_wait0();
        __syncthreads();
        if (kcb + 1 < 8) fill_W((kcb + 1) * 16, (kcb + 1) & 1);
        unsigned int* Wb = WsA + (kcb & 1) * 4096;
        int kc = kcb * 16;
#pragma unroll
        for (int ks = 0; ks < 2; ks++) {
            int kb_ = 8 * ks;
            unsigned int a[4][4];
#pragma unroll
            for (int mt = 0; mt < 4; mt++) {
                int row = mt * 16 + g;
                a[mt][0] = Xs[row * 132 + kc + kb_ + tg];
                a[mt][1] = Xs[(row + 8) * 132 + kc + kb_ + tg];
                a[mt][2] = Xs[row * 132 + kc + kb_ + tg + 4];
                a[mt][3] = Xs[(row + 8) * 132 + kc + kb_ + tg + 4];
            }
            int kk0 = kb_ + tg, kk1 = kb_ + tg + 4;
            int sh = (tg & 3) << 1;
#pragma unroll
            for (int nt = 0; nt < 4; nt++) {
                int col = n0 + nt * 8 + g;
                int idx = (((col >> 2) ^ sh) << 2) | (col & 3);
                unsigned int b0 = Wb[kk0 * 256 + idx];
                unsigned int b1 = Wb[kk1 * 256 + idx];
#pragma unroll
                for (int mt = 0; mt < 4; mt++)
                    mma_tf32(acc[mt][nt][0], acc[mt][nt][1], acc[mt][nt][2],
                             acc[mt][nt][3], a[mt][0], a[mt][1], a[mt][2],
                             a[mt][3], b0, b1);
            }
        }
    }
#pragma unroll
    for (int mt = 0; mt < 4; mt++)
#pragma unroll
        for (int nt = 0; nt < 4; nt++) {
            int row = r0 + mt * 16 + g;
            int col = n0 + nt * 8 + 2 * tg;
            float bv0 = __ldg(&bias[col]);
            float bv1 = __ldg(&bias[col + 1]);
            __nv_bfloat162 p0 = __floats2bfloat162_rn(
                (acc[mt][nt][0] + bv0) * oscale, (acc[mt][nt][1] + bv1) * oscale);
            __nv_bfloat162 p1 = __floats2bfloat162_rn(
                (acc[mt][nt][2] + bv0) * oscale, (acc[mt][nt][3] + bv1) * oscale);
            *(__nv_bfloat162*)&out[(size_t)row * 256 + col] = p0;
            *(__nv_bfloat162*)&out[(size_t)(row + 8) * 256 + col] = p1;
        }
}

// ---------------------------------------------------------------------------
// Flash attention (UNCHANGED from R12 winner)
// ---------------------------------------------------------------------------
constexpr int TILE_B = 64 * 128;
constexpr int ATTN_SMEM_BYTES = 6 * TILE_B;

__global__ __launch_bounds__(128) void attn_kernel() {
    extern __shared__ char smem[];
    unsigned int sb = (unsigned int)__cvta_generic_to_shared(smem);
    unsigned int Qb = sb;
    unsigned int Kbase = sb + TILE_B;
    unsigned int Vbase = sb + 3 * TILE_B;
    unsigned int Pb = sb + 5 * TILE_B;
    char* Pp = smem + 5 * TILE_B;

    int t = threadIdx.x;
    int warp = t >> 5, lane = t & 31;
    int g = lane >> 2, tg = lane & 3;
    int qt = blockIdx.x, m = blockIdx.y, b = blockIdx.z;
    int q0 = warp * 16;

    int mat = lane >> 3, r8 = lane & 7;
    int arow = q0 + r8 + (mat & 1) * 8;
    unsigned int aoff = arow * 128;
    int arm = arow & 7;
    int ac = mat >> 1;
    int brow0 = r8 + ((mat >> 1) << 3);
    int bc = mat & 1;
    int vrow0 = r8 + ((mat & 1) << 3);
    int vc = mat >> 1;

    const __nv_bfloat16* kbase = g_kh + (size_t)(b * 6) * 640 * 256 + m * 64;
    const __nv_bfloat16* vbase = g_vh + (size_t)(b * 6) * 640 * 256 + m * 64;

    auto fill64 = [&](const __nv_bfloat16* src, unsigned int dstBase) {
#pragma unroll
        for (int j = 0; j < 4; j++) {
            int i = t + 128 * j;
            int row = i >> 3, c = i & 7;
            cpa16(dstBase + row * 128 + ((c ^ (row & 7)) << 4),
                  src + row * 256 + c * 8);
        }
    };
    auto issue_tile = [&](int it, int buf) {
        fill64(kbase + (size_t)it * 64 * 256, Kbase + buf * TILE_B);
        fill64(vbase + (size_t)it * 64 * 256, Vbase + buf * TILE_B);
        cpa_commit();
    };

    float o[8][4];
#pragma unroll
    for (int nt = 0; nt < 8; nt++)
#pragma unroll
        for (int c = 0; c < 4; c++) o[nt][c] = 0.f;
    float mrun0 = -1e30f, mrun1 = -1e30f, lrun0 = 0.f, lrun1 = 0.f;
    int mk0 = 1, mk1 = 1;

    issue_tile(0, 0);

    for (int it = 0; it < 60; it++) {
        int buf = it & 1;
        if (it % 10 == 0) {
            int n = it / 10;
            __syncthreads();
            const __nv_bfloat16* qbase =
                g_qh + (size_t)((b * 6 + n) * 1024 + qt * 64) * 256 + m * 64;
            fill64(qbase, Qb);
            cpa_commit();
            mk0 = __ldg(&g_mask[n * 1024 + qt * 64 + q0 + g]);
            mk1 = __ldg(&g_mask[n * 1024 + qt * 64 + q0 + g + 8]);
        }
        cpa_wait0();
        __syncthreads();
        if (it + 1 < 60) issue_tile(it + 1, buf ^ 1);

        unsigned int Kb = Kbase + buf * TILE_B;
        unsigned int Vb = Vbase + buf * TILE_B;

        float s[8][4];
#pragma unroll
        for (int nt = 0; nt < 8; nt++)
#pragma unroll
            for (int c = 0; c < 4; c++) s[nt][c] = 0.f;
#pragma unroll
        for (int ks = 0; ks < 4; ks++) {
            unsigned int a0, a1, a2, a3;
            ldsm_x4(a0, a1, a2, a3, Qb + aoff + (((2 * ks + ac) ^ arm) << 4));
#pragma unroll
            for (int nb = 0; nb < 4; nb++) {
                int row = brow0 + nb * 16;
                unsigned int b0, b1, b2, b3;
                ldsm_x4(b0, b1, b2, b3,
                        Kb + row * 128 + (((2 * ks + bc) ^ (row & 7)) << 4));
                mma_bf16(s[2 * nb], a0, a1, a2, a3, b0, b1);
                mma_bf16(s[2 * nb + 1], a0, a1, a2, a3, b2, b3);
            }
        }

        if (!mk0) {
#pragma unroll
            for (int nt = 0; nt < 8; nt++) { s[nt][0] = -1e30f; s[nt][1] = -1e30f; }
        }
        if (!mk1) {
#pragma unroll
            for (int nt = 0; nt < 8; nt++) { s[nt][2] = -1e30f; s[nt][3] = -1e30f; }
        }

        float rm0 = -1e30f, rm1 = -1e30f;
#pragma unroll
        for (int nt = 0; nt < 8; nt++) {
            rm0 = fmaxf(rm0, fmaxf(s[nt][0], s[nt][1]));
            rm1 = fmaxf(rm1, fmaxf(s[nt][2], s[nt][3]));
        }
        rm0 = fmaxf(rm0, __shfl_xor_sync(0xffffffffu, rm0, 1));
        rm0 = fmaxf(rm0, __shfl_xor_sync(0xffffffffu, rm0, 2));
        rm1 = fmaxf(rm1, __shfl_xor_sync(0xffffffffu, rm1, 1));
        rm1 = fmaxf(rm1, __shfl_xor_sync(0xffffffffu, rm1, 2));
        float mn0 = fmaxf(mrun0, rm0), mn1 = fmaxf(mrun1, rm1);
        float cr0 = ex2f(mrun0 - mn0), cr1 = ex2f(mrun1 - mn1);
        mrun0 = mn0; mrun1 = mn1;
        float sum0 = 0.f, sum1 = 0.f;
        int row0 = q0 + g, row1 = q0 + g + 8;
        char* P0 = Pp + row0 * 128 + tg * 4;
        char* P1 = Pp + row1 * 128 + tg * 4;
        int rm0i = row0 & 7, rm1i = row1 & 7;
#pragma unroll
        for (int nt = 0; nt < 8; nt++) {
            float p00 = ex2f(s[nt][0] - mn0);
            float p01 = ex2f(s[nt][1] - mn0);
            float p10 = ex2f(s[nt][2] - mn1);
            float p11 = ex2f(s[nt][3] - mn1);
            sum0 += p00 + p01;
            sum1 += p10 + p11;
            *(__nv_bfloat162*)(P0 + ((nt ^ rm0i) << 4)) =
                __floats2bfloat162_rn(p00, p01);
            *(__nv_bfloat162*)(P1 + ((nt ^ rm1i) << 4)) =
                __floats2bfloat162_rn(p10, p11);
        }
        sum0 += __shfl_xor_sync(0xffffffffu, sum0, 1);
        sum0 += __shfl_xor_sync(0xffffffffu, sum0, 2);
        sum1 += __shfl_xor_sync(0xffffffffu, sum1, 1);
        sum1 += __shfl_xor_sync(0xffffffffu, sum1, 2);
        lrun0 = lrun0 * cr0 + sum0;
        lrun1 = lrun1 * cr1 + sum1;
#pragma unroll
        for (int nt = 0; nt < 8; nt++) {
            o[nt][0] *= cr0; o[nt][1] *= cr0;
            o[nt][2] *= cr1; o[nt][3] *= cr1;
        }
        __syncwarp();

#pragma unroll
        for (int ks = 0; ks < 4; ks++) {
            unsigned int a0, a1, a2, a3;
            ldsm_x4(a0, a1, a2, a3, Pb + aoff + (((2 * ks + ac) ^ arm) << 4));
#pragma unroll
            for (int db = 0; db < 4; db++) {
                int row = vrow0 + ks * 16;
                unsigned int b0, b1, b2, b3;
                ldsm_x4_t(b0, b1, b2, b3,
                          Vb + row * 128 + (((2 * db + vc) ^ (row & 7)) << 4));
                mma_bf16(o[2 * db], a0, a1, a2, a3, b0, b1);
                mma_bf16(o[2 * db + 1], a0, a1, a2, a3, b2, b3);
            }
        }
    }

    float inv0 = 1.f / lrun0, inv1 = 1.f / lrun1;
    float* ob = g_a + (size_t)(b * 1024 + qt * 64 + q0) * 256 + m * 64;
#pragma unroll
    for (int nt = 0; nt < 8; nt++) {
        float2 v0 = {o[nt][0] * inv0, o[nt][1] * inv0};
        float2 v1 = {o[nt][2] * inv1, o[nt][3] * inv1};
        *(float2*)&ob[g * 256 + 8 * nt + 2 * tg] = v0;
        *(float2*)&ob[(g + 8) * 256 + 8 * nt + 2 * tg] = v1;
    }
}

// ---------------------------------------------------------------------------
// Fused tail: z1 = LN(a@Wp+bp+skip); h = gelu(z1@W1+b1);
// out = transpose(LN(h@W2+b2+z1)). One CTA = 32 rows; all intermediates in
// smem (fp32, raw bits feed tf32 mma). W staged cp.async double-buffered,
// 16B-chunk swizzle c ^ ((kk&3)<<1) (same algebra as proj_all).
// ---------------------------------------------------------------------------
constexpr int TZ1 = 0;                 // z1: 32 x 132 fp32
constexpr int TH = 32 * 132;           // h/A: 32 x 260 fp32
constexpr int TWB = TH + 32 * 260;     // W double-buffer: 2 x 4096 words
constexpr int TSCR = TWB + 2 * 4096;   // rowsum[32][4], rowsq[32][4]
constexpr int TAIL_SMEM_BYTES = (TSCR + 256) * 4;

__global__ __launch_bounds__(256) void tail_fused(
    const float* __restrict__ Wp, const float* __restrict__ bp,
    const float* __restrict__ skip, const float* __restrict__ pre_g,
    const float* __restrict__ pre_b, const float* __restrict__ W1,
    const float* __restrict__ b1, const float* __restrict__ W2,
    const float* __restrict__ b2, const float* __restrict__ post_g,
    const float* __restrict__ post_b, float* __restrict__ out) {
    extern __shared__ unsigned int smem_u[];
    unsigned int* Z1 = smem_u + TZ1;
    unsigned int* Hs = smem_u + TH;
    unsigned int* WB = smem_u + TWB;
    float* rowsum = (float*)(smem_u + TSCR);
    float* rowsq = rowsum + 128;
    unsigned int wb_b = (unsigned int)__cvta_generic_to_shared(WB);
    unsigned int h_b = (unsigned int)__cvta_generic_to_shared(Hs);

    int t = threadIdx.x;
    int r0 = blockIdx.x * 32;
    int warp = t >> 5, lane = t & 31;
    int g = lane >> 2, tg = lane & 3;
    int mt = warp & 1, wg = warp >> 1;

    // W fill: N=128 weights (Wp, W2): 16 rows x 32 chunks
    auto fill_w128 = [&](const float* Wm, int kc, int buf) {
#pragma unroll
        for (int j = 0; j < 2; j++) {
            int i = t + 256 * j;
            int kk = i >> 5, c = i & 31;
            cpa16(wb_b + buf * 16384 + kk * 512 + ((c ^ ((kk & 3) << 1)) << 4),
                  Wm + (size_t)(kc + kk) * 128 + c * 4);
        }
        cpa_commit();
    };
    // W fill: N=256 weight (W1): 16 rows x 64 chunks
    auto fill_w256 = [&](const float* Wm, int kc, int buf) {
#pragma unroll
        for (int j = 0; j < 4; j++) {
            int i = t + 256 * j;
            int kk = i >> 6, c = i & 63;
            cpa16(wb_b + buf * 16384 + kk * 1024 + ((c ^ ((kk & 3) << 1)) << 4),
                  Wm + (size_t)(kc + kk) * 256 + c * 4);
        }
        cpa_commit();
    };

    // Stage A (g_a 32 rows x 256) into Hs (stride 260) + first Wp chunk
    {
        const float* asrc = g_a + (size_t)r0 * 256;
#pragma unroll
        for (int j = 0; j < 8; j++) {
            int i = t + 256 * j;
            int row = i >> 6, c = i & 63;
            cpa16(h_b + (row * 260 + c * 4) * 4, asrc + row * 256 + c * 4);
        }
    }
    fill_w128(Wp, 0, 0);

    int rA = mt * 16 + g, rB = rA + 8;
    int grA = r0 + rA, grB = r0 + rB;
    int bA = grA >> 10, qA = grA & 1023;
    int bBi = grB >> 10, qB = grB & 1023;
    int sh = tg << 1;

    // ---- Phase 1: acc1 = A @ Wp   (M32 N128 K256) ----
    float acc1[4][4];
#pragma unroll
    for (int nt = 0; nt < 4; nt++)
#pragma unroll
        for (int c = 0; c < 4; c++) acc1[nt][c] = 0.f;
    int n0 = wg * 32;
    for (int kcb = 0; kcb < 16; kcb++) {
        cpa_wait0();
        __syncthreads();
        if (kcb + 1 < 16) fill_w128(Wp, (kcb + 1) * 16, (kcb + 1) & 1);
        unsigned int* Wb = WB + (kcb & 1) * 4096;
        int kc = kcb * 16;
#pragma unroll
        for (int ks = 0; ks < 2; ks++) {
            int kb_ = kc + 8 * ks;
            unsigned int a0 = Hs[rA * 260 + kb_ + tg];
            unsigned int a1 = Hs[rB * 260 + kb_ + tg];
            unsigned int a2 = Hs[rA * 260 + kb_ + tg + 4];
            unsigned int a3 = Hs[rB * 260 + kb_ + tg + 4];
            int kk0 = 8 * ks + tg, kk1 = kk0 + 4;
#pragma unroll
            for (int nt = 0; nt < 4; nt++) {
                int col = n0 + nt * 8 + g;
                int idx = (((col >> 2) ^ sh) << 2) | (col & 3);
                mma_tf32(acc1[nt][0], acc1[nt][1], acc1[nt][2], acc1[nt][3],
                         a0, a1, a2, a3, Wb[kk0 * 128 + idx],
                         Wb[kk1 * 128 + idx]);
            }
        }
    }
    fill_w256(W1, 0, 0); // prefetch overlaps epilogue

    // ---- Epilogue 1: +bp +skip, LN -> Z1 ----
    {
        float vA[8], vB[8];
        float sA = 0.f, qAs = 0.f, sB = 0.f, qBs = 0.f;
#pragma unroll
        for (int nt = 0; nt < 4; nt++) {
#pragma unroll
            for (int x = 0; x < 2; x++) {
                int col = n0 + nt * 8 + 2 * tg + x;
                float bb = __ldg(&bp[col]);
                float a = acc1[nt][2 * x] ;
                float va = acc1[nt][x] + bb +
                           __ldg(&skip[bA * (128 * 1024) + col * 1024 + qA]);
                float vb = acc1[nt][2 + x] + bb +
                           __ldg(&skip[bBi * (128 * 1024) + col * 1024 + qB]);
                (void)a;
                vA[nt * 2 + x] = va; vB[nt * 2 + x] = vb;
                sA += va; qAs += va * va;
                sB += vb; qBs += vb * vb;
            }
        }
        sA += __shfl_xor_sync(0xffffffffu, sA, 1);
        sA += __shfl_xor_sync(0xffffffffu, sA, 2);
        qAs += __shfl_xor_sync(0xffffffffu, qAs, 1);
        qAs += __shfl_xor_sync(0xffffffffu, qAs, 2);
        sB += __shfl_xor_sync(0xffffffffu, sB, 1);
        sB += __shfl_xor_sync(0xffffffffu, sB, 2);
        qBs += __shfl_xor_sync(0xffffffffu, qBs, 1);
        qBs += __shfl_xor_sync(0xffffffffu, qBs, 2);
        if (tg == 0) {
            rowsum[rA * 4 + wg] = sA; rowsq[rA * 4 + wg] = qAs;
            rowsum[rB * 4 + wg] = sB; rowsq[rB * 4 + wg] = qBs;
        }
        __syncthreads();
        float muA, rsAv, muB, rsBv;
        {
            float sm = rowsum[rA * 4] + rowsum[rA * 4 + 1] + rowsum[rA * 4 + 2] +
                       rowsum[rA * 4 + 3];
            float sq = rowsq[rA * 4] + rowsq[rA * 4 + 1] + rowsq[rA * 4 + 2] +
                       rowsq[rA * 4 + 3];
            muA = sm * (1.f / 128.f);
            rsAv = rsqrtf(sq * (1.f / 128.f) - muA * muA + 1e-5f);
            sm = rowsum[rB * 4] + rowsum[rB * 4 + 1] + rowsum[rB * 4 + 2] +
                 rowsum[rB * 4 + 3];
            sq = rowsq[rB * 4] + rowsq[rB * 4 + 1] + rowsq[rB * 4 + 2] +
                 rowsq[rB * 4 + 3];
            muB = sm * (1.f / 128.f);
            rsBv = rsqrtf(sq * (1.f / 128.f) - muB * muB + 1e-5f);
        }
#pragma unroll
        for (int nt = 0; nt < 4; nt++) {
#pragma unroll
            for (int x = 0; x < 2; x++) {
                int col = n0 + nt * 8 + 2 * tg + x;
                float gg = __ldg(&pre_g[col]), bbx = __ldg(&pre_b[col]);
                Z1[rA * 132 + col] =
                    __float_as_uint((vA[nt * 2 + x] - muA) * rsAv * gg + bbx);
                Z1[rB * 132 + col] =
                    __float_as_uint((vB[nt * 2 + x] - muB) * rsBv * gg + bbx);
            }
        }
    }

    // ---- Phase 2: acc2 = Z1 @ W1 (M32 N256 K128), gelu -> Hs ----
    float acc2[8][4];
#pragma unroll
    for (int nt = 0; nt < 8; nt++)
#pragma unroll
        for (int c = 0; c < 4; c++) acc2[nt][c] = 0.f;
    int n02 = wg * 64;
    for (int kcb = 0; kcb < 8; kcb++) {
        cpa_wait0();
        __syncthreads();
        if (kcb + 1 < 8) fill_w256(W1, (kcb + 1) * 16, (kcb + 1) & 1);
        unsigned int* Wb = WB + (kcb & 1) * 4096;
        int kc = kcb * 16;
#pragma unroll
        for (int ks = 0; ks < 2; ks++) {
            int kb_ = kc + 8 * ks;
            unsigned int a0 = Z1[rA * 132 + kb_ + tg];
            unsigned int a1 = Z1[rB * 132 + kb_ + tg];
            unsigned int a2 = Z1[rA * 132 + kb_ + tg + 4];
            unsigned int a3 = Z1[rB * 132 + kb_ + tg + 4];
            int kk0 = 8 * ks + tg, kk1 = kk0 + 4;
#pragma unroll
            for (int nt = 0; nt < 8; nt++) {
                int col = n02 + nt * 8 + g;
                int idx = (((col >> 2) ^ sh) << 2) | (col & 3);
                mma_tf32(acc2[nt][0], acc2[nt][1], acc2[nt][2], acc2[nt][3],
                         a0, a1, a2, a3, Wb[kk0 * 256 + idx],
                         Wb[kk1 * 256 + idx]);
            }
        }
    }
    fill_w128(W2, 0, 0); // prefetch
    __syncthreads();     // all Phase-2 A-reads of Z1 done; Hs writes safe
#pragma unroll
    for (int nt = 0; nt < 8; nt++) {
#pragma unroll
        for (int x = 0; x < 2; x++) {
            int col = n02 + nt * 8 + 2 * tg + x;
            float bb = __ldg(&b1[col]);
            float hA = acc2[nt][x] + bb;
            float hB = acc2[nt][2 + x] + bb;
            hA = 0.5f * hA * (1.0f + erff(hA * 0.70710678118654752f));
            hB = 0.5f * hB * (1.0f + erff(hB * 0.70710678118654752f));
            Hs[rA * 260 + col] = __float_as_uint(hA);
            Hs[rB * 260 + col] = __float_as_uint(hB);
        }
    }

    // ---- Phase 3: acc1 = Hs @ W2 (M32 N128 K256), +b2 +Z1, LN, transpose ---
#pragma unroll
    for (int nt = 0; nt < 4; nt++)
#pragma unroll
        for (int c = 0; c < 4; c++) acc1[nt][c] = 0.f;
    for (int kcb = 0; kcb < 16; kcb++) {
        cpa_wait0();
        __syncthreads();
        if (kcb + 1 < 16) fill_w128(W2, (kcb + 1) * 16, (kcb + 1) & 1);
        unsigned int* Wb = WB + (kcb & 1) * 4096;
        int kc = kcb * 16;
#pragma unroll
        for (int ks = 0; ks < 2; ks++) {
            int kb_ = kc + 8 * ks;
            unsigned int a0 = Hs[rA * 260 + kb_ + tg];
            unsigned int a1 = Hs[rB * 260 + kb_ + tg];
            unsigned int a2 = Hs[rA * 260 + kb_ + tg + 4];
            unsigned int a3 = Hs[rB * 260 + kb_ + tg + 4];
            int kk0 = 8 * ks + tg, kk1 = kk0 + 4;
#pragma unroll
            for (int nt = 0; nt < 4; nt++) {
                int col = n0 + nt * 8 + g;
                int idx = (((col >> 2) ^ sh) << 2) | (col & 3);
                mma_tf32(acc1[nt][0], acc1[nt][1], acc1[nt][2], acc1[nt][3],
                         a0, a1, a2, a3, Wb[kk0 * 128 + idx],
                         Wb[kk1 * 128 + idx]);
            }
        }
    }
    {
        float vA[8], vB[8];
        float sA = 0.f, qAs = 0.f, sB = 0.f, qBs = 0.f;
#pragma unroll
        for (int nt = 0; nt < 4; nt++) {
#pragma unroll
            for (int x = 0; x < 2; x++) {
                int col = n0 + nt * 8 + 2 * tg + x;
                float bb = __ldg(&b2[col]);
                float va = acc1[nt][x] + bb + __uint_as_float(Z1[rA * 132 + col]);
                float vb = acc1[nt][2 + x] + bb + __uint_as_float(Z1[rB * 132 + col]);
                vA[nt * 2 + x] = va; vB[nt * 2 + x] = vb;
                sA += va; qAs += va * va;
                sB += vb; qBs += vb * vb;
            }
        }
        sA += __shfl_xor_sync(0xffffffffu, sA, 1);
        sA += __shfl_xor_sync(0xffffffffu, sA, 2);
        qAs += __shfl_xor_sync(0xffffffffu, qAs, 1);
        qAs += __shfl_xor_sync(0xffffffffu, qAs, 2);
        sB += __shfl_xor_sync(0xffffffffu, sB, 1);
        sB += __shfl_xor_sync(0xffffffffu, sB, 2);
        qBs += __shfl_xor_sync(0xffffffffu, qBs, 1);
        qBs += __shfl_xor_sync(0xffffffffu, qBs, 2);
        __syncthreads(); // phase-3 done everywhere; safe to reuse rowsum
        if (tg == 0) {
            rowsum[rA * 4 + wg] = sA; rowsq[rA * 4 + wg] = qAs;
            rowsum[rB * 4 + wg] = sB; rowsq[rB * 4 + wg] = qBs;
        }
        __syncthreads();
        float sm = rowsum[rA * 4] + rowsum[rA * 4 + 1] + rowsum[rA * 4 + 2] +
                   rowsum[rA * 4 + 3];
        float sq = rowsq[rA * 4] + rowsq[rA * 4 + 1] + rowsq[rA * 4 + 2] +
                   rowsq[rA * 4 + 3];
        float muA = sm * (1.f / 128.f);
        float rsAv = rsqrtf(sq * (1.f / 128.f) - muA * muA + 1e-5f);
        sm = rowsum[rB * 4] + rowsum[rB * 4 + 1] + rowsum[rB * 4 + 2] +
             rowsum[rB * 4 + 3];
        sq = rowsq[rB * 4] + rowsq[rB * 4 + 1] + rowsq[rB * 4 + 2] +
             rowsq[rB * 4 + 3];
        float muB = sm * (1.f / 128.f);
        float rsBv = rsqrtf(sq * (1.f / 128.f) - muB * muB + 1e-5f);
#pragma unroll
        for (int nt = 0; nt < 4; nt++) {
#pragma unroll
            for (int x = 0; x < 2; x++) {
                int col = n0 + nt * 8 + 2 * tg + x;
                float gg = __ldg(&post_g[col]), bbx = __ldg(&post_b[col]);
                out[((size_t)bA * 128 + col) * 1024 + qA] =
                    (vA[nt * 2 + x] - muA) * rsAv * gg + bbx;
                out[((size_t)bBi * 128 + col) * 1024 + qB] =
                    (vB[nt * 2 + x] - muB) * rsBv * gg + bbx;
            }
        }
    }
}

// ---------------------------------------------------------------------------
extern "C" void kernel_launch(void* const* d_in, const int* in_sizes, int n_in,
                              void* d_out, int out_size) {
    const float* q = (const float*)d_in[0];
    const float* k = (const float*)d_in[1];
    const float* v = (const float*)d_in[2];
    const float* skip = (const float*)d_in[3];
    const unsigned char* mask = (const unsigned char*)d_in[4];
    const float* lnq_g = (const float*)d_in[5];
    const float* lnq_b = (const float*)d_in[6];
    const float* lnk_g = (const float*)d_in[7];
    const float* lnk_b = (const float*)d_in[8];
    const float* lnv_g = (const float*)d_in[9];
    const float* lnv_b = (const float*)d_in[10];
    const float* Wq = (const float*)d_in[11];
    const float* bq = (const float*)d_in[12];
    const float* Wk = (const float*)d_in[13];
    const float* bk = (const float*)d_in[14];
    const float* Wv = (const float*)d_in[15];
    const float* bv = (const float*)d_in[16];
    const float* Wp = (const float*)d_in[17];
    const float* bp = (const float*)d_in[18];
    const float* pre_g = (const float*)d_in[19];
    const float* pre_b = (const float*)d_in[20];
    const float* W1 = (const float*)d_in[21];
    const float* b1 = (const float*)d_in[22];
    const float* W2 = (const float*)d_in[23];
    const float* b2 = (const float*)d_in[24];
    const float* post_g = (const float*)d_in[25];
    const float* post_b = (const float*)d_in[26];
    float* out = (float*)d_out;

    cudaFuncSetAttribute(attn_kernel,
                         cudaFuncAttributeMaxDynamicSharedMemorySize,
                         ATTN_SMEM_BYTES);
    cudaFuncSetAttribute(proj_all,
                         cudaFuncAttributeMaxDynamicSharedMemorySize,
                         PROJ_SMEM_BYTES);
    cudaFuncSetAttribute(tail_fused,
                         cudaFuncAttributeMaxDynamicSharedMemorySize,
                         TAIL_SMEM_BYTES);

    mask_prep<<<1, 256>>>(mask);

    __nv_bfloat16* d_qh; cudaGetSymbolAddress((void**)&d_qh, g_qh);
    __nv_bfloat16* d_kh; cudaGetSymbolAddress((void**)&d_kh, g_kh);
    __nv_bfloat16* d_vh; cudaGetSymbolAddress((void**)&d_vh, g_vh);

    const float QSC = 0.125f * 1.4426950408889634f; // scale * log2(e)

    proj_all<<<864, 256, PROJ_SMEM_BYTES>>>(
        q, k, v, lnq_g, lnq_b, lnk_g, lnk_b, lnv_g, lnv_b, Wq, bq, Wk, bk,
        Wv, bv, d_qh, d_kh, d_vh, QSC);

    attn_kernel<<<dim3(16, 4, 4), 128, ATTN_SMEM_BYTES>>>();

    tail_fused<<<BB * QQ / 32, 256, TAIL_SMEM_BYTES>>>(
        Wp, bp, skip, pre_g, pre_b, W1, b1, W2, b2, post_g, post_b, out);
}

// round 15
// speedup vs baseline: 5.9391x; 1.0138x over previous
#include <cuda_runtime.h>
#include <cuda_bf16.h>
#include <math.h>

// Problem constants
constexpr int BB = 4;     // batch
constexpr int NN = 6;     // views
constexpr int DDIM = 128; // model dim
constexpr int QQ = 1024;  // H*W queries
constexpr int KImg = 640; // h*w keys per view
constexpr int MD = 256;   // heads * dim_head

// Scratch (device globals; no allocation allowed)
__device__ __nv_bfloat16 g_qh[BB * NN * QQ * MD];
__device__ __nv_bfloat16 g_kh[BB * NN * KImg * MD];
__device__ __nv_bfloat16 g_vh[BB * NN * KImg * MD];
__device__ float g_a[BB * QQ * MD];
__device__ int g_mask[NN * QQ];

// ---------------------------------------------------------------------------
// Helpers
// ---------------------------------------------------------------------------
__device__ __forceinline__ unsigned int f2tf(float x) {
    unsigned int r;
    asm("cvt.rna.tf32.f32 %0, %1;" : "=r"(r) : "f"(x));
    return r;
}

__device__ __forceinline__ float ex2f(float x) {
    float y;
    asm("ex2.approx.f32 %0, %1;" : "=f"(y) : "f"(x));
    return y;
}

__device__ __forceinline__ void mma_tf32(float& c0, float& c1, float& c2,
                                         float& c3, unsigned int a0,
                                         unsigned int a1, unsigned int a2,
                                         unsigned int a3, unsigned int b0,
                                         unsigned int b1) {
    asm volatile(
        "mma.sync.aligned.m16n8k8.row.col.f32.tf32.tf32.f32 "
        "{%0,%1,%2,%3},{%4,%5,%6,%7},{%8,%9},{%0,%1,%2,%3};\n"
        : "+f"(c0), "+f"(c1), "+f"(c2), "+f"(c3)
        : "r"(a0), "r"(a1), "r"(a2), "r"(a3), "r"(b0), "r"(b1));
}

__device__ __forceinline__ void mma_bf16(float* c, unsigned int a0,
                                         unsigned int a1, unsigned int a2,
                                         unsigned int a3, unsigned int b0,
                                         unsigned int b1) {
    asm volatile(
        "mma.sync.aligned.m16n8k16.row.col.f32.bf16.bf16.f32 "
        "{%0,%1,%2,%3},{%4,%5,%6,%7},{%8,%9},{%0,%1,%2,%3};\n"
        : "+f"(c[0]), "+f"(c[1]), "+f"(c[2]), "+f"(c[3])
        : "r"(a0), "r"(a1), "r"(a2), "r"(a3), "r"(b0), "r"(b1));
}

__device__ __forceinline__ void ldsm_x4(unsigned int& r0, unsigned int& r1,
                                        unsigned int& r2, unsigned int& r3,
                                        unsigned int addr) {
    asm volatile(
        "ldmatrix.sync.aligned.m8n8.x4.shared.b16 {%0,%1,%2,%3}, [%4];"
        : "=r"(r0), "=r"(r1), "=r"(r2), "=r"(r3)
        : "r"(addr));
}

__device__ __forceinline__ void ldsm_x4_t(unsigned int& r0, unsigned int& r1,
                                          unsigned int& r2, unsigned int& r3,
                                          unsigned int addr) {
    asm volatile(
        "ldmatrix.sync.aligned.m8n8.x4.trans.shared.b16 {%0,%1,%2,%3}, [%4];"
        : "=r"(r0), "=r"(r1), "=r"(r2), "=r"(r3)
        : "r"(addr));
}

__device__ __forceinline__ void cpa16(unsigned int dst, const void* src) {
    asm volatile("cp.async.cg.shared.global [%0], [%1], 16;" ::"r"(dst),
                 "l"(src));
}
__device__ __forceinline__ void cpa_commit() {
    asm volatile("cp.async.commit_group;");
}
__device__ __forceinline__ void cpa_wait0() {
    asm volatile("cp.async.wait_group 0;");
}

// ---------------------------------------------------------------------------
// Merged LayerNorm + projection (q, k, v) + mask prep, ONE launch (865 CTAs).
// bid 864 expands the mask; bids [0,864) are proj tiles (R13 winner logic).
// ---------------------------------------------------------------------------
constexpr int PROJ_XS_W = 64 * 132;
constexpr int PROJ_WS_W = 2 * 16 * 256;
constexpr int PROJ_SCR_W = 896;
constexpr int PROJ_SMEM_BYTES = (PROJ_XS_W + PROJ_WS_W + PROJ_SCR_W) * 4;

__global__ __launch_bounds__(256) void proj_all(
    const float* __restrict__ qx, const float* __restrict__ kx,
    const float* __restrict__ vx, const float* __restrict__ lnq_g,
    const float* __restrict__ lnq_b, const float* __restrict__ lnk_g,
    const float* __restrict__ lnk_b, const float* __restrict__ lnv_g,
    const float* __restrict__ lnv_b, const float* __restrict__ Wq,
    const float* __restrict__ bq, const float* __restrict__ Wk,
    const float* __restrict__ bk, const float* __restrict__ Wv,
    const float* __restrict__ bv, __nv_bfloat16* __restrict__ outq,
    __nv_bfloat16* __restrict__ outk, __nv_bfloat16* __restrict__ outv,
    float qsc, const unsigned char* __restrict__ mraw) {
    extern __shared__ unsigned int smem_u[];
    int t = threadIdx.x;
    int bid = blockIdx.x;

    if (bid == 864) {
        // ---- mask prep (detect bool/float32/int32, expand) ----
        int* flags = (int*)smem_u;
        if (t == 0) { flags[0] = 0; flags[1] = 0; }
        __syncthreads();
        int fb = 0, ff = 0;
        for (int i = t; i < NN * QQ; i += 256) {
            unsigned char v = mraw[i];
            if (v) {
                int r = i & 3;
                if (r == 1) fb = 1;
                else if (r >= 2) ff = 1;
            }
        }
        if (fb) atomicOr(&flags[0], 1);
        if (ff) atomicOr(&flags[1], 1);
        __syncthreads();
        int mode = flags[0] ? 0 : (flags[1] ? 1 : 2);
        const float* mf = (const float*)mraw;
        const int* mi = (const int*)mraw;
        for (int i = t; i < NN * QQ; i += 256) {
            int q = i / 6, n = i % 6;
            int val;
            if (mode == 0) val = (mraw[i] != 0);
            else if (mode == 1) val = (mf[i] != 0.0f);
            else val = (mi[i] != 0);
            g_mask[n * QQ + q] = val;
        }
        return;
    }

    unsigned int* Xs = smem_u;
    unsigned int* WsA = smem_u + PROJ_XS_W;
    float* fscr = (float*)(smem_u + PROJ_XS_W + PROJ_WS_W);
    float* rsum = fscr;
    float* rsq = fscr + 256;
    float* mu_s = fscr + 512;
    float* rs_s = fscr + 576;
    float* gs = fscr + 640;
    float* bs = fscr + 768;

    const float *x, *lg, *lb, *Wm, *bias;
    float oscale;
    __nv_bfloat16* out;
    int S, r0;
    if (bid < 384) {
        x = qx; S = 1024; r0 = bid * 64;
        lg = lnq_g; lb = lnq_b; Wm = Wq; bias = bq;
        oscale = qsc; out = outq;
    } else if (bid < 624) {
        x = kx; S = 640; r0 = (bid - 384) * 64;
        lg = lnk_g; lb = lnk_b; Wm = Wk; bias = bk;
        oscale = 1.0f; out = outk;
    } else {
        x = vx; S = 640; r0 = (bid - 624) * 64;
        lg = lnv_g; lb = lnv_b; Wm = Wv; bias = bv;
        oscale = 1.0f; out = outv;
    }
    unsigned int ws_b = (unsigned int)__cvta_generic_to_shared(WsA);

    auto fill_W = [&](int kc, int buf) {
#pragma unroll
        for (int j = 0; j < 4; j++) {
            int i = t + 256 * j;
            int kk = i >> 6, c = i & 63;
            cpa16(ws_b + buf * 16384 + kk * 1024 +
                      ((c ^ ((kk & 3) << 1)) << 4),
                  Wm + (size_t)(kc + kk) * 256 + c * 4);
        }
        cpa_commit();
    };

    fill_W(0, 0);

    int bn = r0 / S;
    int s0 = r0 % S;
    const float* xb = x + (size_t)bn * DDIM * S + s0;
    for (int i = t; i < 64 * 128; i += 256) {
        int sl = i & 63, d = i >> 6;
        Xs[sl * 132 + d] = __float_as_uint(xb[(size_t)d * S + sl]);
    }
    if (t < 128) { gs[t] = lg[t]; bs[t] = lb[t]; }
    __syncthreads();
    {
        int row = t >> 2, part = t & 3;
        float sm = 0.f, sq = 0.f;
#pragma unroll
        for (int j = 0; j < 32; j++) {
            float v = __uint_as_float(Xs[row * 132 + part * 32 + j]);
            sm += v; sq += v * v;
        }
        rsum[row * 4 + part] = sm; rsq[row * 4 + part] = sq;
    }
    __syncthreads();
    if (t < 64) {
        float sm = rsum[t * 4] + rsum[t * 4 + 1] + rsum[t * 4 + 2] + rsum[t * 4 + 3];
        float sq = rsq[t * 4] + rsq[t * 4 + 1] + rsq[t * 4 + 2] + rsq[t * 4 + 3];
        float mu = sm * (1.f / 128.f);
        float var = sq * (1.f / 128.f) - mu * mu;
        mu_s[t] = mu;
        rs_s[t] = rsqrtf(var + 1e-5f);
    }
    __syncthreads();
    for (int i = t; i < 64 * 128; i += 256) {
        int d = i & 127, sl = i >> 7;
        float v = __uint_as_float(Xs[sl * 132 + d]);
        Xs[sl * 132 + d] = f2tf((v - mu_s[sl]) * rs_s[sl] * gs[d] + bs[d]);
    }

    int warp = t >> 5, lane = t & 31;
    int g = lane >> 2, tg = lane & 3;
    int n0 = warp * 32;
    float acc[4][4][4];
#pragma unroll
    for (int mt = 0; mt < 4; mt++)
#pragma unroll
        for (int nt = 0; nt < 4; nt++)
#pragma unroll
            for (int c = 0; c < 4; c++) acc[mt][nt][c] = 0.f;

    for (int kcb = 0; kcb < 8; kcb++) {
        cpa_wait0();
        __syncthreads();
        if (kcb + 1 < 8) fill_W((kcb + 1) * 16, (kcb + 1) & 1);
        unsigned int* Wb = WsA + (kcb & 1) * 4096;
        int kc = kcb * 16;
#pragma unroll
        for (int ks = 0; ks < 2; ks++) {
            int kb_ = 8 * ks;
            unsigned int a[4][4];
#pragma unroll
            for (int mt = 0; mt < 4; mt++) {
                int row = mt * 16 + g;
                a[mt][0] = Xs[row * 132 + kc + kb_ + tg];
                a[mt][1] = Xs[(row + 8) * 132 + kc + kb_ + tg];
                a[mt][2] = Xs[row * 132 + kc + kb_ + tg + 4];
                a[mt][3] = Xs[(row + 8) * 132 + kc + kb_ + tg + 4];
            }
            int kk0 = kb_ + tg, kk1 = kb_ + tg + 4;
            int sh = (tg & 3) << 1;
#pragma unroll
            for (int nt = 0; nt < 4; nt++) {
                int col = n0 + nt * 8 + g;
                int idx = (((col >> 2) ^ sh) << 2) | (col & 3);
                unsigned int b0 = Wb[kk0 * 256 + idx];
                unsigned int b1 = Wb[kk1 * 256 + idx];
#pragma unroll
                for (int mt = 0; mt < 4; mt++)
                    mma_tf32(acc[mt][nt][0], acc[mt][nt][1], acc[mt][nt][2],
                             acc[mt][nt][3], a[mt][0], a[mt][1], a[mt][2],
                             a[mt][3], b0, b1);
            }
        }
    }
#pragma unroll
    for (int mt = 0; mt < 4; mt++)
#pragma unroll
        for (int nt = 0; nt < 4; nt++) {
            int row = r0 + mt * 16 + g;
            int col = n0 + nt * 8 + 2 * tg;
            float bv0 = __ldg(&bias[col]);
            float bv1 = __ldg(&bias[col + 1]);
            __nv_bfloat162 p0 = __floats2bfloat162_rn(
                (acc[mt][nt][0] + bv0) * oscale, (acc[mt][nt][1] + bv1) * oscale);
            __nv_bfloat162 p1 = __floats2bfloat162_rn(
                (acc[mt][nt][2] + bv0) * oscale, (acc[mt][nt][3] + bv1) * oscale);
            *(__nv_bfloat162*)&out[(size_t)row * 256 + col] = p0;
            *(__nv_bfloat162*)&out[(size_t)(row + 8) * 256 + col] = p1;
        }
}

// ---------------------------------------------------------------------------
// Flash attention (UNCHANGED from R12 winner)
// ---------------------------------------------------------------------------
constexpr int TILE_B = 64 * 128;
constexpr int ATTN_SMEM_BYTES = 6 * TILE_B;

__global__ __launch_bounds__(128) void attn_kernel() {
    extern __shared__ char smem[];
    unsigned int sb = (unsigned int)__cvta_generic_to_shared(smem);
    unsigned int Qb = sb;
    unsigned int Kbase = sb + TILE_B;
    unsigned int Vbase = sb + 3 * TILE_B;
    unsigned int Pb = sb + 5 * TILE_B;
    char* Pp = smem + 5 * TILE_B;

    int t = threadIdx.x;
    int warp = t >> 5, lane = t & 31;
    int g = lane >> 2, tg = lane & 3;
    int qt = blockIdx.x, m = blockIdx.y, b = blockIdx.z;
    int q0 = warp * 16;

    int mat = lane >> 3, r8 = lane & 7;
    int arow = q0 + r8 + (mat & 1) * 8;
    unsigned int aoff = arow * 128;
    int arm = arow & 7;
    int ac = mat >> 1;
    int brow0 = r8 + ((mat >> 1) << 3);
    int bc = mat & 1;
    int vrow0 = r8 + ((mat & 1) << 3);
    int vc = mat >> 1;

    const __nv_bfloat16* kbase = g_kh + (size_t)(b * 6) * 640 * 256 + m * 64;
    const __nv_bfloat16* vbase = g_vh + (size_t)(b * 6) * 640 * 256 + m * 64;

    auto fill64 = [&](const __nv_bfloat16* src, unsigned int dstBase) {
#pragma unroll
        for (int j = 0; j < 4; j++) {
            int i = t + 128 * j;
            int row = i >> 3, c = i & 7;
            cpa16(dstBase + row * 128 + ((c ^ (row & 7)) << 4),
                  src + row * 256 + c * 8);
        }
    };
    auto issue_tile = [&](int it, int buf) {
        fill64(kbase + (size_t)it * 64 * 256, Kbase + buf * TILE_B);
        fill64(vbase + (size_t)it * 64 * 256, Vbase + buf * TILE_B);
        cpa_commit();
    };

    float o[8][4];
#pragma unroll
    for (int nt = 0; nt < 8; nt++)
#pragma unroll
        for (int c = 0; c < 4; c++) o[nt][c] = 0.f;
    float mrun0 = -1e30f, mrun1 = -1e30f, lrun0 = 0.f, lrun1 = 0.f;
    int mk0 = 1, mk1 = 1;

    issue_tile(0, 0);

    for (int it = 0; it < 60; it++) {
        int buf = it & 1;
        if (it % 10 == 0) {
            int n = it / 10;
            __syncthreads();
            const __nv_bfloat16* qbase =
                g_qh + (size_t)((b * 6 + n) * 1024 + qt * 64) * 256 + m * 64;
            fill64(qbase, Qb);
            cpa_commit();
            mk0 = __ldg(&g_mask[n * 1024 + qt * 64 + q0 + g]);
            mk1 = __ldg(&g_mask[n * 1024 + qt * 64 + q0 + g + 8]);
        }
        cpa_wait0();
        __syncthreads();
        if (it + 1 < 60) issue_tile(it + 1, buf ^ 1);

        unsigned int Kb = Kbase + buf * TILE_B;
        unsigned int Vb = Vbase + buf * TILE_B;

        float s[8][4];
#pragma unroll
        for (int nt = 0; nt < 8; nt++)
#pragma unroll
            for (int c = 0; c < 4; c++) s[nt][c] = 0.f;
#pragma unroll
        for (int ks = 0; ks < 4; ks++) {
            unsigned int a0, a1, a2, a3;
            ldsm_x4(a0, a1, a2, a3, Qb + aoff + (((2 * ks + ac) ^ arm) << 4));
#pragma unroll
            for (int nb = 0; nb < 4; nb++) {
                int row = brow0 + nb * 16;
                unsigned int b0, b1, b2, b3;
                ldsm_x4(b0, b1, b2, b3,
                        Kb + row * 128 + (((2 * ks + bc) ^ (row & 7)) << 4));
                mma_bf16(s[2 * nb], a0, a1, a2, a3, b0, b1);
                mma_bf16(s[2 * nb + 1], a0, a1, a2, a3, b2, b3);
            }
        }

        if (!mk0) {
#pragma unroll
            for (int nt = 0; nt < 8; nt++) { s[nt][0] = -1e30f; s[nt][1] = -1e30f; }
        }
        if (!mk1) {
#pragma unroll
            for (int nt = 0; nt < 8; nt++) { s[nt][2] = -1e30f; s[nt][3] = -1e30f; }
        }

        float rm0 = -1e30f, rm1 = -1e30f;
#pragma unroll
        for (int nt = 0; nt < 8; nt++) {
            rm0 = fmaxf(rm0, fmaxf(s[nt][0], s[nt][1]));
            rm1 = fmaxf(rm1, fmaxf(s[nt][2], s[nt][3]));
        }
        rm0 = fmaxf(rm0, __shfl_xor_sync(0xffffffffu, rm0, 1));
        rm0 = fmaxf(rm0, __shfl_xor_sync(0xffffffffu, rm0, 2));
        rm1 = fmaxf(rm1, __shfl_xor_sync(0xffffffffu, rm1, 1));
        rm1 = fmaxf(rm1, __shfl_xor_sync(0xffffffffu, rm1, 2));
        float mn0 = fmaxf(mrun0, rm0), mn1 = fmaxf(mrun1, rm1);
        float cr0 = ex2f(mrun0 - mn0), cr1 = ex2f(mrun1 - mn1);
        mrun0 = mn0; mrun1 = mn1;
        float sum0 = 0.f, sum1 = 0.f;
        int row0 = q0 + g, row1 = q0 + g + 8;
        char* P0 = Pp + row0 * 128 + tg * 4;
        char* P1 = Pp + row1 * 128 + tg * 4;
        int rm0i = row0 & 7, rm1i = row1 & 7;
#pragma unroll
        for (int nt = 0; nt < 8; nt++) {
            float p00 = ex2f(s[nt][0] - mn0);
            float p01 = ex2f(s[nt][1] - mn0);
            float p10 = ex2f(s[nt][2] - mn1);
            float p11 = ex2f(s[nt][3] - mn1);
            sum0 += p00 + p01;
            sum1 += p10 + p11;
            *(__nv_bfloat162*)(P0 + ((nt ^ rm0i) << 4)) =
                __floats2bfloat162_rn(p00, p01);
            *(__nv_bfloat162*)(P1 + ((nt ^ rm1i) << 4)) =
                __floats2bfloat162_rn(p10, p11);
        }
        sum0 += __shfl_xor_sync(0xffffffffu, sum0, 1);
        sum0 += __shfl_xor_sync(0xffffffffu, sum0, 2);
        sum1 += __shfl_xor_sync(0xffffffffu, sum1, 1);
        sum1 += __shfl_xor_sync(0xffffffffu, sum1, 2);
        lrun0 = lrun0 * cr0 + sum0;
        lrun1 = lrun1 * cr1 + sum1;
#pragma unroll
        for (int nt = 0; nt < 8; nt++) {
            o[nt][0] *= cr0; o[nt][1] *= cr0;
            o[nt][2] *= cr1; o[nt][3] *= cr1;
        }
        __syncwarp();

#pragma unroll
        for (int ks = 0; ks < 4; ks++) {
            unsigned int a0, a1, a2, a3;
            ldsm_x4(a0, a1, a2, a3, Pb + aoff + (((2 * ks + ac) ^ arm) << 4));
#pragma unroll
            for (int db = 0; db < 4; db++) {
                int row = vrow0 + ks * 16;
                unsigned int b0, b1, b2, b3;
                ldsm_x4_t(b0, b1, b2, b3,
                          Vb + row * 128 + (((2 * db + vc) ^ (row & 7)) << 4));
                mma_bf16(o[2 * db], a0, a1, a2, a3, b0, b1);
                mma_bf16(o[2 * db + 1], a0, a1, a2, a3, b2, b3);
            }
        }
    }

    float inv0 = 1.f / lrun0, inv1 = 1.f / lrun1;
    float* ob = g_a + (size_t)(b * 1024 + qt * 64 + q0) * 256 + m * 64;
#pragma unroll
    for (int nt = 0; nt < 8; nt++) {
        float2 v0 = {o[nt][0] * inv0, o[nt][1] * inv0};
        float2 v1 = {o[nt][2] * inv1, o[nt][3] * inv1};
        *(float2*)&ob[g * 256 + 8 * nt + 2 * tg] = v0;
        *(float2*)&ob[(g + 8) * 256 + 8 * nt + 2 * tg] = v1;
    }
}

// ---------------------------------------------------------------------------
// Fused tail, 16 rows/CTA (grid 256): z1 = LN(a@Wp+bp+skip);
// h = gelu(z1@W1+b1); out = transpose(LN(h@W2+b2+z1)).
// One m16 tile; 8 warps split N (n0 = warp*16 for N=128, warp*32 for N=256).
// W cp.async double-buffered, chunk swizzle c ^ ((kk&3)<<1).
// ---------------------------------------------------------------------------
constexpr int TZ1 = 0;                  // z1: 16 x 132
constexpr int TH = 16 * 132;            // h/A: 16 x 260
constexpr int TWB = TH + 16 * 260;      // W double-buffer: 2 x 4096 words
constexpr int TSCR = TWB + 2 * 4096;    // rowsum[16][8], rowsq[16][8]
constexpr int TAIL_SMEM_BYTES = (TSCR + 256) * 4;

__global__ __launch_bounds__(256) void tail_fused(
    const float* __restrict__ Wp, const float* __restrict__ bp,
    const float* __restrict__ skip, const float* __restrict__ pre_g,
    const float* __restrict__ pre_b, const float* __restrict__ W1,
    const float* __restrict__ b1, const float* __restrict__ W2,
    const float* __restrict__ b2, const float* __restrict__ post_g,
    const float* __restrict__ post_b, float* __restrict__ out) {
    extern __shared__ unsigned int smem_u[];
    unsigned int* Z1 = smem_u + TZ1;
    unsigned int* Hs = smem_u + TH;
    unsigned int* WB = smem_u + TWB;
    float* rowsum = (float*)(smem_u + TSCR);
    float* rowsq = rowsum + 128;
    unsigned int wb_b = (unsigned int)__cvta_generic_to_shared(WB);
    unsigned int h_b = (unsigned int)__cvta_generic_to_shared(Hs);

    int t = threadIdx.x;
    int r0 = blockIdx.x * 16;
    int warp = t >> 5, lane = t & 31;
    int g = lane >> 2, tg = lane & 3;

    auto fill_w128 = [&](const float* Wm, int kc, int buf) {
#pragma unroll
        for (int j = 0; j < 2; j++) {
            int i = t + 256 * j;
            int kk = i >> 5, c = i & 31;
            cpa16(wb_b + buf * 16384 + kk * 512 + ((c ^ ((kk & 3) << 1)) << 4),
                  Wm + (size_t)(kc + kk) * 128 + c * 4);
        }
        cpa_commit();
    };
    auto fill_w256 = [&](const float* Wm, int kc, int buf) {
#pragma unroll
        for (int j = 0; j < 4; j++) {
            int i = t + 256 * j;
            int kk = i >> 6, c = i & 63;
            cpa16(wb_b + buf * 16384 + kk * 1024 + ((c ^ ((kk & 3) << 1)) << 4),
                  Wm + (size_t)(kc + kk) * 256 + c * 4);
        }
        cpa_commit();
    };

    // Stage A (g_a, 16 rows x 256) into Hs (stride 260)
    {
        const float* asrc = g_a + (size_t)r0 * 256;
#pragma unroll
        for (int j = 0; j < 4; j++) {
            int i = t + 256 * j;
            int row = i >> 6, c = i & 63;
            cpa16(h_b + (row * 260 + c * 4) * 4, asrc + row * 256 + c * 4);
        }
    }
    fill_w128(Wp, 0, 0);

    int rA = g, rB = g + 8;
    int grA = r0 + rA, grB = r0 + rB;
    int bA = grA >> 10, qA = grA & 1023;
    int bBi = grB >> 10, qB = grB & 1023;
    int sh = tg << 1;

    // ---- Phase 1: acc1 = A @ Wp (M16 N128 K256); warp covers 16 cols ----
    float acc1[2][4];
#pragma unroll
    for (int nt = 0; nt < 2; nt++)
#pragma unroll
        for (int c = 0; c < 4; c++) acc1[nt][c] = 0.f;
    int n0 = warp * 16;
    for (int kcb = 0; kcb < 16; kcb++) {
        cpa_wait0();
        __syncthreads();
        if (kcb + 1 < 16) fill_w128(Wp, (kcb + 1) * 16, (kcb + 1) & 1);
        unsigned int* Wb = WB + (kcb & 1) * 4096;
        int kc = kcb * 16;
#pragma unroll
        for (int ks = 0; ks < 2; ks++) {
            int kb_ = kc + 8 * ks;
            unsigned int a0 = Hs[rA * 260 + kb_ + tg];
            unsigned int a1 = Hs[rB * 260 + kb_ + tg];
            unsigned int a2 = Hs[rA * 260 + kb_ + tg + 4];
            unsigned int a3 = Hs[rB * 260 + kb_ + tg + 4];
            int kk0 = 8 * ks + tg, kk1 = kk0 + 4;
#pragma unroll
            for (int nt = 0; nt < 2; nt++) {
                int col = n0 + nt * 8 + g;
                int idx = (((col >> 2) ^ sh) << 2) | (col & 3);
                mma_tf32(acc1[nt][0], acc1[nt][1], acc1[nt][2], acc1[nt][3],
                         a0, a1, a2, a3, Wb[kk0 * 128 + idx],
                         Wb[kk1 * 128 + idx]);
            }
        }
    }
    fill_w256(W1, 0, 0); // prefetch overlaps epilogue

    // ---- Epilogue 1: +bp +skip, LN -> Z1 ----
    {
        float vA[4], vB[4];
        float sA = 0.f, qAs = 0.f, sB = 0.f, qBs = 0.f;
#pragma unroll
        for (int nt = 0; nt < 2; nt++) {
#pragma unroll
            for (int x = 0; x < 2; x++) {
                int col = n0 + nt * 8 + 2 * tg + x;
                float bb = __ldg(&bp[col]);
                float va = acc1[nt][x] + bb +
                           __ldg(&skip[bA * (128 * 1024) + col * 1024 + qA]);
                float vb = acc1[nt][2 + x] + bb +
                           __ldg(&skip[bBi * (128 * 1024) + col * 1024 + qB]);
                vA[nt * 2 + x] = va; vB[nt * 2 + x] = vb;
                sA += va; qAs += va * va;
                sB += vb; qBs += vb * vb;
            }
        }
        sA += __shfl_xor_sync(0xffffffffu, sA, 1);
        sA += __shfl_xor_sync(0xffffffffu, sA, 2);
        qAs += __shfl_xor_sync(0xffffffffu, qAs, 1);
        qAs += __shfl_xor_sync(0xffffffffu, qAs, 2);
        sB += __shfl_xor_sync(0xffffffffu, sB, 1);
        sB += __shfl_xor_sync(0xffffffffu, sB, 2);
        qBs += __shfl_xor_sync(0xffffffffu, qBs, 1);
        qBs += __shfl_xor_sync(0xffffffffu, qBs, 2);
        if (tg == 0) {
            rowsum[rA * 8 + warp] = sA; rowsq[rA * 8 + warp] = qAs;
            rowsum[rB * 8 + warp] = sB; rowsq[rB * 8 + warp] = qBs;
        }
        __syncthreads();
        float smA = 0.f, sqA = 0.f, smB = 0.f, sqB = 0.f;
#pragma unroll
        for (int w = 0; w < 8; w++) {
            smA += rowsum[rA * 8 + w]; sqA += rowsq[rA * 8 + w];
            smB += rowsum[rB * 8 + w]; sqB += rowsq[rB * 8 + w];
        }
        float muA = smA * (1.f / 128.f);
        float rsAv = rsqrtf(sqA * (1.f / 128.f) - muA * muA + 1e-5f);
        float muB = smB * (1.f / 128.f);
        float rsBv = rsqrtf(sqB * (1.f / 128.f) - muB * muB + 1e-5f);
#pragma unroll
        for (int nt = 0; nt < 2; nt++) {
#pragma unroll
            for (int x = 0; x < 2; x++) {
                int col = n0 + nt * 8 + 2 * tg + x;
                float gg = __ldg(&pre_g[col]), bbx = __ldg(&pre_b[col]);
                Z1[rA * 132 + col] =
                    __float_as_uint((vA[nt * 2 + x] - muA) * rsAv * gg + bbx);
                Z1[rB * 132 + col] =
                    __float_as_uint((vB[nt * 2 + x] - muB) * rsBv * gg + bbx);
            }
        }
    }

    // ---- Phase 2: acc2 = Z1 @ W1 (M16 N256 K128); warp covers 32 cols ----
    float acc2[4][4];
#pragma unroll
    for (int nt = 0; nt < 4; nt++)
#pragma unroll
        for (int c = 0; c < 4; c++) acc2[nt][c] = 0.f;
    int n02 = warp * 32;
    for (int kcb = 0; kcb < 8; kcb++) {
        cpa_wait0();
        __syncthreads();
        if (kcb + 1 < 8) fill_w256(W1, (kcb + 1) * 16, (kcb + 1) & 1);
        unsigned int* Wb = WB + (kcb & 1) * 4096;
        int kc = kcb * 16;
#pragma unroll
        for (int ks = 0; ks < 2; ks++) {
            int kb_ = kc + 8 * ks;
            unsigned int a0 = Z1[rA * 132 + kb_ + tg];
            unsigned int a1 = Z1[rB * 132 + kb_ + tg];
            unsigned int a2 = Z1[rA * 132 + kb_ + tg + 4];
            unsigned int a3 = Z1[rB * 132 + kb_ + tg + 4];
            int kk0 = 8 * ks + tg, kk1 = kk0 + 4;
#pragma unroll
            for (int nt = 0; nt < 4; nt++) {
                int col = n02 + nt * 8 + g;
                int idx = (((col >> 2) ^ sh) << 2) | (col & 3);
                mma_tf32(acc2[nt][0], acc2[nt][1], acc2[nt][2], acc2[nt][3],
                         a0, a1, a2, a3, Wb[kk0 * 256 + idx],
                         Wb[kk1 * 256 + idx]);
            }
        }
    }
    fill_w128(W2, 0, 0); // prefetch
    __syncthreads();     // all Phase-2 reads done; Hs writes safe
#pragma unroll
    for (int nt = 0; nt < 4; nt++) {
#pragma unroll
        for (int x = 0; x < 2; x++) {
            int col = n02 + nt * 8 + 2 * tg + x;
            float bb = __ldg(&b1[col]);
            float hA = acc2[nt][x] + bb;
            float hB = acc2[nt][2 + x] + bb;
            hA = 0.5f * hA * (1.0f + erff(hA * 0.70710678118654752f));
            hB = 0.5f * hB * (1.0f + erff(hB * 0.70710678118654752f));
            Hs[rA * 260 + col] = __float_as_uint(hA);
            Hs[rB * 260 + col] = __float_as_uint(hB);
        }
    }

    // ---- Phase 3: acc1 = Hs @ W2 (M16 N128 K256), +b2 +Z1, LN, transpose ---
#pragma unroll
    for (int nt = 0; nt < 2; nt++)
#pragma unroll
        for (int c = 0; c < 4; c++) acc1[nt][c] = 0.f;
    for (int kcb = 0; kcb < 16; kcb++) {
        cpa_wait0();
        __syncthreads();
        if (kcb + 1 < 16) fill_w128(W2, (kcb + 1) * 16, (kcb + 1) & 1);
        unsigned int* Wb = WB + (kcb & 1) * 4096;
        int kc = kcb * 16;
#pragma unroll
        for (int ks = 0; ks < 2; ks++) {
            int kb_ = kc + 8 * ks;
            unsigned int a0 = Hs[rA * 260 + kb_ + tg];
            unsigned int a1 = Hs[rB * 260 + kb_ + tg];
            unsigned int a2 = Hs[rA * 260 + kb_ + tg + 4];
            unsigned int a3 = Hs[rB * 260 + kb_ + tg + 4];
            int kk0 = 8 * ks + tg, kk1 = kk0 + 4;
#pragma unroll
            for (int nt = 0; nt < 2; nt++) {
                int col = n0 + nt * 8 + g;
                int idx = (((col >> 2) ^ sh) << 2) | (col & 3);
                mma_tf32(acc1[nt][0], acc1[nt][1], acc1[nt][2], acc1[nt][3],
                         a0, a1, a2, a3, Wb[kk0 * 128 + idx],
                         Wb[kk1 * 128 + idx]);
            }
        }
    }
    {
        float vA[4], vB[4];
        float sA = 0.f, qAs = 0.f, sB = 0.f, qBs = 0.f;
#pragma unroll
        for (int nt = 0; nt < 2; nt++) {
#pragma unroll
            for (int x = 0; x < 2; x++) {
                int col = n0 + nt * 8 + 2 * tg + x;
                float bb = __ldg(&b2[col]);
                float va = acc1[nt][x] + bb + __uint_as_float(Z1[rA * 132 + col]);
                float vb = acc1[nt][2 + x] + bb + __uint_as_float(Z1[rB * 132 + col]);
                vA[nt * 2 + x] = va; vB[nt * 2 + x] = vb;
                sA += va; qAs += va * va;
                sB += vb; qBs += vb * vb;
            }
        }
        sA += __shfl_xor_sync(0xffffffffu, sA, 1);
        sA += __shfl_xor_sync(0xffffffffu, sA, 2);
        qAs += __shfl_xor_sync(0xffffffffu, qAs, 1);
        qAs += __shfl_xor_sync(0xffffffffu, qAs, 2);
        sB += __shfl_xor_sync(0xffffffffu, sB, 1);
        sB += __shfl_xor_sync(0xffffffffu, sB, 2);
        qBs += __shfl_xor_sync(0xffffffffu, qBs, 1);
        qBs += __shfl_xor_sync(0xffffffffu, qBs, 2);
        __syncthreads(); // phase-3 done everywhere; safe to reuse rowsum
        if (tg == 0) {
            rowsum[rA * 8 + warp] = sA; rowsq[rA * 8 + warp] = qAs;
            rowsum[rB * 8 + warp] = sB; rowsq[rB * 8 + warp] = qBs;
        }
        __syncthreads();
        float smA = 0.f, sqA = 0.f, smB = 0.f, sqB = 0.f;
#pragma unroll
        for (int w = 0; w < 8; w++) {
            smA += rowsum[rA * 8 + w]; sqA += rowsq[rA * 8 + w];
            smB += rowsum[rB * 8 + w]; sqB += rowsq[rB * 8 + w];
        }
        float muA = smA * (1.f / 128.f);
        float rsAv = rsqrtf(sqA * (1.f / 128.f) - muA * muA + 1e-5f);
        float muB = smB * (1.f / 128.f);
        float rsBv = rsqrtf(sqB * (1.f / 128.f) - muB * muB + 1e-5f);
#pragma unroll
        for (int nt = 0; nt < 2; nt++) {
#pragma unroll
            for (int x = 0; x < 2; x++) {
                int col = n0 + nt * 8 + 2 * tg + x;
                float gg = __ldg(&post_g[col]), bbx = __ldg(&post_b[col]);
                out[((size_t)bA * 128 + col) * 1024 + qA] =
                    (vA[nt * 2 + x] - muA) * rsAv * gg + bbx;
                out[((size_t)bBi * 128 + col) * 1024 + qB] =
                    (vB[nt * 2 + x] - muB) * rsBv * gg + bbx;
            }
        }
    }
}

// ---------------------------------------------------------------------------
extern "C" void kernel_launch(void* const* d_in, const int* in_sizes, int n_in,
                              void* d_out, int out_size) {
    const float* q = (const float*)d_in[0];
    const float* k = (const float*)d_in[1];
    const float* v = (const float*)d_in[2];
    const float* skip = (const float*)d_in[3];
    const unsigned char* mask = (const unsigned char*)d_in[4];
    const float* lnq_g = (const float*)d_in[5];
    const float* lnq_b = (const float*)d_in[6];
    const float* lnk_g = (const float*)d_in[7];
    const float* lnk_b = (const float*)d_in[8];
    const float* lnv_g = (const float*)d_in[9];
    const float* lnv_b = (const float*)d_in[10];
    const float* Wq = (const float*)d_in[11];
    const float* bq = (const float*)d_in[12];
    const float* Wk = (const float*)d_in[13];
    const float* bk = (const float*)d_in[14];
    const float* Wv = (const float*)d_in[15];
    const float* bv = (const float*)d_in[16];
    const float* Wp = (const float*)d_in[17];
    const float* bp = (const float*)d_in[18];
    const float* pre_g = (const float*)d_in[19];
    const float* pre_b = (const float*)d_in[20];
    const float* W1 = (const float*)d_in[21];
    const float* b1 = (const float*)d_in[22];
    const float* W2 = (const float*)d_in[23];
    const float* b2 = (const float*)d_in[24];
    const float* post_g = (const float*)d_in[25];
    const float* post_b = (const float*)d_in[26];
    float* out = (float*)d_out;

    cudaFuncSetAttribute(attn_kernel,
                         cudaFuncAttributeMaxDynamicSharedMemorySize,
                         ATTN_SMEM_BYTES);
    cudaFuncSetAttribute(proj_all,
                         cudaFuncAttributeMaxDynamicSharedMemorySize,
                         PROJ_SMEM_BYTES);
    cudaFuncSetAttribute(tail_fused,
                         cudaFuncAttributeMaxDynamicSharedMemorySize,
                         TAIL_SMEM_BYTES);

    __nv_bfloat16* d_qh; cudaGetSymbolAddress((void**)&d_qh, g_qh);
    __nv_bfloat16* d_kh; cudaGetSymbolAddress((void**)&d_kh, g_kh);
    __nv_bfloat16* d_vh; cudaGetSymbolAddress((void**)&d_vh, g_vh);

    const float QSC = 0.125f * 1.4426950408889634f; // scale * log2(e)

    proj_all<<<865, 256, PROJ_SMEM_BYTES>>>(
        q, k, v, lnq_g, lnq_b, lnk_g, lnk_b, lnv_g, lnv_b, Wq, bq, Wk, bk,
        Wv, bv, d_qh, d_kh, d_vh, QSC, mask);

    attn_kernel<<<dim3(16, 4, 4), 128, ATTN_SMEM_BYTES>>>();

    tail_fused<<<BB * QQ / 16, 256, TAIL_SMEM_BYTES>>>(
        Wp, bp, skip, pre_g, pre_b, W1, b1, W2, b2, post_g, post_b, out);
}